// round 1
// baseline (speedup 1.0000x reference)
#include <cuda_runtime.h>

#define NN 100000
#define EE 640000
#define GG 256
#define HH 128
#define TPB 256
#define BM 32

// ---------------- scratch (static device globals; no allocation) ----------------
__device__ float g_h[NN * HH];                 // 51.2 MB node features
__device__ float g_agg[NN * HH];               // 51.2 MB aggregation buffer
__device__ float g_e[(long long)EE * HH];      // 327.7 MB edge features
__device__ float g_rdeg[NN];
__device__ float g_deg[NN];
__device__ float g_pool[GG * HH];
__device__ float g_cnt[GG];

// ---------------- shared tile helpers ----------------
// A tile in smem: k-major [KC][36] (pad 36 keeps float4 alignment, A-frag read is a
// warp-broadcast). B tile: [KC][128].
template<int KC>
__device__ __forceinline__ void load_B(float* Bs, const float* __restrict__ W, int k0) {
    int t = threadIdx.x;
#pragma unroll
    for (int i = 0; i < (KC * HH / 4) / TPB; i++) {
        int f = t + i * TPB;
        int k = f >> 5;
        int c = (f & 31) << 2;
        *(float4*)(Bs + k * HH + c) = *(const float4*)(W + (long long)(k0 + k) * HH + c);
    }
}

__device__ __forceinline__ void storeA4(float* As, int r, int q, float4 v) {
    As[(q * 4 + 0) * 36 + r] = v.x;
    As[(q * 4 + 1) * 36 + r] = v.y;
    As[(q * 4 + 2) * 36 + r] = v.z;
    As[(q * 4 + 3) * 36 + r] = v.w;
}

template<int KC>
__device__ __forceinline__ void mma(const float* As, const float* Bs, int tr, int tc,
                                    float acc[4][4]) {
#pragma unroll
    for (int k = 0; k < KC; k++) {
        float4 a = *(const float4*)(As + k * 36 + (tr << 2));   // broadcast within warp
        float4 b = *(const float4*)(Bs + k * HH + (tc << 2));
        acc[0][0] += a.x * b.x; acc[0][1] += a.x * b.y; acc[0][2] += a.x * b.z; acc[0][3] += a.x * b.w;
        acc[1][0] += a.y * b.x; acc[1][1] += a.y * b.y; acc[1][2] += a.y * b.z; acc[1][3] += a.y * b.w;
        acc[2][0] += a.z * b.x; acc[2][1] += a.z * b.y; acc[2][2] += a.z * b.z; acc[2][3] += a.z * b.w;
        acc[3][0] += a.w * b.x; acc[3][1] += a.w * b.y; acc[3][2] += a.w * b.z; acc[3][3] += a.w * b.w;
    }
}

// ---------------- small utility kernels ----------------
__global__ void k_zero_misc() {
    int i = blockIdx.x * blockDim.x + threadIdx.x;
    if (i < NN) g_deg[i] = 0.f;
    if (i < GG * HH) g_pool[i] = 0.f;
    if (i < GG) g_cnt[i] = 0.f;
}
__global__ void k_zero_agg() {
    int i = blockIdx.x * blockDim.x + threadIdx.x;
    if (i < NN * HH) g_agg[i] = 0.f;
}
__global__ void k_deg(const int* __restrict__ dst) {
    int e = blockIdx.x * blockDim.x + threadIdx.x;
    if (e < EE) atomicAdd(&g_deg[dst[e]], 1.f);
}
__global__ void k_rdeg() {
    int n = blockIdx.x * blockDim.x + threadIdx.x;
    if (n < NN) g_rdeg[n] = 1.f / fmaxf(g_deg[n], 1.f);
}

// ---------------- node encoder: h = relu(x @ Wn0 + bn0), [N,64]x[64,128] ----------------
__global__ void __launch_bounds__(TPB) k_enc_nodes(const float* __restrict__ x,
                                                   const float* __restrict__ W,
                                                   const float* __restrict__ b) {
    __shared__ __align__(16) float As[32 * 36];
    __shared__ __align__(16) float Bs[32 * HH];
    int t = threadIdx.x, tr = t >> 5, tc = t & 31;
    int r = t >> 3, q = t & 7;
    int n0 = blockIdx.x * BM;
    float acc[4][4] = {};
#pragma unroll 1
    for (int c = 0; c < 2; c++) {
        __syncthreads();
        float4 v = *(const float4*)(x + (long long)(n0 + r) * 64 + c * 32 + q * 4);
        storeA4(As, r, q, v);
        load_B<32>(Bs, W, c * 32);
        __syncthreads();
        mma<32>(As, Bs, tr, tc, acc);
    }
    float4 bb = *(const float4*)(b + (tc << 2));
    float bj[4] = {bb.x, bb.y, bb.z, bb.w};
#pragma unroll
    for (int i = 0; i < 4; i++) {
        float* o = g_h + (long long)(n0 + (tr << 2) + i) * HH + (tc << 2);
        float4 ov;
        ov.x = fmaxf(acc[i][0] + bj[0], 0.f);
        ov.y = fmaxf(acc[i][1] + bj[1], 0.f);
        ov.z = fmaxf(acc[i][2] + bj[2], 0.f);
        ov.w = fmaxf(acc[i][3] + bj[3], 0.f);
        *(float4*)o = ov;
    }
}

// ---------------- edge encoder: e = relu(ea @ We0 + be0), [E,16]x[16,128] ----------------
__global__ void __launch_bounds__(TPB) k_enc_edges(const float* __restrict__ ea,
                                                   const float* __restrict__ W,
                                                   const float* __restrict__ b) {
    __shared__ __align__(16) float As[16 * 36];
    __shared__ __align__(16) float Bs[16 * HH];
    int t = threadIdx.x, tr = t >> 5, tc = t & 31;
    int e0 = blockIdx.x * BM;
    float acc[4][4] = {};
    if (t < 128) {
        int r = t >> 2, q = t & 3;
        float4 v = *(const float4*)(ea + (long long)(e0 + r) * 16 + q * 4);
        storeA4(As, r, q, v);
    }
    load_B<16>(Bs, W, 0);
    __syncthreads();
    mma<16>(As, Bs, tr, tc, acc);
    float4 bb = *(const float4*)(b + (tc << 2));
    float bj[4] = {bb.x, bb.y, bb.z, bb.w};
#pragma unroll
    for (int i = 0; i < 4; i++) {
        float* o = g_e + (long long)(e0 + (tr << 2) + i) * HH + (tc << 2);
        float4 ov;
        ov.x = fmaxf(acc[i][0] + bj[0], 0.f);
        ov.y = fmaxf(acc[i][1] + bj[1], 0.f);
        ov.z = fmaxf(acc[i][2] + bj[2], 0.f);
        ov.w = fmaxf(acc[i][3] + bj[3], 0.f);
        *(float4*)o = ov;
    }
}

// ---------------- message: m = relu([h[dst],h[src],e] @ WM + bM); atomic scatter to agg[dst]
__global__ void __launch_bounds__(TPB) k_msg(const int* __restrict__ src,
                                             const int* __restrict__ dst,
                                             const float* __restrict__ WM,
                                             const float* __restrict__ bM) {
    __shared__ __align__(16) float As[32 * 36];
    __shared__ __align__(16) float Bs[32 * HH];
    int t = threadIdx.x, tr = t >> 5, tc = t & 31;
    int r = t >> 3, q = t & 7;
    int e0 = blockIdx.x * BM;
    int ge = e0 + r;
    int s = src[ge], d = dst[ge];
    const float* hd = g_h + (long long)d * HH;
    const float* hs = g_h + (long long)s * HH;
    const float* ep = g_e + (long long)ge * HH;
    float acc[4][4] = {};
#pragma unroll 1
    for (int c = 0; c < 12; c++) {
        __syncthreads();
        const float* p = (c < 4) ? (hd + c * 32)
                       : (c < 8) ? (hs + (c - 4) * 32)
                                 : (ep + (c - 8) * 32);
        float4 v = *(const float4*)(p + q * 4);
        storeA4(As, r, q, v);
        load_B<32>(Bs, WM, c * 32);
        __syncthreads();
        mma<32>(As, Bs, tr, tc, acc);
    }
    float4 bb = *(const float4*)(bM + (tc << 2));
    float bj[4] = {bb.x, bb.y, bb.z, bb.w};
#pragma unroll
    for (int i = 0; i < 4; i++) {
        int gge = e0 + (tr << 2) + i;
        int dd = dst[gge];
        float* aggp = g_agg + (long long)dd * HH + (tc << 2);
#pragma unroll
        for (int j = 0; j < 4; j++) {
            float v = fmaxf(acc[i][j] + bj[j], 0.f);
            atomicAdd(aggp + j, v);
        }
    }
}

// ---------------- fused update + node linear:
// u = relu([h, agg/deg] @ WU + bU); h = relu(u @ Wn + bn)
__global__ void __launch_bounds__(TPB) k_update(const float* __restrict__ WU,
                                                const float* __restrict__ bU,
                                                const float* __restrict__ Wn,
                                                const float* __restrict__ bn) {
    __shared__ __align__(16) float As[32 * 36];
    __shared__ __align__(16) float Bs[32 * HH];
    __shared__ __align__(16) float Cs[128 * 36];   // u, transposed (k-major)
    int t = threadIdx.x, tr = t >> 5, tc = t & 31;
    int r = t >> 3, q = t & 7;
    int n0 = blockIdx.x * BM;
    int row = n0 + r;
    float rd = g_rdeg[row];
    float acc[4][4] = {};
#pragma unroll 1
    for (int c = 0; c < 8; c++) {
        __syncthreads();
        const float* p = (c < 4) ? (g_h + (long long)row * HH + c * 32)
                                 : (g_agg + (long long)row * HH + (c - 4) * 32);
        float sc = (c < 4) ? 1.f : rd;
        float4 v = *(const float4*)(p + q * 4);
        v.x *= sc; v.y *= sc; v.z *= sc; v.w *= sc;
        storeA4(As, r, q, v);
        load_B<32>(Bs, WU, c * 32);
        __syncthreads();
        mma<32>(As, Bs, tr, tc, acc);
    }
    // stage-1 epilogue -> Cs transposed
    {
        float4 bb = *(const float4*)(bU + (tc << 2));
        float bj[4] = {bb.x, bb.y, bb.z, bb.w};
#pragma unroll
        for (int i = 0; i < 4; i++)
#pragma unroll
            for (int j = 0; j < 4; j++)
                Cs[((tc << 2) + j) * 36 + (tr << 2) + i] = fmaxf(acc[i][j] + bj[j], 0.f);
    }
    // stage 2: u @ Wn
    float acc2[4][4] = {};
#pragma unroll 1
    for (int kc = 0; kc < 4; kc++) {
        __syncthreads();
        load_B<32>(Bs, Wn, kc * 32);
        __syncthreads();
        mma<32>(Cs + kc * 32 * 36, Bs, tr, tc, acc2);
    }
    float4 bb2 = *(const float4*)(bn + (tc << 2));
    float bj2[4] = {bb2.x, bb2.y, bb2.z, bb2.w};
#pragma unroll
    for (int i = 0; i < 4; i++) {
        float* o = g_h + (long long)(n0 + (tr << 2) + i) * HH + (tc << 2);
        float4 ov;
        ov.x = fmaxf(acc2[i][0] + bj2[0], 0.f);
        ov.y = fmaxf(acc2[i][1] + bj2[1], 0.f);
        ov.z = fmaxf(acc2[i][2] + bj2[2], 0.f);
        ov.w = fmaxf(acc2[i][3] + bj2[3], 0.f);
        *(float4*)o = ov;
    }
}

// ---------------- edge linear (in place): e = relu(e @ We + be) ----------------
__global__ void __launch_bounds__(TPB) k_edge_lin(const float* __restrict__ W,
                                                  const float* __restrict__ b) {
    __shared__ __align__(16) float As[32 * 36];
    __shared__ __align__(16) float Bs[32 * HH];
    int t = threadIdx.x, tr = t >> 5, tc = t & 31;
    int r = t >> 3, q = t & 7;
    int e0 = blockIdx.x * BM;
    float acc[4][4] = {};
#pragma unroll 1
    for (int c = 0; c < 4; c++) {
        __syncthreads();
        float4 v = *(const float4*)(g_e + (long long)(e0 + r) * HH + c * 32 + q * 4);
        storeA4(As, r, q, v);
        load_B<32>(Bs, W, c * 32);
        __syncthreads();
        mma<32>(As, Bs, tr, tc, acc);
    }
    float4 bb = *(const float4*)(b + (tc << 2));
    float bj[4] = {bb.x, bb.y, bb.z, bb.w};
#pragma unroll
    for (int i = 0; i < 4; i++) {
        float* o = g_e + (long long)(e0 + (tr << 2) + i) * HH + (tc << 2);
        float4 ov;
        ov.x = fmaxf(acc[i][0] + bj[0], 0.f);
        ov.y = fmaxf(acc[i][1] + bj[1], 0.f);
        ov.z = fmaxf(acc[i][2] + bj[2], 0.f);
        ov.w = fmaxf(acc[i][3] + bj[3], 0.f);
        *(float4*)o = ov;
    }
}

// ---------------- global mean pool + head ----------------
__global__ void k_pool(const int* __restrict__ bvec) {
    int idx = blockIdx.x * blockDim.x + threadIdx.x;
    if (idx < NN * HH) {
        int n = idx >> 7, c = idx & 127;
        int g = bvec[n];
        atomicAdd(&g_pool[g * HH + c], g_h[idx]);
        if (c == 0) atomicAdd(&g_cnt[g], 1.f);
    }
}

__global__ void k_head(const float* __restrict__ Wh, const float* __restrict__ bh,
                       float* __restrict__ out) {
    int g = threadIdx.x;  // 256 graphs, one block
    float rc = 1.f / fmaxf(g_cnt[g], 1.f);
    float acc = bh[0];
#pragma unroll
    for (int k = 0; k < HH; k++)
        acc += g_pool[g * HH + k] * rc * Wh[k];
    out[g] = acc;
}

// ---------------- launch ----------------
extern "C" void kernel_launch(void* const* d_in, const int* in_sizes, int n_in,
                              void* d_out, int out_size) {
    const float* x    = (const float*)d_in[0];
    const int*   ei   = (const int*)d_in[1];      // int32 (JAX default x64-disabled)
    const float* ea   = (const float*)d_in[2];
    const int*   bvec = (const int*)d_in[3];
    const float* Wn0  = (const float*)d_in[4];
    const float* bn0  = (const float*)d_in[5];
    const float* We0  = (const float*)d_in[6];
    const float* be0  = (const float*)d_in[7];
    const float* WM   = (const float*)d_in[8];
    const float* bM   = (const float*)d_in[9];
    const float* WU   = (const float*)d_in[10];
    const float* bU   = (const float*)d_in[11];
    const float* Wn   = (const float*)d_in[12];
    const float* bn   = (const float*)d_in[13];
    const float* We   = (const float*)d_in[14];
    const float* be   = (const float*)d_in[15];
    const float* Wh   = (const float*)d_in[16];
    const float* bh   = (const float*)d_in[17];
    float* out = (float*)d_out;

    const int* src = ei;
    const int* dst = ei + EE;

    k_zero_misc<<<(GG * HH > NN ? GG * HH : NN + 255) / 256 + 1, 256>>>();
    k_deg<<<(EE + 255) / 256, 256>>>(dst);
    k_rdeg<<<(NN + 255) / 256, 256>>>();

    k_enc_nodes<<<NN / BM, TPB>>>(x, Wn0, bn0);
    k_enc_edges<<<EE / BM, TPB>>>(ea, We0, be0);

    for (int l = 0; l < 3; l++) {
        k_zero_agg<<<(NN * HH + 255) / 256, 256>>>();
        k_msg<<<EE / BM, TPB>>>(src, dst, WM + (long long)l * 384 * HH, bM + l * HH);
        k_update<<<NN / BM, TPB>>>(WU + (long long)l * 256 * HH, bU + l * HH,
                                   Wn + (long long)l * HH * HH, bn + l * HH);
        if (l < 2)  // layer-2 edge update is dead (e unused afterward)
            k_edge_lin<<<EE / BM, TPB>>>(We + (long long)l * HH * HH, be + l * HH);
    }

    k_pool<<<(NN * HH + 255) / 256, 256>>>(bvec);
    k_head<<<1, GG>>>(Wh, bh, out);
}

// round 2
// speedup vs baseline: 1.2021x; 1.2021x over previous
#include <cuda_runtime.h>

#define NN 100000
#define EE 640000
#define GG 256
#define HH 128
#define TPB 256
#define BM 64

typedef long long ll;

// ---------------- scratch (static device globals; no allocation) ----------------
__device__ float g_h[NN * HH];            // 51.2 MB node features
__device__ float g_agg[NN * HH];          // 51.2 MB aggregation buffer
__device__ float g_e[(ll)EE * HH];        // 327.7 MB edge features
__device__ float g_rdeg[NN];
__device__ float g_deg[NN];
__device__ float g_pool[GG * HH];
__device__ float g_cnt[GG];

// ---------------- tile helpers ----------------
// A tile: row-major [BM][lda] (lda = KC+4, mult of 4 for float4 alignment).
// B tile: [KC][128] row-major.
template<int KC>
__device__ __forceinline__ void load_B(float* Bs, const float* __restrict__ W, int k0) {
    int t = threadIdx.x;
#pragma unroll
    for (int i = 0; i < (KC * HH / 4) / TPB; i++) {
        int f = t + i * TPB;
        int k = f >> 5;
        int c = (f & 31) << 2;
        *(float4*)(Bs + k * HH + c) = *(const float4*)(W + (ll)(k0 + k) * HH + c);
    }
}

// 8x4 per-thread register tile. A-reads are warp-broadcast float4 along k.
template<int KB, int LDA>
__device__ __forceinline__ void mma8x4(const float* __restrict__ As,
                                       const float* __restrict__ Bs,
                                       int tr8, int tc4, float acc[8][4]) {
#pragma unroll
    for (int kb = 0; kb < KB; kb++) {
        float4 b0 = *(const float4*)(Bs + (kb * 4 + 0) * HH + tc4);
        float4 b1 = *(const float4*)(Bs + (kb * 4 + 1) * HH + tc4);
        float4 b2 = *(const float4*)(Bs + (kb * 4 + 2) * HH + tc4);
        float4 b3 = *(const float4*)(Bs + (kb * 4 + 3) * HH + tc4);
#pragma unroll
        for (int i = 0; i < 8; i++) {
            float4 a = *(const float4*)(As + (tr8 + i) * LDA + kb * 4);
            acc[i][0] += a.x * b0.x; acc[i][1] += a.x * b0.y; acc[i][2] += a.x * b0.z; acc[i][3] += a.x * b0.w;
            acc[i][0] += a.y * b1.x; acc[i][1] += a.y * b1.y; acc[i][2] += a.y * b1.z; acc[i][3] += a.y * b1.w;
            acc[i][0] += a.z * b2.x; acc[i][1] += a.z * b2.y; acc[i][2] += a.z * b2.z; acc[i][3] += a.z * b2.w;
            acc[i][0] += a.w * b3.x; acc[i][1] += a.w * b3.y; acc[i][2] += a.w * b3.z; acc[i][3] += a.w * b3.w;
        }
    }
}

__device__ __forceinline__ float4 relu4(const float acc[4], float4 b) {
    float4 v;
    v.x = fmaxf(acc[0] + b.x, 0.f);
    v.y = fmaxf(acc[1] + b.y, 0.f);
    v.z = fmaxf(acc[2] + b.z, 0.f);
    v.w = fmaxf(acc[3] + b.w, 0.f);
    return v;
}

// ---------------- small utility kernels ----------------
__global__ void k_zero_misc() {
    int i = blockIdx.x * blockDim.x + threadIdx.x;
    if (i < NN) g_deg[i] = 0.f;
    if (i < GG * HH) g_pool[i] = 0.f;
    if (i < GG) g_cnt[i] = 0.f;
}
__global__ void k_zero_agg() {
    int i = blockIdx.x * blockDim.x + threadIdx.x;
    if (i < NN * HH) g_agg[i] = 0.f;
}
__global__ void k_deg(const int* __restrict__ dst) {
    int e = blockIdx.x * blockDim.x + threadIdx.x;
    if (e < EE) atomicAdd(&g_deg[dst[e]], 1.f);
}
__global__ void k_rdeg() {
    int n = blockIdx.x * blockDim.x + threadIdx.x;
    if (n < NN) g_rdeg[n] = 1.f / fmaxf(g_deg[n], 1.f);
}

// ---------------- node encoder: h = relu(x @ Wn0 + bn0), [N,64]x[64,128] ----------------
__global__ void __launch_bounds__(TPB) k_enc_nodes(const float* __restrict__ x,
                                                   const float* __restrict__ W,
                                                   const float* __restrict__ b) {
    __shared__ __align__(16) float As[BM * 36];
    __shared__ __align__(16) float Bs[32 * HH];
    int t = threadIdx.x;
    int tr8 = (t >> 5) << 3, tc4 = (t & 31) << 2;
    int r = t >> 2, q = t & 3;
    int n0 = blockIdx.x * BM;
    int row = min(n0 + r, NN - 1);
    float acc[8][4] = {};
#pragma unroll 1
    for (int c = 0; c < 2; c++) {
        __syncthreads();
        const float* p = x + (ll)row * 64 + c * 32;
        *(float4*)(As + r * 36 + q * 4)      = *(const float4*)(p + q * 4);
        *(float4*)(As + r * 36 + 16 + q * 4) = *(const float4*)(p + 16 + q * 4);
        load_B<32>(Bs, W, c * 32);
        __syncthreads();
        mma8x4<8, 36>(As, Bs, tr8, tc4, acc);
    }
    float4 bb = *(const float4*)(b + tc4);
#pragma unroll
    for (int i = 0; i < 8; i++) {
        int rr = n0 + tr8 + i;
        if (rr < NN)
            *(float4*)(g_h + (ll)rr * HH + tc4) = relu4(acc[i], bb);
    }
}

// ---------------- edge encoder: e = relu(ea @ We0 + be0), [E,16]x[16,128] ----------------
__global__ void __launch_bounds__(TPB) k_enc_edges(const float* __restrict__ ea,
                                                   const float* __restrict__ W,
                                                   const float* __restrict__ b) {
    __shared__ __align__(16) float As[BM * 20];
    __shared__ __align__(16) float Bs[16 * HH];
    int t = threadIdx.x;
    int tr8 = (t >> 5) << 3, tc4 = (t & 31) << 2;
    int r = t >> 2, q = t & 3;
    int e0 = blockIdx.x * BM;
    float acc[8][4] = {};
    *(float4*)(As + r * 20 + q * 4) = *(const float4*)(ea + (ll)(e0 + r) * 16 + q * 4);
    load_B<16>(Bs, W, 0);
    __syncthreads();
    mma8x4<4, 20>(As, Bs, tr8, tc4, acc);
    float4 bb = *(const float4*)(b + tc4);
#pragma unroll
    for (int i = 0; i < 8; i++)
        *(float4*)(g_e + (ll)(e0 + tr8 + i) * HH + tc4) = relu4(acc[i], bb);
}

// ---------------- message: m = relu([h[dst],h[src],e] @ WM + bM); float4 atomic scatter
__global__ void __launch_bounds__(TPB) k_msg(const int* __restrict__ src,
                                             const int* __restrict__ dst,
                                             const float* __restrict__ WM,
                                             const float* __restrict__ bM) {
    __shared__ __align__(16) float As[BM * 36];
    __shared__ __align__(16) float Bs[32 * HH];
    int t = threadIdx.x;
    int tr8 = (t >> 5) << 3, tc4 = (t & 31) << 2;
    int r = t >> 2, q = t & 3;
    int e0 = blockIdx.x * BM;
    int ge = e0 + r;
    const float* rowp0 = g_h + (ll)dst[ge] * HH;
    const float* rowp1 = g_h + (ll)src[ge] * HH;
    const float* rowp2 = g_e + (ll)ge * HH;
    float acc[8][4] = {};
#pragma unroll 1
    for (int c = 0; c < 12; c++) {
        __syncthreads();
        const float* p = ((c < 4) ? rowp0 : (c < 8) ? rowp1 : rowp2) + ((c & 3) << 5);
        *(float4*)(As + r * 36 + q * 4)      = *(const float4*)(p + q * 4);
        *(float4*)(As + r * 36 + 16 + q * 4) = *(const float4*)(p + 16 + q * 4);
        load_B<32>(Bs, WM, c * 32);
        __syncthreads();
        mma8x4<8, 36>(As, Bs, tr8, tc4, acc);
    }
    float4 bb = *(const float4*)(bM + tc4);
#pragma unroll
    for (int i = 0; i < 8; i++) {
        int dd = dst[e0 + tr8 + i];
        float4 v = relu4(acc[i], bb);
        atomicAdd((float4*)(g_agg + (ll)dd * HH + tc4), v);
    }
}

// ---------------- fused update + node linear:
// u = relu([h, agg/deg] @ WU + bU); h = relu(u @ Wn + bn)
__global__ void __launch_bounds__(TPB) k_update(const float* __restrict__ WU,
                                                const float* __restrict__ bU,
                                                const float* __restrict__ Wn,
                                                const float* __restrict__ bn) {
    __shared__ __align__(16) float As[BM * 36];
    __shared__ __align__(16) float Bs[32 * HH];
    __shared__ __align__(16) float Cs[BM * 132];   // u, row-major
    int t = threadIdx.x;
    int tr8 = (t >> 5) << 3, tc4 = (t & 31) << 2;
    int r = t >> 2, q = t & 3;
    int n0 = blockIdx.x * BM;
    int row = min(n0 + r, NN - 1);
    float rd = g_rdeg[row];
    float acc[8][4] = {};
#pragma unroll 1
    for (int c = 0; c < 8; c++) {
        __syncthreads();
        const float* p = (c < 4) ? (g_h + (ll)row * HH + c * 32)
                                 : (g_agg + (ll)row * HH + (c - 4) * 32);
        float sc = (c < 4) ? 1.f : rd;
        float4 v0 = *(const float4*)(p + q * 4);
        float4 v1 = *(const float4*)(p + 16 + q * 4);
        v0.x *= sc; v0.y *= sc; v0.z *= sc; v0.w *= sc;
        v1.x *= sc; v1.y *= sc; v1.z *= sc; v1.w *= sc;
        *(float4*)(As + r * 36 + q * 4)      = v0;
        *(float4*)(As + r * 36 + 16 + q * 4) = v1;
        load_B<32>(Bs, WU, c * 32);
        __syncthreads();
        mma8x4<8, 36>(As, Bs, tr8, tc4, acc);
    }
    // stage-1 epilogue: u -> Cs (row-major, conflict-free float4 stores)
    {
        float4 bb = *(const float4*)(bU + tc4);
#pragma unroll
        for (int i = 0; i < 8; i++)
            *(float4*)(Cs + (tr8 + i) * 132 + tc4) = relu4(acc[i], bb);
    }
    // stage 2: h = relu(u @ Wn + bn)
    float acc2[8][4] = {};
#pragma unroll 1
    for (int kc = 0; kc < 4; kc++) {
        __syncthreads();
        load_B<32>(Bs, Wn, kc * 32);
        __syncthreads();
        mma8x4<8, 132>(Cs + kc * 32, Bs, tr8, tc4, acc2);
    }
    float4 bb2 = *(const float4*)(bn + tc4);
#pragma unroll
    for (int i = 0; i < 8; i++) {
        int rr = n0 + tr8 + i;
        if (rr < NN)
            *(float4*)(g_h + (ll)rr * HH + tc4) = relu4(acc2[i], bb2);
    }
}

// ---------------- edge linear (in place): e = relu(e @ We + be) ----------------
__global__ void __launch_bounds__(TPB) k_edge_lin(const float* __restrict__ W,
                                                  const float* __restrict__ b) {
    __shared__ __align__(16) float As[BM * 36];
    __shared__ __align__(16) float Bs[32 * HH];
    int t = threadIdx.x;
    int tr8 = (t >> 5) << 3, tc4 = (t & 31) << 2;
    int r = t >> 2, q = t & 3;
    int e0 = blockIdx.x * BM;
    float acc[8][4] = {};
#pragma unroll 1
    for (int c = 0; c < 4; c++) {
        __syncthreads();
        const float* p = g_e + (ll)(e0 + r) * HH + c * 32;
        *(float4*)(As + r * 36 + q * 4)      = *(const float4*)(p + q * 4);
        *(float4*)(As + r * 36 + 16 + q * 4) = *(const float4*)(p + 16 + q * 4);
        load_B<32>(Bs, W, c * 32);
        __syncthreads();
        mma8x4<8, 36>(As, Bs, tr8, tc4, acc);
    }
    float4 bb = *(const float4*)(b + tc4);
#pragma unroll
    for (int i = 0; i < 8; i++)
        *(float4*)(g_e + (ll)(e0 + tr8 + i) * HH + tc4) = relu4(acc[i], bb);
}

// ---------------- global mean pool + head ----------------
__global__ void k_pool(const int* __restrict__ bvec) {
    int idx = blockIdx.x * blockDim.x + threadIdx.x;
    if (idx < NN * 32) {
        int n = idx >> 5, c4 = (idx & 31) << 2;
        int g = bvec[n];
        float4 hv = *(const float4*)(g_h + (ll)n * HH + c4);
        atomicAdd((float4*)(g_pool + g * HH + c4), hv);
        if ((idx & 31) == 0) atomicAdd(&g_cnt[g], 1.f);
    }
}

__global__ void k_head(const float* __restrict__ Wh, const float* __restrict__ bh,
                       float* __restrict__ out) {
    int g = threadIdx.x;  // 256 graphs, one block
    float rc = 1.f / fmaxf(g_cnt[g], 1.f);
    float acc = bh[0];
#pragma unroll
    for (int k = 0; k < HH; k++)
        acc += g_pool[g * HH + k] * rc * Wh[k];
    out[g] = acc;
}

// ---------------- launch ----------------
extern "C" void kernel_launch(void* const* d_in, const int* in_sizes, int n_in,
                              void* d_out, int out_size) {
    const float* x    = (const float*)d_in[0];
    const int*   ei   = (const int*)d_in[1];
    const float* ea   = (const float*)d_in[2];
    const int*   bvec = (const int*)d_in[3];
    const float* Wn0  = (const float*)d_in[4];
    const float* bn0  = (const float*)d_in[5];
    const float* We0  = (const float*)d_in[6];
    const float* be0  = (const float*)d_in[7];
    const float* WM   = (const float*)d_in[8];
    const float* bM   = (const float*)d_in[9];
    const float* WU   = (const float*)d_in[10];
    const float* bU   = (const float*)d_in[11];
    const float* Wn   = (const float*)d_in[12];
    const float* bn   = (const float*)d_in[13];
    const float* We   = (const float*)d_in[14];
    const float* be   = (const float*)d_in[15];
    const float* Wh   = (const float*)d_in[16];
    const float* bh   = (const float*)d_in[17];
    float* out = (float*)d_out;

    const int* src = ei;
    const int* dst = ei + EE;

    k_zero_misc<<<(NN + 255) / 256, 256>>>();
    k_deg<<<(EE + 255) / 256, 256>>>(dst);
    k_rdeg<<<(NN + 255) / 256, 256>>>();

    k_enc_nodes<<<(NN + BM - 1) / BM, TPB>>>(x, Wn0, bn0);
    k_enc_edges<<<EE / BM, TPB>>>(ea, We0, be0);

    for (int l = 0; l < 3; l++) {
        k_zero_agg<<<(NN * HH + 255) / 256, 256>>>();
        k_msg<<<EE / BM, TPB>>>(src, dst, WM + (ll)l * 384 * HH, bM + l * HH);
        k_update<<<(NN + BM - 1) / BM, TPB>>>(WU + (ll)l * 256 * HH, bU + l * HH,
                                              Wn + (ll)l * HH * HH, bn + l * HH);
        if (l < 2)  // layer-2 edge update is dead (e unused afterward)
            k_edge_lin<<<EE / BM, TPB>>>(We + (ll)l * HH * HH, be + l * HH);
    }

    k_pool<<<(NN * 32 + 255) / 256, 256>>>(bvec);
    k_head<<<1, GG>>>(Wh, bh, out);
}

// round 3
// speedup vs baseline: 1.9299x; 1.6055x over previous
#include <cuda_runtime.h>

#define NN 100000
#define EE 640000
#define GG 256
#define HH 128
#define TPB 256
#define BM 64

typedef long long ll;

// ---------------- scratch (static device globals; no allocation) ----------------
__device__ float g_h[NN * HH];            // node features
__device__ float g_agg[NN * HH];          // aggregation buffer
__device__ float g_p1[NN * HH];           // h @ WM1 (dst part)
__device__ float g_p2[NN * HH];           // h @ WM2 (src part)
__device__ float g_e[(ll)EE * HH];        // edge features
__device__ float g_rdeg[NN];
__device__ float g_deg[NN];
__device__ float g_pool[GG * HH];
__device__ float g_cnt[GG];

// ---------------- tile helpers ----------------
template<int KC>
__device__ __forceinline__ void load_B(float* Bs, const float* __restrict__ W, int k0) {
    int t = threadIdx.x;
#pragma unroll
    for (int i = 0; i < (KC * HH / 4) / TPB; i++) {
        int f = t + i * TPB;
        int k = f >> 5;
        int c = (f & 31) << 2;
        *(float4*)(Bs + k * HH + c) = *(const float4*)(W + (ll)(k0 + k) * HH + c);
    }
}

// 8x4 per-thread register tile; A reads are warp-broadcast float4.
template<int KB, int LDA>
__device__ __forceinline__ void mma8x4(const float* __restrict__ As,
                                       const float* __restrict__ Bs,
                                       int tr8, int tc4, float acc[8][4]) {
#pragma unroll
    for (int kb = 0; kb < KB; kb++) {
        float4 b0 = *(const float4*)(Bs + (kb * 4 + 0) * HH + tc4);
        float4 b1 = *(const float4*)(Bs + (kb * 4 + 1) * HH + tc4);
        float4 b2 = *(const float4*)(Bs + (kb * 4 + 2) * HH + tc4);
        float4 b3 = *(const float4*)(Bs + (kb * 4 + 3) * HH + tc4);
#pragma unroll
        for (int i = 0; i < 8; i++) {
            float4 a = *(const float4*)(As + (tr8 + i) * LDA + kb * 4);
            acc[i][0] += a.x * b0.x; acc[i][1] += a.x * b0.y; acc[i][2] += a.x * b0.z; acc[i][3] += a.x * b0.w;
            acc[i][0] += a.y * b1.x; acc[i][1] += a.y * b1.y; acc[i][2] += a.y * b1.z; acc[i][3] += a.y * b1.w;
            acc[i][0] += a.z * b2.x; acc[i][1] += a.z * b2.y; acc[i][2] += a.z * b2.z; acc[i][3] += a.z * b2.w;
            acc[i][0] += a.w * b3.x; acc[i][1] += a.w * b3.y; acc[i][2] += a.w * b3.z; acc[i][3] += a.w * b3.w;
        }
    }
}

__device__ __forceinline__ float4 relu4(const float acc[4], float4 b) {
    float4 v;
    v.x = fmaxf(acc[0] + b.x, 0.f);
    v.y = fmaxf(acc[1] + b.y, 0.f);
    v.z = fmaxf(acc[2] + b.z, 0.f);
    v.w = fmaxf(acc[3] + b.w, 0.f);
    return v;
}

// ---------------- small utility kernels ----------------
__global__ void k_zero_misc() {
    int i = blockIdx.x * blockDim.x + threadIdx.x;
    if (i < NN) g_deg[i] = 0.f;
    if (i < GG * HH) g_pool[i] = 0.f;
    if (i < GG) g_cnt[i] = 0.f;
}
__global__ void k_zero_agg() {
    int i = blockIdx.x * blockDim.x + threadIdx.x;
    if (i < NN * HH) g_agg[i] = 0.f;
}
__global__ void k_deg(const int* __restrict__ dst) {
    int e = blockIdx.x * blockDim.x + threadIdx.x;
    if (e < EE) atomicAdd(&g_deg[dst[e]], 1.f);
}
__global__ void k_rdeg() {
    int n = blockIdx.x * blockDim.x + threadIdx.x;
    if (n < NN) g_rdeg[n] = 1.f / fmaxf(g_deg[n], 1.f);
}

// ---------------- node encoder: h = relu(x @ Wn0 + bn0), [N,64]x[64,128] ----------------
__global__ void __launch_bounds__(TPB) k_enc_nodes(const float* __restrict__ x,
                                                   const float* __restrict__ W,
                                                   const float* __restrict__ b) {
    __shared__ __align__(16) float As[BM * 36];
    __shared__ __align__(16) float Bs[32 * HH];
    int t = threadIdx.x;
    int tr8 = (t >> 5) << 3, tc4 = (t & 31) << 2;
    int r = t >> 2, q = t & 3;
    int n0 = blockIdx.x * BM;
    int row = min(n0 + r, NN - 1);
    float acc[8][4] = {};
#pragma unroll 1
    for (int c = 0; c < 2; c++) {
        __syncthreads();
        const float* p = x + (ll)row * 64 + c * 32;
        *(float4*)(As + r * 36 + q * 4)      = *(const float4*)(p + q * 4);
        *(float4*)(As + r * 36 + 16 + q * 4) = *(const float4*)(p + 16 + q * 4);
        load_B<32>(Bs, W, c * 32);
        __syncthreads();
        mma8x4<8, 36>(As, Bs, tr8, tc4, acc);
    }
    float4 bb = *(const float4*)(b + tc4);
#pragma unroll
    for (int i = 0; i < 8; i++) {
        int rr = n0 + tr8 + i;
        if (rr < NN)
            *(float4*)(g_h + (ll)rr * HH + tc4) = relu4(acc[i], bb);
    }
}

// ---------------- edge encoder: e = relu(ea @ We0 + be0), [E,16]x[16,128] ----------------
__global__ void __launch_bounds__(TPB) k_enc_edges(const float* __restrict__ ea,
                                                   const float* __restrict__ W,
                                                   const float* __restrict__ b) {
    __shared__ __align__(16) float As[BM * 20];
    __shared__ __align__(16) float Bs[16 * HH];
    int t = threadIdx.x;
    int tr8 = (t >> 5) << 3, tc4 = (t & 31) << 2;
    int r = t >> 2, q = t & 3;
    int e0 = blockIdx.x * BM;
    float acc[8][4] = {};
    *(float4*)(As + r * 20 + q * 4) = *(const float4*)(ea + (ll)(e0 + r) * 16 + q * 4);
    load_B<16>(Bs, W, 0);
    __syncthreads();
    mma8x4<4, 20>(As, Bs, tr8, tc4, acc);
    float4 bb = *(const float4*)(b + tc4);
#pragma unroll
    for (int i = 0; i < 8; i++)
        *(float4*)(g_e + (ll)(e0 + tr8 + i) * HH + tc4) = relu4(acc[i], bb);
}

// ---------------- per-node message partials: P1 = h @ WM1, P2 = h @ WM2 ----------------
// blockIdx.y selects which half of WM (rows 0..127 -> P1, rows 128..255 -> P2).
__global__ void __launch_bounds__(TPB) k_node_pp(const float* __restrict__ WM) {
    const float* W = WM + (ll)blockIdx.y * HH * HH;
    float* outp = blockIdx.y ? g_p2 : g_p1;
    __shared__ __align__(16) float As[BM * 132];
    __shared__ __align__(16) float Bs[32 * HH];
    int t = threadIdx.x;
    int tr8 = (t >> 5) << 3, tc4 = (t & 31) << 2;
    int n0 = blockIdx.x * BM;
#pragma unroll
    for (int i = 0; i < 8; i++) {
        int f = t + i * TPB;
        int row = f >> 5, c4 = (f & 31) << 2;
        int rr = min(n0 + row, NN - 1);
        *(float4*)(As + row * 132 + c4) = *(const float4*)(g_h + (ll)rr * HH + c4);
    }
    float acc[8][4] = {};
#pragma unroll 1
    for (int c = 0; c < 4; c++) {
        __syncthreads();
        load_B<32>(Bs, W, c * 32);
        __syncthreads();
        mma8x4<8, 132>(As + c * 32, Bs, tr8, tc4, acc);
    }
#pragma unroll
    for (int i = 0; i < 8; i++) {
        int rr = n0 + tr8 + i;
        if (rr < NN) {
            float4 v = make_float4(acc[i][0], acc[i][1], acc[i][2], acc[i][3]);
            *(float4*)(outp + (ll)rr * HH + tc4) = v;
        }
    }
}

// ---------------- fused edge kernel:
// m = relu(e @ WM3 + P1[dst] + P2[src] + bM)  -> atomic scatter to agg[dst]
// if do_edge: e = relu(e @ We + be)           (reuses the staged e tile)
__global__ void __launch_bounds__(TPB) k_edge_fused(const int* __restrict__ src,
                                                    const int* __restrict__ dst,
                                                    const float* __restrict__ WM3,
                                                    const float* __restrict__ bM,
                                                    const float* __restrict__ We,
                                                    const float* __restrict__ be,
                                                    int do_edge) {
    __shared__ __align__(16) float As[BM * 132];
    __shared__ __align__(16) float Bs[32 * HH];
    int t = threadIdx.x;
    int tr8 = (t >> 5) << 3, tc4 = (t & 31) << 2;
    int e0 = blockIdx.x * BM;
    // stage e tile once (coalesced)
#pragma unroll
    for (int i = 0; i < 8; i++) {
        int f = t + i * TPB;
        int row = f >> 5, c4 = (f & 31) << 2;
        *(float4*)(As + row * 132 + c4) = *(const float4*)(g_e + (ll)(e0 + row) * HH + c4);
    }
    // GEMM 1: e @ WM3
    float acc[8][4] = {};
#pragma unroll 1
    for (int c = 0; c < 4; c++) {
        __syncthreads();
        load_B<32>(Bs, WM3, c * 32);
        __syncthreads();
        mma8x4<8, 132>(As + c * 32, Bs, tr8, tc4, acc);
    }
    // epilogue 1: add node partials, relu, scatter
    {
        float4 bb = *(const float4*)(bM + tc4);
#pragma unroll
        for (int i = 0; i < 8; i++) {
            int row = e0 + tr8 + i;
            int d = dst[row], s = src[row];
            float4 p1 = *(const float4*)(g_p1 + (ll)d * HH + tc4);
            float4 p2 = *(const float4*)(g_p2 + (ll)s * HH + tc4);
            float4 v;
            v.x = fmaxf(acc[i][0] + bb.x + p1.x + p2.x, 0.f);
            v.y = fmaxf(acc[i][1] + bb.y + p1.y + p2.y, 0.f);
            v.z = fmaxf(acc[i][2] + bb.z + p1.z + p2.z, 0.f);
            v.w = fmaxf(acc[i][3] + bb.w + p1.w + p2.w, 0.f);
            atomicAdd((float4*)(g_agg + (ll)d * HH + tc4), v);
        }
    }
    // GEMM 2 (optional): edge linear, same A tile
    if (do_edge) {
        float acc2[8][4] = {};
#pragma unroll 1
        for (int c = 0; c < 4; c++) {
            __syncthreads();
            load_B<32>(Bs, We, c * 32);
            __syncthreads();
            mma8x4<8, 132>(As + c * 32, Bs, tr8, tc4, acc2);
        }
        float4 b2 = *(const float4*)(be + tc4);
#pragma unroll
        for (int i = 0; i < 8; i++)
            *(float4*)(g_e + (ll)(e0 + tr8 + i) * HH + tc4) = relu4(acc2[i], b2);
    }
}

// ---------------- fused update + node linear:
// u = relu([h, agg/deg] @ WU + bU); h = relu(u @ Wn + bn)
__global__ void __launch_bounds__(TPB) k_update(const float* __restrict__ WU,
                                                const float* __restrict__ bU,
                                                const float* __restrict__ Wn,
                                                const float* __restrict__ bn) {
    __shared__ __align__(16) float As[BM * 36];
    __shared__ __align__(16) float Bs[32 * HH];
    __shared__ __align__(16) float Cs[BM * 132];   // u, row-major
    int t = threadIdx.x;
    int tr8 = (t >> 5) << 3, tc4 = (t & 31) << 2;
    int r = t >> 2, q = t & 3;
    int n0 = blockIdx.x * BM;
    int row = min(n0 + r, NN - 1);
    float rd = g_rdeg[row];
    float acc[8][4] = {};
#pragma unroll 1
    for (int c = 0; c < 8; c++) {
        __syncthreads();
        const float* p = (c < 4) ? (g_h + (ll)row * HH + c * 32)
                                 : (g_agg + (ll)row * HH + (c - 4) * 32);
        float sc = (c < 4) ? 1.f : rd;
        float4 v0 = *(const float4*)(p + q * 4);
        float4 v1 = *(const float4*)(p + 16 + q * 4);
        v0.x *= sc; v0.y *= sc; v0.z *= sc; v0.w *= sc;
        v1.x *= sc; v1.y *= sc; v1.z *= sc; v1.w *= sc;
        *(float4*)(As + r * 36 + q * 4)      = v0;
        *(float4*)(As + r * 36 + 16 + q * 4) = v1;
        load_B<32>(Bs, WU, c * 32);
        __syncthreads();
        mma8x4<8, 36>(As, Bs, tr8, tc4, acc);
    }
    {
        float4 bb = *(const float4*)(bU + tc4);
#pragma unroll
        for (int i = 0; i < 8; i++)
            *(float4*)(Cs + (tr8 + i) * 132 + tc4) = relu4(acc[i], bb);
    }
    float acc2[8][4] = {};
#pragma unroll 1
    for (int kc = 0; kc < 4; kc++) {
        __syncthreads();
        load_B<32>(Bs, Wn, kc * 32);
        __syncthreads();
        mma8x4<8, 132>(Cs + kc * 32, Bs, tr8, tc4, acc2);
    }
    float4 bb2 = *(const float4*)(bn + tc4);
#pragma unroll
    for (int i = 0; i < 8; i++) {
        int rr = n0 + tr8 + i;
        if (rr < NN)
            *(float4*)(g_h + (ll)rr * HH + tc4) = relu4(acc2[i], bb2);
    }
}

// ---------------- global mean pool + head ----------------
__global__ void k_pool(const int* __restrict__ bvec) {
    int idx = blockIdx.x * blockDim.x + threadIdx.x;
    if (idx < NN * 32) {
        int n = idx >> 5, c4 = (idx & 31) << 2;
        int g = bvec[n];
        float4 hv = *(const float4*)(g_h + (ll)n * HH + c4);
        atomicAdd((float4*)(g_pool + g * HH + c4), hv);
        if ((idx & 31) == 0) atomicAdd(&g_cnt[g], 1.f);
    }
}

__global__ void k_head(const float* __restrict__ Wh, const float* __restrict__ bh,
                       float* __restrict__ out) {
    int g = threadIdx.x;  // 256 graphs, one block
    float rc = 1.f / fmaxf(g_cnt[g], 1.f);
    float acc = bh[0];
#pragma unroll
    for (int k = 0; k < HH; k++)
        acc += g_pool[g * HH + k] * rc * Wh[k];
    out[g] = acc;
}

// ---------------- launch ----------------
extern "C" void kernel_launch(void* const* d_in, const int* in_sizes, int n_in,
                              void* d_out, int out_size) {
    const float* x    = (const float*)d_in[0];
    const int*   ei   = (const int*)d_in[1];
    const float* ea   = (const float*)d_in[2];
    const int*   bvec = (const int*)d_in[3];
    const float* Wn0  = (const float*)d_in[4];
    const float* bn0  = (const float*)d_in[5];
    const float* We0  = (const float*)d_in[6];
    const float* be0  = (const float*)d_in[7];
    const float* WM   = (const float*)d_in[8];
    const float* bM   = (const float*)d_in[9];
    const float* WU   = (const float*)d_in[10];
    const float* bU   = (const float*)d_in[11];
    const float* Wn   = (const float*)d_in[12];
    const float* bn   = (const float*)d_in[13];
    const float* We   = (const float*)d_in[14];
    const float* be   = (const float*)d_in[15];
    const float* Wh   = (const float*)d_in[16];
    const float* bh   = (const float*)d_in[17];
    float* out = (float*)d_out;

    const int* src = ei;
    const int* dst = ei + EE;

    k_zero_misc<<<(NN + 255) / 256, 256>>>();
    k_deg<<<(EE + 255) / 256, 256>>>(dst);
    k_rdeg<<<(NN + 255) / 256, 256>>>();

    k_enc_nodes<<<(NN + BM - 1) / BM, TPB>>>(x, Wn0, bn0);
    k_enc_edges<<<EE / BM, TPB>>>(ea, We0, be0);

    int nblk = (NN + BM - 1) / BM;
    for (int l = 0; l < 3; l++) {
        const float* WMl = WM + (ll)l * 384 * HH;
        k_node_pp<<<dim3(nblk, 2), TPB>>>(WMl);
        k_zero_agg<<<(NN * HH + 255) / 256, 256>>>();
        k_edge_fused<<<EE / BM, TPB>>>(src, dst,
                                       WMl + (ll)256 * HH, bM + l * HH,
                                       We + (ll)l * HH * HH, be + l * HH,
                                       l < 2 ? 1 : 0);
        k_update<<<nblk, TPB>>>(WU + (ll)l * 256 * HH, bU + l * HH,
                                Wn + (ll)l * HH * HH, bn + l * HH);
    }

    k_pool<<<(NN * 32 + 255) / 256, 256>>>(bvec);
    k_head<<<1, GG>>>(Wh, bh, out);
}

// round 4
// speedup vs baseline: 2.1907x; 1.1351x over previous
#include <cuda_runtime.h>
#include <cstdint>

#define NN 100000
#define EE 640000
#define GG 256
#define HH 128
#define TPB 256
#define BM 64
#define LDA 132
#define LDB 136

typedef long long ll;

// ---------------- scratch (static device globals; no allocation) ----------------
__device__ float g_h[NN * HH];
__device__ float g_agg[NN * HH];
__device__ float g_p1[NN * HH];           // h @ WM1 (dst part)
__device__ float g_p2[NN * HH];           // h @ WM2 (src part)
__device__ float g_e[(ll)EE * HH];
__device__ float g_rdeg[NN];
__device__ float g_deg[NN];
__device__ float g_pool[GG * HH];
__device__ float g_cnt[GG];

// ---------------- tf32 helpers ----------------
__device__ __forceinline__ uint32_t f2tf(float f) {
    uint32_t u;
    asm("cvt.rna.tf32.f32 %0, %1;" : "=r"(u) : "f"(f));
    return u;
}
__device__ __forceinline__ void mma_tf32(float* c, uint32_t a0, uint32_t a1,
                                         uint32_t a2, uint32_t a3,
                                         uint32_t b0, uint32_t b1) {
    asm volatile(
        "mma.sync.aligned.m16n8k8.row.col.f32.tf32.tf32.f32 "
        "{%0,%1,%2,%3}, {%4,%5,%6,%7}, {%8,%9}, {%0,%1,%2,%3};\n"
        : "+f"(c[0]), "+f"(c[1]), "+f"(c[2]), "+f"(c[3])
        : "r"(a0), "r"(a1), "r"(a2), "r"(a3), "r"(b0), "r"(b1));
}

// ---------------- fp32 tile helpers (node-side GEMMs) ----------------
template<int KC>
__device__ __forceinline__ void load_B(float* Bs, const float* __restrict__ W, int k0) {
    int t = threadIdx.x;
#pragma unroll
    for (int i = 0; i < (KC * HH / 4) / TPB; i++) {
        int f = t + i * TPB;
        int k = f >> 5;
        int c = (f & 31) << 2;
        *(float4*)(Bs + k * HH + c) = *(const float4*)(W + (ll)(k0 + k) * HH + c);
    }
}

template<int KB, int LA>
__device__ __forceinline__ void mma8x4(const float* __restrict__ As,
                                       const float* __restrict__ Bs,
                                       int tr8, int tc4, float acc[8][4]) {
#pragma unroll
    for (int kb = 0; kb < KB; kb++) {
        float4 b0 = *(const float4*)(Bs + (kb * 4 + 0) * HH + tc4);
        float4 b1 = *(const float4*)(Bs + (kb * 4 + 1) * HH + tc4);
        float4 b2 = *(const float4*)(Bs + (kb * 4 + 2) * HH + tc4);
        float4 b3 = *(const float4*)(Bs + (kb * 4 + 3) * HH + tc4);
#pragma unroll
        for (int i = 0; i < 8; i++) {
            float4 a = *(const float4*)(As + (tr8 + i) * LA + kb * 4);
            acc[i][0] += a.x * b0.x; acc[i][1] += a.x * b0.y; acc[i][2] += a.x * b0.z; acc[i][3] += a.x * b0.w;
            acc[i][0] += a.y * b1.x; acc[i][1] += a.y * b1.y; acc[i][2] += a.y * b1.z; acc[i][3] += a.y * b1.w;
            acc[i][0] += a.z * b2.x; acc[i][1] += a.z * b2.y; acc[i][2] += a.z * b2.z; acc[i][3] += a.z * b2.w;
            acc[i][0] += a.w * b3.x; acc[i][1] += a.w * b3.y; acc[i][2] += a.w * b3.z; acc[i][3] += a.w * b3.w;
        }
    }
}

__device__ __forceinline__ float4 relu4(const float acc[4], float4 b) {
    float4 v;
    v.x = fmaxf(acc[0] + b.x, 0.f);
    v.y = fmaxf(acc[1] + b.y, 0.f);
    v.z = fmaxf(acc[2] + b.z, 0.f);
    v.w = fmaxf(acc[3] + b.w, 0.f);
    return v;
}

// ---------------- small utility kernels ----------------
__global__ void k_zero_misc() {
    int i = blockIdx.x * blockDim.x + threadIdx.x;
    if (i < NN) g_deg[i] = 0.f;
    if (i < GG * HH) g_pool[i] = 0.f;
    if (i < GG) g_cnt[i] = 0.f;
}
__global__ void k_zero_agg() {
    int i = blockIdx.x * blockDim.x + threadIdx.x;
    if (i < NN * HH) g_agg[i] = 0.f;
}
__global__ void k_deg(const int* __restrict__ dst) {
    int e = blockIdx.x * blockDim.x + threadIdx.x;
    if (e < EE) atomicAdd(&g_deg[dst[e]], 1.f);
}
__global__ void k_rdeg() {
    int n = blockIdx.x * blockDim.x + threadIdx.x;
    if (n < NN) g_rdeg[n] = 1.f / fmaxf(g_deg[n], 1.f);
}

// ---------------- node encoder ----------------
__global__ void __launch_bounds__(TPB) k_enc_nodes(const float* __restrict__ x,
                                                   const float* __restrict__ W,
                                                   const float* __restrict__ b) {
    __shared__ __align__(16) float As[BM * 36];
    __shared__ __align__(16) float Bs[32 * HH];
    int t = threadIdx.x;
    int tr8 = (t >> 5) << 3, tc4 = (t & 31) << 2;
    int r = t >> 2, q = t & 3;
    int n0 = blockIdx.x * BM;
    int row = min(n0 + r, NN - 1);
    float acc[8][4] = {};
#pragma unroll 1
    for (int c = 0; c < 2; c++) {
        __syncthreads();
        const float* p = x + (ll)row * 64 + c * 32;
        *(float4*)(As + r * 36 + q * 4)      = *(const float4*)(p + q * 4);
        *(float4*)(As + r * 36 + 16 + q * 4) = *(const float4*)(p + 16 + q * 4);
        load_B<32>(Bs, W, c * 32);
        __syncthreads();
        mma8x4<8, 36>(As, Bs, tr8, tc4, acc);
    }
    float4 bb = *(const float4*)(b + tc4);
#pragma unroll
    for (int i = 0; i < 8; i++) {
        int rr = n0 + tr8 + i;
        if (rr < NN)
            *(float4*)(g_h + (ll)rr * HH + tc4) = relu4(acc[i], bb);
    }
}

// ---------------- edge encoder ----------------
__global__ void __launch_bounds__(TPB) k_enc_edges(const float* __restrict__ ea,
                                                   const float* __restrict__ W,
                                                   const float* __restrict__ b) {
    __shared__ __align__(16) float As[BM * 20];
    __shared__ __align__(16) float Bs[16 * HH];
    int t = threadIdx.x;
    int tr8 = (t >> 5) << 3, tc4 = (t & 31) << 2;
    int r = t >> 2, q = t & 3;
    int e0 = blockIdx.x * BM;
    float acc[8][4] = {};
    *(float4*)(As + r * 20 + q * 4) = *(const float4*)(ea + (ll)(e0 + r) * 16 + q * 4);
    load_B<16>(Bs, W, 0);
    __syncthreads();
    mma8x4<4, 20>(As, Bs, tr8, tc4, acc);
    float4 bb = *(const float4*)(b + tc4);
#pragma unroll
    for (int i = 0; i < 8; i++)
        *(float4*)(g_e + (ll)(e0 + tr8 + i) * HH + tc4) = relu4(acc[i], bb);
}

// ---------------- per-node message partials: P1 = h @ WM1, P2 = h @ WM2 ----------------
__global__ void __launch_bounds__(TPB) k_node_pp(const float* __restrict__ WM) {
    const float* W = WM + (ll)blockIdx.y * HH * HH;
    float* outp = blockIdx.y ? g_p2 : g_p1;
    __shared__ __align__(16) float As[BM * 132];
    __shared__ __align__(16) float Bs[32 * HH];
    int t = threadIdx.x;
    int tr8 = (t >> 5) << 3, tc4 = (t & 31) << 2;
    int n0 = blockIdx.x * BM;
#pragma unroll
    for (int i = 0; i < 8; i++) {
        int f = t + i * TPB;
        int row = f >> 5, c4 = (f & 31) << 2;
        int rr = min(n0 + row, NN - 1);
        *(float4*)(As + row * 132 + c4) = *(const float4*)(g_h + (ll)rr * HH + c4);
    }
    float acc[8][4] = {};
#pragma unroll 1
    for (int c = 0; c < 4; c++) {
        __syncthreads();
        load_B<32>(Bs, W, c * 32);
        __syncthreads();
        mma8x4<8, 132>(As + c * 32, Bs, tr8, tc4, acc);
    }
#pragma unroll
    for (int i = 0; i < 8; i++) {
        int rr = n0 + tr8 + i;
        if (rr < NN) {
            float4 v = make_float4(acc[i][0], acc[i][1], acc[i][2], acc[i][3]);
            *(float4*)(outp + (ll)rr * HH + tc4) = v;
        }
    }
}

// ---------------- tf32 fused edge kernel ----------------
// GEMM1: m = relu(e @ WM3 + P1[dst] + P2[src] + bM) -> atomic scatter to agg[dst]
// GEMM2 (do_edge): e = relu(e @ We + be), reusing staged e tile.
// SMEM: As = 64x132 tf32 (full K), R = union{ Bs 32x136 tf32 chunk, Cs 64x132 f32 }.
__global__ void __launch_bounds__(TPB) k_edge_tf32(const int* __restrict__ src,
                                                   const int* __restrict__ dst,
                                                   const float* __restrict__ WM3,
                                                   const float* __restrict__ bM,
                                                   const float* __restrict__ We,
                                                   const float* __restrict__ be,
                                                   int do_edge) {
    extern __shared__ uint32_t smem_u[];
    uint32_t* As = smem_u;                         // 64*LDA uints
    uint32_t* Bs = smem_u + BM * LDA;              // 32*LDB uints (aliased with Cs)
    float*    Cs = (float*)(smem_u + BM * LDA);    // 64*LDA floats

    int t = threadIdx.x;
    int lane = t & 31, wid = t >> 5;
    int wm = (wid >> 1) << 4;       // warp row base (0,16,32,48)
    int wn = (wid & 1) << 6;        // warp col base (0,64)
    int lr = lane >> 2, ka = lane & 3;
    ll e0 = (ll)blockIdx.x * BM;

    // stage e tile as tf32 (coalesced)
#pragma unroll
    for (int i = 0; i < 8; i++) {
        int f = t + i * TPB;
        int row = f >> 5, c4 = (f & 31) << 2;
        float4 v = *(const float4*)(g_e + (e0 + row) * HH + c4);
        uint4 u;
        u.x = f2tf(v.x); u.y = f2tf(v.y); u.z = f2tf(v.z); u.w = f2tf(v.w);
        *(uint4*)(As + row * LDA + c4) = u;
    }

    int npass = do_edge ? 2 : 1;
#pragma unroll 1
    for (int pass = 0; pass < npass; pass++) {
        const float* W = pass ? We : WM3;
        float acc[8][4];
#pragma unroll
        for (int i = 0; i < 8; i++)
#pragma unroll
            for (int j = 0; j < 4; j++) acc[i][j] = 0.f;

#pragma unroll 1
        for (int kc = 0; kc < 4; kc++) {
            __syncthreads();
#pragma unroll
            for (int i = 0; i < 4; i++) {
                int f = t + i * TPB;
                int krow = f >> 5, c4 = (f & 31) << 2;
                float4 v = *(const float4*)(W + (ll)(kc * 32 + krow) * HH + c4);
                uint4 u;
                u.x = f2tf(v.x); u.y = f2tf(v.y); u.z = f2tf(v.z); u.w = f2tf(v.w);
                *(uint4*)(Bs + krow * LDB + c4) = u;
            }
            __syncthreads();
#pragma unroll
            for (int ks = 0; ks < 4; ks++) {
                int kb = kc * 32 + ks * 8 + ka;
                uint32_t a0 = As[(wm + lr) * LDA + kb];
                uint32_t a1 = As[(wm + 8 + lr) * LDA + kb];
                uint32_t a2 = As[(wm + lr) * LDA + kb + 4];
                uint32_t a3 = As[(wm + 8 + lr) * LDA + kb + 4];
#pragma unroll
                for (int nt = 0; nt < 8; nt++) {
                    int nb = wn + nt * 8 + lr;
                    uint32_t b0 = Bs[(ks * 8 + ka) * LDB + nb];
                    uint32_t b1 = Bs[(ks * 8 + 4 + ka) * LDB + nb];
                    mma_tf32(acc[nt], a0, a1, a2, a3, b0, b1);
                }
            }
        }
        __syncthreads();   // done reading Bs; overlay Cs
        // stage C fragments -> Cs (row-major)
#pragma unroll
        for (int nt = 0; nt < 8; nt++) {
            int col = wn + nt * 8 + (ka << 1);
            *(float2*)(Cs + (wm + lr) * LDA + col)     = make_float2(acc[nt][0], acc[nt][1]);
            *(float2*)(Cs + (wm + 8 + lr) * LDA + col) = make_float2(acc[nt][2], acc[nt][3]);
        }
        __syncthreads();
        if (pass == 0) {
            // epilogue 1: add node partials + bias, relu, atomic scatter
#pragma unroll
            for (int i = 0; i < 8; i++) {
                int f = t + i * TPB;
                int row = f >> 5, c4 = (f & 31) << 2;
                int ge = (int)e0 + row;
                int d = dst[ge], s = src[ge];
                float4 c  = *(const float4*)(Cs + row * LDA + c4);
                float4 bb = *(const float4*)(bM + c4);
                float4 p1 = *(const float4*)(g_p1 + (ll)d * HH + c4);
                float4 p2 = *(const float4*)(g_p2 + (ll)s * HH + c4);
                float4 v;
                v.x = fmaxf(c.x + bb.x + p1.x + p2.x, 0.f);
                v.y = fmaxf(c.y + bb.y + p1.y + p2.y, 0.f);
                v.z = fmaxf(c.z + bb.z + p1.z + p2.z, 0.f);
                v.w = fmaxf(c.w + bb.w + p1.w + p2.w, 0.f);
                atomicAdd((float4*)(g_agg + (ll)d * HH + c4), v);
            }
        } else {
            // epilogue 2: relu + coalesced store to g_e
#pragma unroll
            for (int i = 0; i < 8; i++) {
                int f = t + i * TPB;
                int row = f >> 5, c4 = (f & 31) << 2;
                float4 c  = *(const float4*)(Cs + row * LDA + c4);
                float4 bb = *(const float4*)(be + c4);
                float4 v;
                v.x = fmaxf(c.x + bb.x, 0.f);
                v.y = fmaxf(c.y + bb.y, 0.f);
                v.z = fmaxf(c.z + bb.z, 0.f);
                v.w = fmaxf(c.w + bb.w, 0.f);
                *(float4*)(g_e + (e0 + row) * HH + c4) = v;
            }
        }
        if (pass + 1 < npass) __syncthreads();  // Cs consumed before restaging Bs
    }
}

// ---------------- fused update + node linear ----------------
__global__ void __launch_bounds__(TPB) k_update(const float* __restrict__ WU,
                                                const float* __restrict__ bU,
                                                const float* __restrict__ Wn,
                                                const float* __restrict__ bn) {
    __shared__ __align__(16) float As[BM * 36];
    __shared__ __align__(16) float Bs[32 * HH];
    __shared__ __align__(16) float Cs[BM * 132];
    int t = threadIdx.x;
    int tr8 = (t >> 5) << 3, tc4 = (t & 31) << 2;
    int r = t >> 2, q = t & 3;
    int n0 = blockIdx.x * BM;
    int row = min(n0 + r, NN - 1);
    float rd = g_rdeg[row];
    float acc[8][4] = {};
#pragma unroll 1
    for (int c = 0; c < 8; c++) {
        __syncthreads();
        const float* p = (c < 4) ? (g_h + (ll)row * HH + c * 32)
                                 : (g_agg + (ll)row * HH + (c - 4) * 32);
        float sc = (c < 4) ? 1.f : rd;
        float4 v0 = *(const float4*)(p + q * 4);
        float4 v1 = *(const float4*)(p + 16 + q * 4);
        v0.x *= sc; v0.y *= sc; v0.z *= sc; v0.w *= sc;
        v1.x *= sc; v1.y *= sc; v1.z *= sc; v1.w *= sc;
        *(float4*)(As + r * 36 + q * 4)      = v0;
        *(float4*)(As + r * 36 + 16 + q * 4) = v1;
        load_B<32>(Bs, WU, c * 32);
        __syncthreads();
        mma8x4<8, 36>(As, Bs, tr8, tc4, acc);
    }
    {
        float4 bb = *(const float4*)(bU + tc4);
#pragma unroll
        for (int i = 0; i < 8; i++)
            *(float4*)(Cs + (tr8 + i) * 132 + tc4) = relu4(acc[i], bb);
    }
    float acc2[8][4] = {};
#pragma unroll 1
    for (int kc = 0; kc < 4; kc++) {
        __syncthreads();
        load_B<32>(Bs, Wn, kc * 32);
        __syncthreads();
        mma8x4<8, 132>(Cs + kc * 32, Bs, tr8, tc4, acc2);
    }
    float4 bb2 = *(const float4*)(bn + tc4);
#pragma unroll
    for (int i = 0; i < 8; i++) {
        int rr = n0 + tr8 + i;
        if (rr < NN)
            *(float4*)(g_h + (ll)rr * HH + tc4) = relu4(acc2[i], bb2);
    }
}

// ---------------- global mean pool + head ----------------
__global__ void k_pool(const int* __restrict__ bvec) {
    int idx = blockIdx.x * blockDim.x + threadIdx.x;
    if (idx < NN * 32) {
        int n = idx >> 5, c4 = (idx & 31) << 2;
        int g = bvec[n];
        float4 hv = *(const float4*)(g_h + (ll)n * HH + c4);
        atomicAdd((float4*)(g_pool + g * HH + c4), hv);
        if ((idx & 31) == 0) atomicAdd(&g_cnt[g], 1.f);
    }
}

__global__ void k_head(const float* __restrict__ Wh, const float* __restrict__ bh,
                       float* __restrict__ out) {
    int g = threadIdx.x;
    float rc = 1.f / fmaxf(g_cnt[g], 1.f);
    float acc = bh[0];
#pragma unroll
    for (int k = 0; k < HH; k++)
        acc += g_pool[g * HH + k] * rc * Wh[k];
    out[g] = acc;
}

// ---------------- launch ----------------
extern "C" void kernel_launch(void* const* d_in, const int* in_sizes, int n_in,
                              void* d_out, int out_size) {
    const float* x    = (const float*)d_in[0];
    const int*   ei   = (const int*)d_in[1];
    const float* ea   = (const float*)d_in[2];
    const int*   bvec = (const int*)d_in[3];
    const float* Wn0  = (const float*)d_in[4];
    const float* bn0  = (const float*)d_in[5];
    const float* We0  = (const float*)d_in[6];
    const float* be0  = (const float*)d_in[7];
    const float* WM   = (const float*)d_in[8];
    const float* bM   = (const float*)d_in[9];
    const float* WU   = (const float*)d_in[10];
    const float* bU   = (const float*)d_in[11];
    const float* Wn   = (const float*)d_in[12];
    const float* bn   = (const float*)d_in[13];
    const float* We   = (const float*)d_in[14];
    const float* be   = (const float*)d_in[15];
    const float* Wh   = (const float*)d_in[16];
    const float* bh   = (const float*)d_in[17];
    float* out = (float*)d_out;

    const int* src = ei;
    const int* dst = ei + EE;

    const int EDGE_SMEM = (BM * LDA + 32 * LDB > BM * LDA + BM * LDA ?
                           BM * LDA + 32 * LDB : BM * LDA + BM * LDA) * 4;  // 67584 B
    static int attr_done = 0;
    if (!attr_done) {
        cudaFuncSetAttribute(k_edge_tf32, cudaFuncAttributeMaxDynamicSharedMemorySize,
                             EDGE_SMEM);
        attr_done = 1;
    }

    k_zero_misc<<<(NN + 255) / 256, 256>>>();
    k_deg<<<(EE + 255) / 256, 256>>>(dst);
    k_rdeg<<<(NN + 255) / 256, 256>>>();

    k_enc_nodes<<<(NN + BM - 1) / BM, TPB>>>(x, Wn0, bn0);
    k_enc_edges<<<EE / BM, TPB>>>(ea, We0, be0);

    int nblk = (NN + BM - 1) / BM;
    for (int l = 0; l < 3; l++) {
        const float* WMl = WM + (ll)l * 384 * HH;
        k_node_pp<<<dim3(nblk, 2), TPB>>>(WMl);
        k_zero_agg<<<(NN * HH + 255) / 256, 256>>>();
        k_edge_tf32<<<EE / BM, TPB, EDGE_SMEM>>>(src, dst,
                                                 WMl + (ll)256 * HH, bM + l * HH,
                                                 We + (ll)l * HH * HH, be + l * HH,
                                                 l < 2 ? 1 : 0);
        k_update<<<nblk, TPB>>>(WU + (ll)l * 256 * HH, bU + l * HH,
                                Wn + (ll)l * HH * HH, bn + l * HH);
    }

    k_pool<<<(NN * 32 + 255) / 256, 256>>>(bvec);
    k_head<<<1, GG>>>(Wh, bh, out);
}

// round 6
// speedup vs baseline: 2.2746x; 1.0383x over previous
#include <cuda_runtime.h>
#include <cstdint>

#define NN 100000
#define EE 640000
#define GG 256
#define HH 128
#define TPB 256
#define BM 64
#define LDA 132
#define LDB 136
#define LDAS 36

typedef long long ll;

// ---------------- scratch ----------------
__device__ float g_h[NN * HH];
__device__ float g_agg[NN * HH];
__device__ float g_p1[NN * HH];           // h @ WM1 (dst part)
__device__ float g_p2[NN * HH];           // h @ WM2 (src part)
__device__ float g_e[(ll)EE * HH];
__device__ float g_rdeg[NN];
__device__ float g_deg[NN];
__device__ float g_pool[GG * HH];
__device__ float g_cnt[GG];

// ---------------- tf32 helpers ----------------
__device__ __forceinline__ uint32_t f2tf(float f) {
    uint32_t u;
    asm("cvt.rna.tf32.f32 %0, %1;" : "=r"(u) : "f"(f));
    return u;
}
__device__ __forceinline__ void split1(float v, uint32_t& hi, uint32_t& lo) {
    hi = f2tf(v);
    lo = f2tf(v - __uint_as_float(hi));
}
__device__ __forceinline__ void mma_tf32(float* c, uint32_t a0, uint32_t a1,
                                         uint32_t a2, uint32_t a3,
                                         uint32_t b0, uint32_t b1) {
    asm volatile(
        "mma.sync.aligned.m16n8k8.row.col.f32.tf32.tf32.f32 "
        "{%0,%1,%2,%3}, {%4,%5,%6,%7}, {%8,%9}, {%0,%1,%2,%3};\n"
        : "+f"(c[0]), "+f"(c[1]), "+f"(c[2]), "+f"(c[3])
        : "r"(a0), "r"(a1), "r"(a2), "r"(a3), "r"(b0), "r"(b1));
}

// ---------------- dynamic smem partition (node kernels) ----------------
#define OFF_AH 0
#define OFF_AL (64 * LDAS)
#define OFF_BH (2 * 64 * LDAS)
#define OFF_BL (2 * 64 * LDAS + 32 * LDB)
#define OFF_CF (2 * 64 * LDAS + 2 * 32 * LDB)
#define NODE_SMEM ((2 * 64 * LDAS + 2 * 32 * LDB + 64 * LDA) * 4)

__device__ __forceinline__ void stage_B3(uint32_t* Bh, uint32_t* Bl,
                                         const float* __restrict__ W, int k0) {
    int t = threadIdx.x;
#pragma unroll
    for (int i = 0; i < 4; i++) {
        int f = t + i * TPB;
        int krow = f >> 5, c4 = (f & 31) << 2;
        float4 v = *(const float4*)(W + (ll)(k0 + krow) * HH + c4);
        uint4 h, l;
        split1(v.x, h.x, l.x); split1(v.y, h.y, l.y);
        split1(v.z, h.z, l.z); split1(v.w, h.w, l.w);
        *(uint4*)(Bh + krow * LDB + c4) = h;
        *(uint4*)(Bl + krow * LDB + c4) = l;
    }
}

__device__ __forceinline__ void splitA_store(uint32_t* Ah, uint32_t* Al,
                                             int r, int q, float4 v0, float4 v1) {
    uint4 h0, l0, h1, l1;
    split1(v0.x, h0.x, l0.x); split1(v0.y, h0.y, l0.y);
    split1(v0.z, h0.z, l0.z); split1(v0.w, h0.w, l0.w);
    split1(v1.x, h1.x, l1.x); split1(v1.y, h1.y, l1.y);
    split1(v1.z, h1.z, l1.z); split1(v1.w, h1.w, l1.w);
    *(uint4*)(Ah + r * LDAS + q * 4)      = h0;
    *(uint4*)(Al + r * LDAS + q * 4)      = l0;
    *(uint4*)(Ah + r * LDAS + 16 + q * 4) = h1;
    *(uint4*)(Al + r * LDAS + 16 + q * 4) = l1;
}

__device__ __forceinline__ void mma3_chunk(const uint32_t* Ah, const uint32_t* Al,
                                           const uint32_t* Bh, const uint32_t* Bl,
                                           int wm, int wn, int lr, int ka,
                                           float acc[8][4]) {
#pragma unroll
    for (int ks = 0; ks < 4; ks++) {
        int kb = ks * 8 + ka;
        uint32_t ah0 = Ah[(wm + lr) * LDAS + kb];
        uint32_t ah1 = Ah[(wm + 8 + lr) * LDAS + kb];
        uint32_t ah2 = Ah[(wm + lr) * LDAS + kb + 4];
        uint32_t ah3 = Ah[(wm + 8 + lr) * LDAS + kb + 4];
        uint32_t al0 = Al[(wm + lr) * LDAS + kb];
        uint32_t al1 = Al[(wm + 8 + lr) * LDAS + kb];
        uint32_t al2 = Al[(wm + lr) * LDAS + kb + 4];
        uint32_t al3 = Al[(wm + 8 + lr) * LDAS + kb + 4];
#pragma unroll
        for (int nt = 0; nt < 8; nt++) {
            int nb = wn + nt * 8 + lr;
            uint32_t bh0 = Bh[(ks * 8 + ka) * LDB + nb];
            uint32_t bh1 = Bh[(ks * 8 + 4 + ka) * LDB + nb];
            uint32_t bl0 = Bl[(ks * 8 + ka) * LDB + nb];
            uint32_t bl1 = Bl[(ks * 8 + 4 + ka) * LDB + nb];
            mma_tf32(acc[nt], ah0, ah1, ah2, ah3, bh0, bh1);
            mma_tf32(acc[nt], al0, al1, al2, al3, bh0, bh1);
            mma_tf32(acc[nt], ah0, ah1, ah2, ah3, bl0, bl1);
        }
    }
}

__device__ __forceinline__ void stage_A3_fromCf(uint32_t* Ah, uint32_t* Al,
                                                const float* Cf, int kc) {
    int t = threadIdx.x;
    int r = t >> 2, q = t & 3;
    float4 v0 = *(const float4*)(Cf + r * LDA + kc * 32 + q * 4);
    float4 v1 = *(const float4*)(Cf + r * LDA + kc * 32 + 16 + q * 4);
    splitA_store(Ah, Al, r, q, v0, v1);
}

__device__ __forceinline__ void frag_relu_toCf(float* Cf, const float acc[8][4],
                                               const float* __restrict__ bias,
                                               int wm, int wn, int lr, int ka) {
#pragma unroll
    for (int nt = 0; nt < 8; nt++) {
        int col = wn + nt * 8 + (ka << 1);
        float2 bb = *(const float2*)(bias + col);
        Cf[(wm + lr) * LDA + col]         = fmaxf(acc[nt][0] + bb.x, 0.f);
        Cf[(wm + lr) * LDA + col + 1]     = fmaxf(acc[nt][1] + bb.y, 0.f);
        Cf[(wm + 8 + lr) * LDA + col]     = fmaxf(acc[nt][2] + bb.x, 0.f);
        Cf[(wm + 8 + lr) * LDA + col + 1] = fmaxf(acc[nt][3] + bb.y, 0.f);
    }
}

__device__ __forceinline__ void p_passes(uint32_t* Ah, uint32_t* Al,
                                         uint32_t* Bh, uint32_t* Bl, float* Cf,
                                         const float* __restrict__ WM1,
                                         int n0, int wm, int wn, int lr, int ka) {
#pragma unroll 1
    for (int pp = 0; pp < 2; pp++) {
        const float* W = WM1 + (ll)pp * HH * HH;
        float* P = pp ? g_p2 : g_p1;
        float acc[8][4];
#pragma unroll
        for (int i = 0; i < 8; i++)
#pragma unroll
            for (int j = 0; j < 4; j++) acc[i][j] = 0.f;
#pragma unroll 1
        for (int kc = 0; kc < 4; kc++) {
            __syncthreads();
            stage_A3_fromCf(Ah, Al, Cf, kc);
            stage_B3(Bh, Bl, W, kc * 32);
            __syncthreads();
            mma3_chunk(Ah, Al, Bh, Bl, wm, wn, lr, ka, acc);
        }
        int row0 = n0 + wm + lr, row1 = row0 + 8;
#pragma unroll
        for (int nt = 0; nt < 8; nt++) {
            int col = wn + nt * 8 + (ka << 1);
            if (row0 < NN)
                *(float2*)(P + (ll)row0 * HH + col) = make_float2(acc[nt][0], acc[nt][1]);
            if (row1 < NN)
                *(float2*)(P + (ll)row1 * HH + col) = make_float2(acc[nt][2], acc[nt][3]);
        }
    }
}

// ---------------- fp32 helpers (encoders) ----------------
template<int KC>
__device__ __forceinline__ void load_B(float* Bs, const float* __restrict__ W, int k0) {
    int t = threadIdx.x;
#pragma unroll
    for (int i = 0; i < (KC * HH / 4) / TPB; i++) {
        int f = t + i * TPB;
        int k = f >> 5;
        int c = (f & 31) << 2;
        *(float4*)(Bs + k * HH + c) = *(const float4*)(W + (ll)(k0 + k) * HH + c);
    }
}

template<int KB, int LA>
__device__ __forceinline__ void mma8x4(const float* __restrict__ As,
                                       const float* __restrict__ Bs,
                                       int tr8, int tc4, float acc[8][4]) {
#pragma unroll
    for (int kb = 0; kb < KB; kb++) {
        float4 b0 = *(const float4*)(Bs + (kb * 4 + 0) * HH + tc4);
        float4 b1 = *(const float4*)(Bs + (kb * 4 + 1) * HH + tc4);
        float4 b2 = *(const float4*)(Bs + (kb * 4 + 2) * HH + tc4);
        float4 b3 = *(const float4*)(Bs + (kb * 4 + 3) * HH + tc4);
#pragma unroll
        for (int i = 0; i < 8; i++) {
            float4 a = *(const float4*)(As + (tr8 + i) * LA + kb * 4);
            acc[i][0] += a.x * b0.x; acc[i][1] += a.x * b0.y; acc[i][2] += a.x * b0.z; acc[i][3] += a.x * b0.w;
            acc[i][0] += a.y * b1.x; acc[i][1] += a.y * b1.y; acc[i][2] += a.y * b1.z; acc[i][3] += a.y * b1.w;
            acc[i][0] += a.z * b2.x; acc[i][1] += a.z * b2.y; acc[i][2] += a.z * b2.z; acc[i][3] += a.z * b2.w;
            acc[i][0] += a.w * b3.x; acc[i][1] += a.w * b3.y; acc[i][2] += a.w * b3.z; acc[i][3] += a.w * b3.w;
        }
    }
}

__device__ __forceinline__ float4 relu4(const float acc[4], float4 b) {
    float4 v;
    v.x = fmaxf(acc[0] + b.x, 0.f);
    v.y = fmaxf(acc[1] + b.y, 0.f);
    v.z = fmaxf(acc[2] + b.z, 0.f);
    v.w = fmaxf(acc[3] + b.w, 0.f);
    return v;
}

// ---------------- small utility kernels ----------------
__global__ void k_zero_misc() {
    int i = blockIdx.x * blockDim.x + threadIdx.x;
    if (i < NN) g_deg[i] = 0.f;
    if (i < GG * HH) g_pool[i] = 0.f;
    if (i < GG) g_cnt[i] = 0.f;
}
__global__ void k_zero_agg() {
    int i = blockIdx.x * blockDim.x + threadIdx.x;
    if (i < NN * HH) g_agg[i] = 0.f;
}
__global__ void k_deg(const int* __restrict__ dst) {
    int e = blockIdx.x * blockDim.x + threadIdx.x;
    if (e < EE) atomicAdd(&g_deg[dst[e]], 1.f);
}
__global__ void k_rdeg() {
    int n = blockIdx.x * blockDim.x + threadIdx.x;
    if (n < NN) g_rdeg[n] = 1.f / fmaxf(g_deg[n], 1.f);
}

// ---------------- fused node encoder: h = relu(x@Wn0+bn0); P1/P2 for layer 0 ----------------
__global__ void __launch_bounds__(TPB) k_enc_fused(const float* __restrict__ x,
                                                   const float* __restrict__ W,
                                                   const float* __restrict__ b,
                                                   const float* __restrict__ WM1) {
    extern __shared__ uint32_t sm[];
    uint32_t* Ah = sm + OFF_AH;
    uint32_t* Al = sm + OFF_AL;
    uint32_t* Bh = sm + OFF_BH;
    uint32_t* Bl = sm + OFF_BL;
    float*    Cf = (float*)(sm + OFF_CF);
    float*    As = (float*)Ah;
    float*    Bs = (float*)Bh;

    int t = threadIdx.x;
    int lane = t & 31, wid = t >> 5;
    int wm = (wid >> 1) << 4, wn = (wid & 1) << 6;
    int lr = lane >> 2, ka = lane & 3;
    int tr8 = (t >> 5) << 3, tc4 = (t & 31) << 2;
    int r = t >> 2, q = t & 3;
    int n0 = blockIdx.x * BM;
    int row = min(n0 + r, NN - 1);

    float acc[8][4] = {};
#pragma unroll 1
    for (int c = 0; c < 2; c++) {
        __syncthreads();
        const float* p = x + (ll)row * 64 + c * 32;
        *(float4*)(As + r * LDAS + q * 4)      = *(const float4*)(p + q * 4);
        *(float4*)(As + r * LDAS + 16 + q * 4) = *(const float4*)(p + 16 + q * 4);
        load_B<32>(Bs, W, c * 32);
        __syncthreads();
        mma8x4<8, LDAS>(As, Bs, tr8, tc4, acc);
    }
    __syncthreads();
    float4 bb = *(const float4*)(b + tc4);
#pragma unroll
    for (int i = 0; i < 8; i++) {
        float4 v = relu4(acc[i], bb);
        int rr = n0 + tr8 + i;
        *(float4*)(Cf + (tr8 + i) * LDA + tc4) = v;
        if (rr < NN)
            *(float4*)(g_h + (ll)rr * HH + tc4) = v;
    }
    p_passes(Ah, Al, Bh, Bl, Cf, WM1, n0, wm, wn, lr, ka);
}

// ---------------- edge encoder ----------------
__global__ void __launch_bounds__(TPB) k_enc_edges(const float* __restrict__ ea,
                                                   const float* __restrict__ W,
                                                   const float* __restrict__ b) {
    __shared__ __align__(16) float As[BM * 20];
    __shared__ __align__(16) float Bs[16 * HH];
    int t = threadIdx.x;
    int tr8 = (t >> 5) << 3, tc4 = (t & 31) << 2;
    int r = t >> 2, q = t & 3;
    int e0 = blockIdx.x * BM;
    float acc[8][4] = {};
    *(float4*)(As + r * 20 + q * 4) = *(const float4*)(ea + (ll)(e0 + r) * 16 + q * 4);
    load_B<16>(Bs, W, 0);
    __syncthreads();
    mma8x4<4, 20>(As, Bs, tr8, tc4, acc);
    float4 bb = *(const float4*)(b + tc4);
#pragma unroll
    for (int i = 0; i < 8; i++)
        *(float4*)(g_e + (ll)(e0 + tr8 + i) * HH + tc4) = relu4(acc[i], bb);
}

// ---------------- tf32 fused edge kernel (validated in R4) ----------------
__global__ void __launch_bounds__(TPB) k_edge_tf32(const int* __restrict__ src,
                                                   const int* __restrict__ dst,
                                                   const float* __restrict__ WM3,
                                                   const float* __restrict__ bM,
                                                   const float* __restrict__ We,
                                                   const float* __restrict__ be,
                                                   int do_edge) {
    extern __shared__ uint32_t smem_u[];
    uint32_t* As = smem_u;
    uint32_t* Bs = smem_u + BM * LDA;
    float*    Cs = (float*)(smem_u + BM * LDA);

    int t = threadIdx.x;
    int lane = t & 31, wid = t >> 5;
    int wm = (wid >> 1) << 4;
    int wn = (wid & 1) << 6;
    int lr = lane >> 2, ka = lane & 3;
    ll e0 = (ll)blockIdx.x * BM;

#pragma unroll
    for (int i = 0; i < 8; i++) {
        int f = t + i * TPB;
        int row = f >> 5, c4 = (f & 31) << 2;
        float4 v = *(const float4*)(g_e + (e0 + row) * HH + c4);
        uint4 u;
        u.x = f2tf(v.x); u.y = f2tf(v.y); u.z = f2tf(v.z); u.w = f2tf(v.w);
        *(uint4*)(As + row * LDA + c4) = u;
    }

    int npass = do_edge ? 2 : 1;
#pragma unroll 1
    for (int pass = 0; pass < npass; pass++) {
        const float* W = pass ? We : WM3;
        float acc[8][4];
#pragma unroll
        for (int i = 0; i < 8; i++)
#pragma unroll
            for (int j = 0; j < 4; j++) acc[i][j] = 0.f;

#pragma unroll 1
        for (int kc = 0; kc < 4; kc++) {
            __syncthreads();
#pragma unroll
            for (int i = 0; i < 4; i++) {
                int f = t + i * TPB;
                int krow = f >> 5, c4 = (f & 31) << 2;
                float4 v = *(const float4*)(W + (ll)(kc * 32 + krow) * HH + c4);
                uint4 u;
                u.x = f2tf(v.x); u.y = f2tf(v.y); u.z = f2tf(v.z); u.w = f2tf(v.w);
                *(uint4*)(Bs + krow * LDB + c4) = u;
            }
            __syncthreads();
#pragma unroll
            for (int ks = 0; ks < 4; ks++) {
                int kb = kc * 32 + ks * 8 + ka;
                uint32_t a0 = As[(wm + lr) * LDA + kb];
                uint32_t a1 = As[(wm + 8 + lr) * LDA + kb];
                uint32_t a2 = As[(wm + lr) * LDA + kb + 4];
                uint32_t a3 = As[(wm + 8 + lr) * LDA + kb + 4];
#pragma unroll
                for (int nt = 0; nt < 8; nt++) {
                    int nb = wn + nt * 8 + lr;
                    uint32_t b0 = Bs[(ks * 8 + ka) * LDB + nb];
                    uint32_t b1 = Bs[(ks * 8 + 4 + ka) * LDB + nb];
                    mma_tf32(acc[nt], a0, a1, a2, a3, b0, b1);
                }
            }
        }
        __syncthreads();
#pragma unroll
        for (int nt = 0; nt < 8; nt++) {
            int col = wn + nt * 8 + (ka << 1);
            *(float2*)(Cs + (wm + lr) * LDA + col)     = make_float2(acc[nt][0], acc[nt][1]);
            *(float2*)(Cs + (wm + 8 + lr) * LDA + col) = make_float2(acc[nt][2], acc[nt][3]);
        }
        __syncthreads();
        if (pass == 0) {
#pragma unroll
            for (int i = 0; i < 8; i++) {
                int f = t + i * TPB;
                int row = f >> 5, c4 = (f & 31) << 2;
                int ge = (int)e0 + row;
                int d = dst[ge], s = src[ge];
                float4 c  = *(const float4*)(Cs + row * LDA + c4);
                float4 bb = *(const float4*)(bM + c4);
                float4 p1 = *(const float4*)(g_p1 + (ll)d * HH + c4);
                float4 p2 = *(const float4*)(g_p2 + (ll)s * HH + c4);
                float4 v;
                v.x = fmaxf(c.x + bb.x + p1.x + p2.x, 0.f);
                v.y = fmaxf(c.y + bb.y + p1.y + p2.y, 0.f);
                v.z = fmaxf(c.z + bb.z + p1.z + p2.z, 0.f);
                v.w = fmaxf(c.w + bb.w + p1.w + p2.w, 0.f);
                atomicAdd((float4*)(g_agg + (ll)d * HH + c4), v);
            }
        } else {
#pragma unroll
            for (int i = 0; i < 8; i++) {
                int f = t + i * TPB;
                int row = f >> 5, c4 = (f & 31) << 2;
                float4 c  = *(const float4*)(Cs + row * LDA + c4);
                float4 bb = *(const float4*)(be + c4);
                float4 v;
                v.x = fmaxf(c.x + bb.x, 0.f);
                v.y = fmaxf(c.y + bb.y, 0.f);
                v.z = fmaxf(c.z + bb.z, 0.f);
                v.w = fmaxf(c.w + bb.w, 0.f);
                *(float4*)(g_e + (e0 + row) * HH + c4) = v;
            }
        }
        if (pass + 1 < npass) __syncthreads();
    }
}

// ---------------- fused update (3xTF32): u -> hnew -> P1/P2(next) ----------------
__global__ void __launch_bounds__(TPB) k_update_fused(const float* __restrict__ WU,
                                                      const float* __restrict__ bU,
                                                      const float* __restrict__ Wn,
                                                      const float* __restrict__ bn,
                                                      const float* __restrict__ WM1_next,
                                                      int has_next) {
    extern __shared__ uint32_t sm[];
    uint32_t* Ah = sm + OFF_AH;
    uint32_t* Al = sm + OFF_AL;
    uint32_t* Bh = sm + OFF_BH;
    uint32_t* Bl = sm + OFF_BL;
    float*    Cf = (float*)(sm + OFF_CF);

    int t = threadIdx.x;
    int lane = t & 31, wid = t >> 5;
    int wm = (wid >> 1) << 4, wn = (wid & 1) << 6;
    int lr = lane >> 2, ka = lane & 3;
    int r = t >> 2, q = t & 3;
    int n0 = blockIdx.x * BM;
    int row = min(n0 + r, NN - 1);
    float rd = g_rdeg[row];

    // ---- stage 1: u = relu([h | agg*rdeg] @ WU + bU), K=256 ----
    float acc[8][4];
#pragma unroll
    for (int i = 0; i < 8; i++)
#pragma unroll
        for (int j = 0; j < 4; j++) acc[i][j] = 0.f;
#pragma unroll 1
    for (int c = 0; c < 8; c++) {
        __syncthreads();
        const float* p = (c < 4) ? (g_h + (ll)row * HH + c * 32)
                                 : (g_agg + (ll)row * HH + (c - 4) * 32);
        float sc = (c < 4) ? 1.f : rd;
        float4 v0 = *(const float4*)(p + q * 4);
        float4 v1 = *(const float4*)(p + 16 + q * 4);
        v0.x *= sc; v0.y *= sc; v0.z *= sc; v0.w *= sc;
        v1.x *= sc; v1.y *= sc; v1.z *= sc; v1.w *= sc;
        splitA_store(Ah, Al, r, q, v0, v1);
        stage_B3(Bh, Bl, WU, c * 32);
        __syncthreads();
        mma3_chunk(Ah, Al, Bh, Bl, wm, wn, lr, ka, acc);
    }
    frag_relu_toCf(Cf, acc, bU, wm, wn, lr, ka);

    // ---- stage 2: hnew = relu(u @ Wn + bn), K=128 ----
#pragma unroll
    for (int i = 0; i < 8; i++)
#pragma unroll
        for (int j = 0; j < 4; j++) acc[i][j] = 0.f;
#pragma unroll 1
    for (int kc = 0; kc < 4; kc++) {
        __syncthreads();
        stage_A3_fromCf(Ah, Al, Cf, kc);
        stage_B3(Bh, Bl, Wn, kc * 32);
        __syncthreads();
        mma3_chunk(Ah, Al, Bh, Bl, wm, wn, lr, ka, acc);
    }
    __syncthreads();            // all Cf(u) reads complete before overwrite
    frag_relu_toCf(Cf, acc, bn, wm, wn, lr, ka);
    __syncthreads();
    // coalesced h store: 64 rows x 128 cols = 2048 float4 = 256 thr x 8 iters
#pragma unroll
    for (int i = 0; i < 8; i++) {
        int f = t + i * TPB;
        int rr = f >> 5, c4 = (f & 31) << 2;
        int gr = n0 + rr;
        if (gr < NN)
            *(float4*)(g_h + (ll)gr * HH + c4) = *(const float4*)(Cf + rr * LDA + c4);
    }

    // ---- stage 3: P1/P2 for next layer ----
    if (has_next)
        p_passes(Ah, Al, Bh, Bl, Cf, WM1_next, n0, wm, wn, lr, ka);
}

// ---------------- global mean pool + head ----------------
__global__ void k_pool(const int* __restrict__ bvec) {
    int idx = blockIdx.x * blockDim.x + threadIdx.x;
    if (idx < NN * 32) {
        int n = idx >> 5, c4 = (idx & 31) << 2;
        int g = bvec[n];
        float4 hv = *(const float4*)(g_h + (ll)n * HH + c4);
        atomicAdd((float4*)(g_pool + g * HH + c4), hv);
        if ((idx & 31) == 0) atomicAdd(&g_cnt[g], 1.f);
    }
}

__global__ void k_head(const float* __restrict__ Wh, const float* __restrict__ bh,
                       float* __restrict__ out) {
    int g = threadIdx.x;
    float rc = 1.f / fmaxf(g_cnt[g], 1.f);
    float acc = bh[0];
#pragma unroll
    for (int k = 0; k < HH; k++)
        acc += g_pool[g * HH + k] * rc * Wh[k];
    out[g] = acc;
}

// ---------------- launch ----------------
extern "C" void kernel_launch(void* const* d_in, const int* in_sizes, int n_in,
                              void* d_out, int out_size) {
    const float* x    = (const float*)d_in[0];
    const int*   ei   = (const int*)d_in[1];
    const float* ea   = (const float*)d_in[2];
    const int*   bvec = (const int*)d_in[3];
    const float* Wn0  = (const float*)d_in[4];
    const float* bn0  = (const float*)d_in[5];
    const float* We0  = (const float*)d_in[6];
    const float* be0  = (const float*)d_in[7];
    const float* WM   = (const float*)d_in[8];
    const float* bM   = (const float*)d_in[9];
    const float* WU   = (const float*)d_in[10];
    const float* bU   = (const float*)d_in[11];
    const float* Wn   = (const float*)d_in[12];
    const float* bn   = (const float*)d_in[13];
    const float* We   = (const float*)d_in[14];
    const float* be   = (const float*)d_in[15];
    const float* Wh   = (const float*)d_in[16];
    const float* bh   = (const float*)d_in[17];
    float* out = (float*)d_out;

    const int* src = ei;
    const int* dst = ei + EE;

    const int EDGE_SMEM = (BM * LDA + BM * LDA) * 4;
    static int attr_done = 0;
    if (!attr_done) {
        cudaFuncSetAttribute(k_edge_tf32, cudaFuncAttributeMaxDynamicSharedMemorySize,
                             EDGE_SMEM);
        cudaFuncSetAttribute(k_enc_fused, cudaFuncAttributeMaxDynamicSharedMemorySize,
                             NODE_SMEM);
        cudaFuncSetAttribute(k_update_fused, cudaFuncAttributeMaxDynamicSharedMemorySize,
                             NODE_SMEM);
        attr_done = 1;
    }

    k_zero_misc<<<(NN + 255) / 256, 256>>>();
    k_deg<<<(EE + 255) / 256, 256>>>(dst);
    k_rdeg<<<(NN + 255) / 256, 256>>>();

    int nblk = (NN + BM - 1) / BM;
    k_enc_fused<<<nblk, TPB, NODE_SMEM>>>(x, Wn0, bn0, WM);
    k_enc_edges<<<EE / BM, TPB>>>(ea, We0, be0);

    for (int l = 0; l < 3; l++) {
        const float* WMl = WM + (ll)l * 384 * HH;
        k_zero_agg<<<(NN * HH + 255) / 256, 256>>>();
        k_edge_tf32<<<EE / BM, TPB, EDGE_SMEM>>>(src, dst,
                                                 WMl + (ll)256 * HH, bM + l * HH,
                                                 We + (ll)l * HH * HH, be + l * HH,
                                                 l < 2 ? 1 : 0);
        k_update_fused<<<nblk, TPB, NODE_SMEM>>>(WU + (ll)l * 256 * HH, bU + l * HH,
                                                 Wn + (ll)l * HH * HH, bn + l * HH,
                                                 WM + (ll)(l + 1) * 384 * HH,
                                                 l < 2 ? 1 : 0);
    }

    k_pool<<<(NN * 32 + 255) / 256, 256>>>(bvec);
    k_head<<<1, GG>>>(Wh, bh, out);
}

// round 7
// speedup vs baseline: 2.6696x; 1.1736x over previous
#include <cuda_runtime.h>
#include <cstdint>

#define NN 100000
#define EE 640000
#define GG 256
#define HH 128
#define TPB 256
#define BM 64
#define LDA 132
#define LDB 136
#define LDAS 36
#define LDAP 20
#define LDBP 136

typedef long long ll;

// ---------------- scratch ----------------
__device__ float g_h[NN * HH];
__device__ float g_agg[NN * HH];
__device__ float g_p1[NN * HH];
__device__ float g_p2[NN * HH];
__device__ float g_e[(ll)EE * HH];
__device__ float g_rdeg[NN];
__device__ float g_deg[NN];
__device__ float g_pool[GG * HH];
__device__ float g_cnt[GG];

// ---------------- tf32 helpers (edge kernel) ----------------
__device__ __forceinline__ uint32_t f2tf(float f) {
    uint32_t u;
    asm("cvt.rna.tf32.f32 %0, %1;" : "=r"(u) : "f"(f));
    return u;
}
__device__ __forceinline__ void mma_tf32(float* c, uint32_t a0, uint32_t a1,
                                         uint32_t a2, uint32_t a3,
                                         uint32_t b0, uint32_t b1) {
    asm volatile(
        "mma.sync.aligned.m16n8k8.row.col.f32.tf32.tf32.f32 "
        "{%0,%1,%2,%3}, {%4,%5,%6,%7}, {%8,%9}, {%0,%1,%2,%3};\n"
        : "+f"(c[0]), "+f"(c[1]), "+f"(c[2]), "+f"(c[3])
        : "r"(a0), "r"(a1), "r"(a2), "r"(a3), "r"(b0), "r"(b1));
}

// ---------------- bf16 split helpers (node kernels) ----------------
// pack (v0 -> lower bf16, v1 -> upper bf16); hi/lo split per element.
__device__ __forceinline__ void split_pack(float v0, float v1,
                                           uint32_t& ph, uint32_t& pl) {
    uint32_t h;
    asm("cvt.rn.bf16x2.f32 %0, %1, %2;" : "=r"(h) : "f"(v1), "f"(v0));
    float h0 = __uint_as_float(h << 16);
    float h1 = __uint_as_float(h & 0xffff0000u);
    asm("cvt.rn.bf16x2.f32 %0, %1, %2;" : "=r"(pl) : "f"(v1 - h1), "f"(v0 - h0));
    ph = h;
}
__device__ __forceinline__ void mma_bf16(float* c, uint32_t a0, uint32_t a1,
                                         uint32_t a2, uint32_t a3,
                                         uint32_t b0, uint32_t b1) {
    asm volatile(
        "mma.sync.aligned.m16n8k16.row.col.f32.bf16.bf16.f32 "
        "{%0,%1,%2,%3}, {%4,%5,%6,%7}, {%8,%9}, {%0,%1,%2,%3};\n"
        : "+f"(c[0]), "+f"(c[1]), "+f"(c[2]), "+f"(c[3])
        : "r"(a0), "r"(a1), "r"(a2), "r"(a3), "r"(b0), "r"(b1));
}

// ---------------- node-kernel smem partition (uint32 words) ----------------
#define OFF_APH 0
#define OFF_APL (64 * LDAP)
#define OFF_BPH (2 * 64 * LDAP)
#define OFF_BPL (2 * 64 * LDAP + 16 * LDBP)
#define OFF_CF  (2 * 64 * LDAP + 2 * 16 * LDBP)
#define NODE_SMEM ((2 * 64 * LDAP + 2 * 16 * LDBP + 64 * LDA) * 4)

// stage a 32-row K-chunk of W [K][128] as packed bf16 hi/lo pairs [kp][n]
__device__ __forceinline__ void stage_Bbf(uint32_t* Bh, uint32_t* Bl,
                                          const float* __restrict__ W, int k0) {
    int t = threadIdx.x;
#pragma unroll
    for (int i = 0; i < 2; i++) {
        int f = t + i * TPB;
        int kp = f >> 5, n = (f & 31) << 2;
        const float* r0 = W + (ll)(k0 + 2 * kp) * HH + n;
        const float* r1 = r0 + HH;
        float4 va = *(const float4*)r0;
        float4 vb = *(const float4*)r1;
        uint4 h, l;
        split_pack(va.x, vb.x, h.x, l.x);
        split_pack(va.y, vb.y, h.y, l.y);
        split_pack(va.z, vb.z, h.z, l.z);
        split_pack(va.w, vb.w, h.w, l.w);
        *(uint4*)(Bh + kp * LDBP + n) = h;
        *(uint4*)(Bl + kp * LDBP + n) = l;
    }
}

// stage one thread's A contribution: row r, float4 v0 (k=4q..), v1 (k=16+4q..)
__device__ __forceinline__ void stage_Abf(uint32_t* Ah, uint32_t* Al,
                                          int r, int q, float4 v0, float4 v1) {
    uint32_t h0, l0, h1, l1;
    split_pack(v0.x, v0.y, h0, l0);
    split_pack(v0.z, v0.w, h1, l1);
    *(uint2*)(Ah + r * LDAP + 2 * q) = make_uint2(h0, h1);
    *(uint2*)(Al + r * LDAP + 2 * q) = make_uint2(l0, l1);
    split_pack(v1.x, v1.y, h0, l0);
    split_pack(v1.z, v1.w, h1, l1);
    *(uint2*)(Ah + r * LDAP + 8 + 2 * q) = make_uint2(h0, h1);
    *(uint2*)(Al + r * LDAP + 8 + 2 * q) = make_uint2(l0, l1);
}

__device__ __forceinline__ void stage_Abf_fromCf(uint32_t* Ah, uint32_t* Al,
                                                 const float* Cf, int kc) {
    int t = threadIdx.x;
    int r = t >> 2, q = t & 3;
    float4 v0 = *(const float4*)(Cf + r * LDA + kc * 32 + q * 4);
    float4 v1 = *(const float4*)(Cf + r * LDA + kc * 32 + 16 + q * 4);
    stage_Abf(Ah, Al, r, q, v0, v1);
}

// 3xBF16 mma over one 32-K chunk; warp computes 16x64
__device__ __forceinline__ void mma3_bf(const uint32_t* Ah, const uint32_t* Al,
                                        const uint32_t* Bh, const uint32_t* Bl,
                                        int wm, int wn, int lr, int ka,
                                        float acc[8][4]) {
#pragma unroll
    for (int ks = 0; ks < 2; ks++) {
        int kpb = ks * 8;
        uint32_t ah0 = Ah[(wm + lr) * LDAP + kpb + ka];
        uint32_t ah1 = Ah[(wm + 8 + lr) * LDAP + kpb + ka];
        uint32_t ah2 = Ah[(wm + lr) * LDAP + kpb + ka + 4];
        uint32_t ah3 = Ah[(wm + 8 + lr) * LDAP + kpb + ka + 4];
        uint32_t al0 = Al[(wm + lr) * LDAP + kpb + ka];
        uint32_t al1 = Al[(wm + 8 + lr) * LDAP + kpb + ka];
        uint32_t al2 = Al[(wm + lr) * LDAP + kpb + ka + 4];
        uint32_t al3 = Al[(wm + 8 + lr) * LDAP + kpb + ka + 4];
#pragma unroll
        for (int nt = 0; nt < 8; nt++) {
            int nb = wn + nt * 8 + lr;
            uint32_t bh0 = Bh[(kpb + ka) * LDBP + nb];
            uint32_t bh1 = Bh[(kpb + ka + 4) * LDBP + nb];
            uint32_t bl0 = Bl[(kpb + ka) * LDBP + nb];
            uint32_t bl1 = Bl[(kpb + ka + 4) * LDBP + nb];
            mma_bf16(acc[nt], ah0, ah1, ah2, ah3, bh0, bh1);
            mma_bf16(acc[nt], al0, al1, al2, al3, bh0, bh1);
            mma_bf16(acc[nt], ah0, ah1, ah2, ah3, bl0, bl1);
        }
    }
}

__device__ __forceinline__ void frag_relu_toCf(float* Cf, const float acc[8][4],
                                               const float* __restrict__ bias,
                                               int wm, int wn, int lr, int ka) {
#pragma unroll
    for (int nt = 0; nt < 8; nt++) {
        int col = wn + nt * 8 + (ka << 1);
        float2 bb = *(const float2*)(bias + col);
        Cf[(wm + lr) * LDA + col]         = fmaxf(acc[nt][0] + bb.x, 0.f);
        Cf[(wm + lr) * LDA + col + 1]     = fmaxf(acc[nt][1] + bb.y, 0.f);
        Cf[(wm + 8 + lr) * LDA + col]     = fmaxf(acc[nt][2] + bb.x, 0.f);
        Cf[(wm + 8 + lr) * LDA + col + 1] = fmaxf(acc[nt][3] + bb.y, 0.f);
    }
}

// P1/P2 passes: P = Cf @ W, frag-stored to global
__device__ __forceinline__ void p_passes(uint32_t* Ah, uint32_t* Al,
                                         uint32_t* Bh, uint32_t* Bl, float* Cf,
                                         const float* __restrict__ WM1,
                                         int n0, int wm, int wn, int lr, int ka) {
#pragma unroll 1
    for (int pp = 0; pp < 2; pp++) {
        const float* W = WM1 + (ll)pp * HH * HH;
        float* P = pp ? g_p2 : g_p1;
        float acc[8][4];
#pragma unroll
        for (int i = 0; i < 8; i++)
#pragma unroll
            for (int j = 0; j < 4; j++) acc[i][j] = 0.f;
#pragma unroll 1
        for (int kc = 0; kc < 4; kc++) {
            __syncthreads();
            stage_Abf_fromCf(Ah, Al, Cf, kc);
            stage_Bbf(Bh, Bl, W, kc * 32);
            __syncthreads();
            mma3_bf(Ah, Al, Bh, Bl, wm, wn, lr, ka, acc);
        }
        int row0 = n0 + wm + lr, row1 = row0 + 8;
#pragma unroll
        for (int nt = 0; nt < 8; nt++) {
            int col = wn + nt * 8 + (ka << 1);
            if (row0 < NN)
                *(float2*)(P + (ll)row0 * HH + col) = make_float2(acc[nt][0], acc[nt][1]);
            if (row1 < NN)
                *(float2*)(P + (ll)row1 * HH + col) = make_float2(acc[nt][2], acc[nt][3]);
        }
    }
}

// ---------------- fp32 helpers (encoders) ----------------
template<int KC>
__device__ __forceinline__ void load_B(float* Bs, const float* __restrict__ W, int k0) {
    int t = threadIdx.x;
#pragma unroll
    for (int i = 0; i < (KC * HH / 4) / TPB; i++) {
        int f = t + i * TPB;
        int k = f >> 5;
        int c = (f & 31) << 2;
        *(float4*)(Bs + k * HH + c) = *(const float4*)(W + (ll)(k0 + k) * HH + c);
    }
}

template<int KB, int LA>
__device__ __forceinline__ void mma8x4(const float* __restrict__ As,
                                       const float* __restrict__ Bs,
                                       int tr8, int tc4, float acc[8][4]) {
#pragma unroll
    for (int kb = 0; kb < KB; kb++) {
        float4 b0 = *(const float4*)(Bs + (kb * 4 + 0) * HH + tc4);
        float4 b1 = *(const float4*)(Bs + (kb * 4 + 1) * HH + tc4);
        float4 b2 = *(const float4*)(Bs + (kb * 4 + 2) * HH + tc4);
        float4 b3 = *(const float4*)(Bs + (kb * 4 + 3) * HH + tc4);
#pragma unroll
        for (int i = 0; i < 8; i++) {
            float4 a = *(const float4*)(As + (tr8 + i) * LA + kb * 4);
            acc[i][0] += a.x * b0.x; acc[i][1] += a.x * b0.y; acc[i][2] += a.x * b0.z; acc[i][3] += a.x * b0.w;
            acc[i][0] += a.y * b1.x; acc[i][1] += a.y * b1.y; acc[i][2] += a.y * b1.z; acc[i][3] += a.y * b1.w;
            acc[i][0] += a.z * b2.x; acc[i][1] += a.z * b2.y; acc[i][2] += a.z * b2.z; acc[i][3] += a.z * b2.w;
            acc[i][0] += a.w * b3.x; acc[i][1] += a.w * b3.y; acc[i][2] += a.w * b3.z; acc[i][3] += a.w * b3.w;
        }
    }
}

__device__ __forceinline__ float4 relu4(const float acc[4], float4 b) {
    float4 v;
    v.x = fmaxf(acc[0] + b.x, 0.f);
    v.y = fmaxf(acc[1] + b.y, 0.f);
    v.z = fmaxf(acc[2] + b.z, 0.f);
    v.w = fmaxf(acc[3] + b.w, 0.f);
    return v;
}

// ---------------- small utility kernels ----------------
__global__ void k_zero_misc() {
    int i = blockIdx.x * blockDim.x + threadIdx.x;
    if (i < NN) g_deg[i] = 0.f;
    if (i < GG * HH) g_pool[i] = 0.f;
    if (i < GG) g_cnt[i] = 0.f;
}
__global__ void k_zero_agg4() {
    int i = blockIdx.x * blockDim.x + threadIdx.x;
    if (i < NN * 32)
        *(float4*)(g_agg + (ll)i * 4) = make_float4(0.f, 0.f, 0.f, 0.f);
}
__global__ void k_deg(const int* __restrict__ dst) {
    int e = blockIdx.x * blockDim.x + threadIdx.x;
    if (e < EE) atomicAdd(&g_deg[dst[e]], 1.f);
}
__global__ void k_rdeg() {
    int n = blockIdx.x * blockDim.x + threadIdx.x;
    if (n < NN) g_rdeg[n] = 1.f / fmaxf(g_deg[n], 1.f);
}

// ---------------- fused node encoder: h = relu(x@Wn0+bn0); P1/P2 for layer 0 ----------------
__global__ void __launch_bounds__(TPB) k_enc_fused(const float* __restrict__ x,
                                                   const float* __restrict__ W,
                                                   const float* __restrict__ b,
                                                   const float* __restrict__ WM1) {
    extern __shared__ uint32_t sm[];
    uint32_t* Ah = sm + OFF_APH;
    uint32_t* Al = sm + OFF_APL;
    uint32_t* Bh = sm + OFF_BPH;
    uint32_t* Bl = sm + OFF_BPL;
    float*    Cf = (float*)(sm + OFF_CF);
    float*    As = (float*)Ah;   // fp32 aliases: 64*36 <= 2*64*LDAP words
    float*    Bs = (float*)Bh;   // 32*128 <= 2*16*LDBP words

    int t = threadIdx.x;
    int lane = t & 31, wid = t >> 5;
    int wm = (wid >> 1) << 4, wn = (wid & 1) << 6;
    int lr = lane >> 2, ka = lane & 3;
    int tr8 = (t >> 5) << 3, tc4 = (t & 31) << 2;
    int r = t >> 2, q = t & 3;
    int n0 = blockIdx.x * BM;
    int row = min(n0 + r, NN - 1);

    float acc[8][4] = {};
#pragma unroll 1
    for (int c = 0; c < 2; c++) {
        __syncthreads();
        const float* p = x + (ll)row * 64 + c * 32;
        *(float4*)(As + r * LDAS + q * 4)      = *(const float4*)(p + q * 4);
        *(float4*)(As + r * LDAS + 16 + q * 4) = *(const float4*)(p + 16 + q * 4);
        load_B<32>(Bs, W, c * 32);
        __syncthreads();
        mma8x4<8, LDAS>(As, Bs, tr8, tc4, acc);
    }
    __syncthreads();
    float4 bb = *(const float4*)(b + tc4);
#pragma unroll
    for (int i = 0; i < 8; i++) {
        float4 v = relu4(acc[i], bb);
        int rr = n0 + tr8 + i;
        *(float4*)(Cf + (tr8 + i) * LDA + tc4) = v;
        if (rr < NN)
            *(float4*)(g_h + (ll)rr * HH + tc4) = v;
    }
    p_passes(Ah, Al, Bh, Bl, Cf, WM1, n0, wm, wn, lr, ka);
}

// ---------------- edge encoder ----------------
__global__ void __launch_bounds__(TPB) k_enc_edges(const float* __restrict__ ea,
                                                   const float* __restrict__ W,
                                                   const float* __restrict__ b) {
    __shared__ __align__(16) float As[BM * 20];
    __shared__ __align__(16) float Bs[16 * HH];
    int t = threadIdx.x;
    int tr8 = (t >> 5) << 3, tc4 = (t & 31) << 2;
    int r = t >> 2, q = t & 3;
    int e0 = blockIdx.x * BM;
    float acc[8][4] = {};
    *(float4*)(As + r * 20 + q * 4) = *(const float4*)(ea + (ll)(e0 + r) * 16 + q * 4);
    load_B<16>(Bs, W, 0);
    __syncthreads();
    mma8x4<4, 20>(As, Bs, tr8, tc4, acc);
    float4 bb = *(const float4*)(b + tc4);
#pragma unroll
    for (int i = 0; i < 8; i++)
        *(float4*)(g_e + (ll)(e0 + tr8 + i) * HH + tc4) = relu4(acc[i], bb);
}

// ---------------- tf32 fused edge kernel (validated, unchanged) ----------------
__global__ void __launch_bounds__(TPB) k_edge_tf32(const int* __restrict__ src,
                                                   const int* __restrict__ dst,
                                                   const float* __restrict__ WM3,
                                                   const float* __restrict__ bM,
                                                   const float* __restrict__ We,
                                                   const float* __restrict__ be,
                                                   int do_edge) {
    extern __shared__ uint32_t smem_u[];
    uint32_t* As = smem_u;
    uint32_t* Bs = smem_u + BM * LDA;
    float*    Cs = (float*)(smem_u + BM * LDA);

    int t = threadIdx.x;
    int lane = t & 31, wid = t >> 5;
    int wm = (wid >> 1) << 4;
    int wn = (wid & 1) << 6;
    int lr = lane >> 2, ka = lane & 3;
    ll e0 = (ll)blockIdx.x * BM;

#pragma unroll
    for (int i = 0; i < 8; i++) {
        int f = t + i * TPB;
        int row = f >> 5, c4 = (f & 31) << 2;
        float4 v = *(const float4*)(g_e + (e0 + row) * HH + c4);
        uint4 u;
        u.x = f2tf(v.x); u.y = f2tf(v.y); u.z = f2tf(v.z); u.w = f2tf(v.w);
        *(uint4*)(As + row * LDA + c4) = u;
    }

    int npass = do_edge ? 2 : 1;
#pragma unroll 1
    for (int pass = 0; pass < npass; pass++) {
        const float* W = pass ? We : WM3;
        float acc[8][4];
#pragma unroll
        for (int i = 0; i < 8; i++)
#pragma unroll
            for (int j = 0; j < 4; j++) acc[i][j] = 0.f;

#pragma unroll 1
        for (int kc = 0; kc < 4; kc++) {
            __syncthreads();
#pragma unroll
            for (int i = 0; i < 4; i++) {
                int f = t + i * TPB;
                int krow = f >> 5, c4 = (f & 31) << 2;
                float4 v = *(const float4*)(W + (ll)(kc * 32 + krow) * HH + c4);
                uint4 u;
                u.x = f2tf(v.x); u.y = f2tf(v.y); u.z = f2tf(v.z); u.w = f2tf(v.w);
                *(uint4*)(Bs + krow * LDB + c4) = u;
            }
            __syncthreads();
#pragma unroll
            for (int ks = 0; ks < 4; ks++) {
                int kb = kc * 32 + ks * 8 + ka;
                uint32_t a0 = As[(wm + lr) * LDA + kb];
                uint32_t a1 = As[(wm + 8 + lr) * LDA + kb];
                uint32_t a2 = As[(wm + lr) * LDA + kb + 4];
                uint32_t a3 = As[(wm + 8 + lr) * LDA + kb + 4];
#pragma unroll
                for (int nt = 0; nt < 8; nt++) {
                    int nb = wn + nt * 8 + lr;
                    uint32_t b0 = Bs[(ks * 8 + ka) * LDB + nb];
                    uint32_t b1 = Bs[(ks * 8 + 4 + ka) * LDB + nb];
                    mma_tf32(acc[nt], a0, a1, a2, a3, b0, b1);
                }
            }
        }
        __syncthreads();
#pragma unroll
        for (int nt = 0; nt < 8; nt++) {
            int col = wn + nt * 8 + (ka << 1);
            *(float2*)(Cs + (wm + lr) * LDA + col)     = make_float2(acc[nt][0], acc[nt][1]);
            *(float2*)(Cs + (wm + 8 + lr) * LDA + col) = make_float2(acc[nt][2], acc[nt][3]);
        }
        __syncthreads();
        if (pass == 0) {
#pragma unroll
            for (int i = 0; i < 8; i++) {
                int f = t + i * TPB;
                int row = f >> 5, c4 = (f & 31) << 2;
                int ge = (int)e0 + row;
                int d = dst[ge], s = src[ge];
                float4 c  = *(const float4*)(Cs + row * LDA + c4);
                float4 bb = *(const float4*)(bM + c4);
                float4 p1 = *(const float4*)(g_p1 + (ll)d * HH + c4);
                float4 p2 = *(const float4*)(g_p2 + (ll)s * HH + c4);
                float4 v;
                v.x = fmaxf(c.x + bb.x + p1.x + p2.x, 0.f);
                v.y = fmaxf(c.y + bb.y + p1.y + p2.y, 0.f);
                v.z = fmaxf(c.z + bb.z + p1.z + p2.z, 0.f);
                v.w = fmaxf(c.w + bb.w + p1.w + p2.w, 0.f);
                atomicAdd((float4*)(g_agg + (ll)d * HH + c4), v);
            }
        } else {
#pragma unroll
            for (int i = 0; i < 8; i++) {
                int f = t + i * TPB;
                int row = f >> 5, c4 = (f & 31) << 2;
                float4 c  = *(const float4*)(Cs + row * LDA + c4);
                float4 bb = *(const float4*)(be + c4);
                float4 v;
                v.x = fmaxf(c.x + bb.x, 0.f);
                v.y = fmaxf(c.y + bb.y, 0.f);
                v.z = fmaxf(c.z + bb.z, 0.f);
                v.w = fmaxf(c.w + bb.w, 0.f);
                *(float4*)(g_e + (e0 + row) * HH + c4) = v;
            }
        }
        if (pass + 1 < npass) __syncthreads();
    }
}

// ---------------- fused update (3xBF16): u -> hnew -> P1/P2(next) ----------------
__global__ void __launch_bounds__(TPB) k_update_fused(const float* __restrict__ WU,
                                                      const float* __restrict__ bU,
                                                      const float* __restrict__ Wn,
                                                      const float* __restrict__ bn,
                                                      const float* __restrict__ WM1_next,
                                                      int has_next) {
    extern __shared__ uint32_t sm[];
    uint32_t* Ah = sm + OFF_APH;
    uint32_t* Al = sm + OFF_APL;
    uint32_t* Bh = sm + OFF_BPH;
    uint32_t* Bl = sm + OFF_BPL;
    float*    Cf = (float*)(sm + OFF_CF);

    int t = threadIdx.x;
    int lane = t & 31, wid = t >> 5;
    int wm = (wid >> 1) << 4, wn = (wid & 1) << 6;
    int lr = lane >> 2, ka = lane & 3;
    int r = t >> 2, q = t & 3;
    int n0 = blockIdx.x * BM;
    int row = min(n0 + r, NN - 1);
    float rd = g_rdeg[row];

    // ---- stage 1: u = relu([h | agg*rdeg] @ WU + bU), K=256 ----
    float acc[8][4];
#pragma unroll
    for (int i = 0; i < 8; i++)
#pragma unroll
        for (int j = 0; j < 4; j++) acc[i][j] = 0.f;
#pragma unroll 1
    for (int c = 0; c < 8; c++) {
        __syncthreads();
        const float* p = (c < 4) ? (g_h + (ll)row * HH + c * 32)
                                 : (g_agg + (ll)row * HH + (c - 4) * 32);
        float sc = (c < 4) ? 1.f : rd;
        float4 v0 = *(const float4*)(p + q * 4);
        float4 v1 = *(const float4*)(p + 16 + q * 4);
        v0.x *= sc; v0.y *= sc; v0.z *= sc; v0.w *= sc;
        v1.x *= sc; v1.y *= sc; v1.z *= sc; v1.w *= sc;
        stage_Abf(Ah, Al, r, q, v0, v1);
        stage_Bbf(Bh, Bl, WU, c * 32);
        __syncthreads();
        mma3_bf(Ah, Al, Bh, Bl, wm, wn, lr, ka, acc);
    }
    frag_relu_toCf(Cf, acc, bU, wm, wn, lr, ka);

    // ---- stage 2: hnew = relu(u @ Wn + bn), K=128 ----
#pragma unroll
    for (int i = 0; i < 8; i++)
#pragma unroll
        for (int j = 0; j < 4; j++) acc[i][j] = 0.f;
#pragma unroll 1
    for (int kc = 0; kc < 4; kc++) {
        __syncthreads();
        stage_Abf_fromCf(Ah, Al, Cf, kc);
        stage_Bbf(Bh, Bl, Wn, kc * 32);
        __syncthreads();
        mma3_bf(Ah, Al, Bh, Bl, wm, wn, lr, ka, acc);
    }
    __syncthreads();            // all Cf(u) reads complete before overwrite
    frag_relu_toCf(Cf, acc, bn, wm, wn, lr, ka);
    __syncthreads();
    // coalesced h store: 64x128 = 2048 float4 = 256 thr x 8 iters
#pragma unroll
    for (int i = 0; i < 8; i++) {
        int f = t + i * TPB;
        int rr = f >> 5, c4 = (f & 31) << 2;
        int gr = n0 + rr;
        if (gr < NN)
            *(float4*)(g_h + (ll)gr * HH + c4) = *(const float4*)(Cf + rr * LDA + c4);
    }

    // ---- stage 3: P1/P2 for next layer ----
    if (has_next)
        p_passes(Ah, Al, Bh, Bl, Cf, WM1_next, n0, wm, wn, lr, ka);
}

// ---------------- global mean pool (run-length batched; bvec is sorted) ----------------
__global__ void k_pool(const int* __restrict__ bvec) {
    int t = blockIdx.x * blockDim.x + threadIdx.x;
    int c4 = (t & 31) << 2;
    int nb = (t >> 5) * 16;
    if (nb >= NN) return;
    int end = min(nb + 16, NN);
    int g = bvec[nb];
    float4 s = make_float4(0.f, 0.f, 0.f, 0.f);
    float cnt = 0.f;
    for (int n = nb; n < end; n++) {
        int gn = bvec[n];
        if (gn != g) {
            atomicAdd((float4*)(g_pool + g * HH + c4), s);
            if (c4 == 0) atomicAdd(&g_cnt[g], cnt);
            s = make_float4(0.f, 0.f, 0.f, 0.f);
            cnt = 0.f;
            g = gn;
        }
        float4 hv = *(const float4*)(g_h + (ll)n * HH + c4);
        s.x += hv.x; s.y += hv.y; s.z += hv.z; s.w += hv.w;
        cnt += 1.f;
    }
    atomicAdd((float4*)(g_pool + g * HH + c4), s);
    if (c4 == 0) atomicAdd(&g_cnt[g], cnt);
}

__global__ void k_head(const float* __restrict__ Wh, const float* __restrict__ bh,
                       float* __restrict__ out) {
    int g = threadIdx.x;
    float rc = 1.f / fmaxf(g_cnt[g], 1.f);
    float acc = bh[0];
#pragma unroll
    for (int k = 0; k < HH; k++)
        acc += g_pool[g * HH + k] * rc * Wh[k];
    out[g] = acc;
}

// ---------------- launch ----------------
extern "C" void kernel_launch(void* const* d_in, const int* in_sizes, int n_in,
                              void* d_out, int out_size) {
    const float* x    = (const float*)d_in[0];
    const int*   ei   = (const int*)d_in[1];
    const float* ea   = (const float*)d_in[2];
    const int*   bvec = (const int*)d_in[3];
    const float* Wn0  = (const float*)d_in[4];
    const float* bn0  = (const float*)d_in[5];
    const float* We0  = (const float*)d_in[6];
    const float* be0  = (const float*)d_in[7];
    const float* WM   = (const float*)d_in[8];
    const float* bM   = (const float*)d_in[9];
    const float* WU   = (const float*)d_in[10];
    const float* bU   = (const float*)d_in[11];
    const float* Wn   = (const float*)d_in[12];
    const float* bn   = (const float*)d_in[13];
    const float* We   = (const float*)d_in[14];
    const float* be   = (const float*)d_in[15];
    const float* Wh   = (const float*)d_in[16];
    const float* bh   = (const float*)d_in[17];
    float* out = (float*)d_out;

    const int* src = ei;
    const int* dst = ei + EE;

    const int EDGE_SMEM = (BM * LDA + BM * LDA) * 4;
    static int attr_done = 0;
    if (!attr_done) {
        cudaFuncSetAttribute(k_edge_tf32, cudaFuncAttributeMaxDynamicSharedMemorySize,
                             EDGE_SMEM);
        cudaFuncSetAttribute(k_enc_fused, cudaFuncAttributeMaxDynamicSharedMemorySize,
                             NODE_SMEM);
        cudaFuncSetAttribute(k_update_fused, cudaFuncAttributeMaxDynamicSharedMemorySize,
                             NODE_SMEM);
        attr_done = 1;
    }

    k_zero_misc<<<(NN + 255) / 256, 256>>>();
    k_deg<<<(EE + 255) / 256, 256>>>(dst);
    k_rdeg<<<(NN + 255) / 256, 256>>>();

    int nblk = (NN + BM - 1) / BM;
    k_enc_fused<<<nblk, TPB, NODE_SMEM>>>(x, Wn0, bn0, WM);
    k_enc_edges<<<EE / BM, TPB>>>(ea, We0, be0);

    for (int l = 0; l < 3; l++) {
        const float* WMl = WM + (ll)l * 384 * HH;
        k_zero_agg4<<<(NN * 32 + 255) / 256, 256>>>();
        k_edge_tf32<<<EE / BM, TPB, EDGE_SMEM>>>(src, dst,
                                                 WMl + (ll)256 * HH, bM + l * HH,
                                                 We + (ll)l * HH * HH, be + l * HH,
                                                 l < 2 ? 1 : 0);
        k_update_fused<<<nblk, TPB, NODE_SMEM>>>(WU + (ll)l * 256 * HH, bU + l * HH,
                                                 Wn + (ll)l * HH * HH, bn + l * HH,
                                                 WM + (ll)(l + 1) * 384 * HH,
                                                 l < 2 ? 1 : 0);
    }

    int pool_threads = ((NN + 15) / 16) * 32;
    k_pool<<<(pool_threads + 255) / 256, 256>>>(bvec);
    k_head<<<1, GG>>>(Wh, bh, out);
}

// round 9
// speedup vs baseline: 2.8281x; 1.0594x over previous
#include <cuda_runtime.h>
#include <cstdint>

#define NN 100000
#define EE 640000
#define GG 256
#define HH 128
#define TPB 256
#define BM 64
#define LDA 132
#define LDB 136
#define LDAS 36
#define LDAP 20
#define LDBP 136

typedef long long ll;

// ---------------- scratch ----------------
__device__ float g_h[NN * HH];
__device__ float g_agg[NN * HH];
__device__ float g_p1[NN * HH];
__device__ float g_p2[NN * HH];
__device__ float g_e[(ll)EE * HH];
__device__ float g_rdeg[NN];
__device__ float g_deg[NN];
__device__ float g_pool[GG * HH];
__device__ float g_cnt[GG];

// pre-converted weights (filled once per launch by k_prep)
__device__ uint32_t g_wu_h[3 * 128 * HH],   g_wu_l[3 * 128 * HH];    // WU: K=256 -> 128 kp
__device__ uint32_t g_wn_h[3 * 64 * HH],    g_wn_l[3 * 64 * HH];     // Wn: K=128 -> 64 kp
__device__ uint32_t g_wm12_h[3 * 128 * HH], g_wm12_l[3 * 128 * HH];  // WM1|WM2 -> 128 kp
__device__ uint32_t g_wm3_t[3 * 128 * HH];                            // WM3 tf32
__device__ uint32_t g_we_t[3 * 128 * HH];                             // We tf32

// ---------------- tf32 helpers ----------------
__device__ __forceinline__ uint32_t f2tf(float f) {
    uint32_t u;
    asm("cvt.rna.tf32.f32 %0, %1;" : "=r"(u) : "f"(f));
    return u;
}
__device__ __forceinline__ void mma_tf32(float* c, uint32_t a0, uint32_t a1,
                                         uint32_t a2, uint32_t a3,
                                         uint32_t b0, uint32_t b1) {
    asm volatile(
        "mma.sync.aligned.m16n8k8.row.col.f32.tf32.tf32.f32 "
        "{%0,%1,%2,%3}, {%4,%5,%6,%7}, {%8,%9}, {%0,%1,%2,%3};\n"
        : "+f"(c[0]), "+f"(c[1]), "+f"(c[2]), "+f"(c[3])
        : "r"(a0), "r"(a1), "r"(a2), "r"(a3), "r"(b0), "r"(b1));
}

// ---------------- bf16 split helpers ----------------
__device__ __forceinline__ void split_pack(float v0, float v1,
                                           uint32_t& ph, uint32_t& pl) {
    uint32_t h;
    asm("cvt.rn.bf16x2.f32 %0, %1, %2;" : "=r"(h) : "f"(v1), "f"(v0));
    float h0 = __uint_as_float(h << 16);
    float h1 = __uint_as_float(h & 0xffff0000u);
    asm("cvt.rn.bf16x2.f32 %0, %1, %2;" : "=r"(pl) : "f"(v1 - h1), "f"(v0 - h0));
    ph = h;
}
__device__ __forceinline__ void mma_bf16(float* c, uint32_t a0, uint32_t a1,
                                         uint32_t a2, uint32_t a3,
                                         uint32_t b0, uint32_t b1) {
    asm volatile(
        "mma.sync.aligned.m16n8k16.row.col.f32.bf16.bf16.f32 "
        "{%0,%1,%2,%3}, {%4,%5,%6,%7}, {%8,%9}, {%0,%1,%2,%3};\n"
        : "+f"(c[0]), "+f"(c[1]), "+f"(c[2]), "+f"(c[3])
        : "r"(a0), "r"(a1), "r"(a2), "r"(a3), "r"(b0), "r"(b1));
}

// ---------------- weight prep: convert all weights once per launch ----------------
__global__ void k_prep(const float* __restrict__ WM, const float* __restrict__ WU,
                       const float* __restrict__ Wn, const float* __restrict__ We) {
    int i = blockIdx.x * blockDim.x + threadIdx.x;
    if (i < 3 * 40960) {
        int l = i / 40960, j = i % 40960;
        int idx = i < 40960 ? j : j;   // keep j
        const float* W;
        uint32_t *dh, *dl;
        if (j < 16384)      { W = WU + (ll)l * 256 * HH; dh = g_wu_h + l * 16384;  dl = g_wu_l + l * 16384; }
        else if (j < 24576) { j -= 16384; W = Wn + (ll)l * 128 * HH; dh = g_wn_h + l * 8192; dl = g_wn_l + l * 8192; }
        else                { j -= 24576; W = WM + (ll)l * 384 * HH; dh = g_wm12_h + l * 16384; dl = g_wm12_l + l * 16384; }
        (void)idx;
        int kp = j >> 7, n = j & 127;
        uint32_t h, lo;
        split_pack(W[(ll)(2 * kp) * HH + n], W[(ll)(2 * kp + 1) * HH + n], h, lo);
        dh[j] = h; dl[j] = lo;
    } else {
        int k = i - 3 * 40960;
        if (k < 3 * 16384) {
            int l = k / 16384, j = k % 16384;
            g_wm3_t[k] = f2tf(WM[(ll)l * 384 * HH + 256 * HH + j]);
        } else {
            k -= 3 * 16384;
            if (k < 3 * 16384)
                g_we_t[k] = f2tf(We[k]);
        }
    }
}

// ---------------- node-kernel smem partition (uint32 words) ----------------
#define OFF_APH 0
#define OFF_APL (64 * LDAP)
#define OFF_BPH (2 * 64 * LDAP)
#define OFF_BPL (2 * 64 * LDAP + 16 * LDBP)
#define OFF_CF  (2 * 64 * LDAP + 2 * 16 * LDBP)
#define NODE_SMEM ((2 * 64 * LDAP + 2 * 16 * LDBP + 64 * LDA) * 4)

// stage pre-split B chunk (16 kp rows): pure uint4 copies
__device__ __forceinline__ void stage_Bpre(uint32_t* Bh, uint32_t* Bl,
                                           const uint32_t* __restrict__ GH,
                                           const uint32_t* __restrict__ GL, int kp0) {
    int t = threadIdx.x;
#pragma unroll
    for (int i = 0; i < 2; i++) {
        int f = t + i * TPB;
        int kp = f >> 5, n = (f & 31) << 2;
        *(uint4*)(Bh + kp * LDBP + n) = *(const uint4*)(GH + (ll)(kp0 + kp) * HH + n);
        *(uint4*)(Bl + kp * LDBP + n) = *(const uint4*)(GL + (ll)(kp0 + kp) * HH + n);
    }
}

__device__ __forceinline__ void stage_Abf(uint32_t* Ah, uint32_t* Al,
                                          int r, int q, float4 v0, float4 v1) {
    uint32_t h0, l0, h1, l1;
    split_pack(v0.x, v0.y, h0, l0);
    split_pack(v0.z, v0.w, h1, l1);
    *(uint2*)(Ah + r * LDAP + 2 * q) = make_uint2(h0, h1);
    *(uint2*)(Al + r * LDAP + 2 * q) = make_uint2(l0, l1);
    split_pack(v1.x, v1.y, h0, l0);
    split_pack(v1.z, v1.w, h1, l1);
    *(uint2*)(Ah + r * LDAP + 8 + 2 * q) = make_uint2(h0, h1);
    *(uint2*)(Al + r * LDAP + 8 + 2 * q) = make_uint2(l0, l1);
}

__device__ __forceinline__ void stage_Abf_fromCf(uint32_t* Ah, uint32_t* Al,
                                                 const float* Cf, int kc) {
    int t = threadIdx.x;
    int r = t >> 2, q = t & 3;
    float4 v0 = *(const float4*)(Cf + r * LDA + kc * 32 + q * 4);
    float4 v1 = *(const float4*)(Cf + r * LDA + kc * 32 + 16 + q * 4);
    stage_Abf(Ah, Al, r, q, v0, v1);
}

// 3xBF16 mma over one 32-K chunk; warp computes 16x64
__device__ __forceinline__ void mma3_bf(const uint32_t* Ah, const uint32_t* Al,
                                        const uint32_t* Bh, const uint32_t* Bl,
                                        int wm, int wn, int lr, int ka,
                                        float acc[8][4]) {
#pragma unroll
    for (int ks = 0; ks < 2; ks++) {
        int kpb = ks * 8;
        uint32_t ah0 = Ah[(wm + lr) * LDAP + kpb + ka];
        uint32_t ah1 = Ah[(wm + 8 + lr) * LDAP + kpb + ka];
        uint32_t ah2 = Ah[(wm + lr) * LDAP + kpb + ka + 4];
        uint32_t ah3 = Ah[(wm + 8 + lr) * LDAP + kpb + ka + 4];
        uint32_t al0 = Al[(wm + lr) * LDAP + kpb + ka];
        uint32_t al1 = Al[(wm + 8 + lr) * LDAP + kpb + ka];
        uint32_t al2 = Al[(wm + lr) * LDAP + kpb + ka + 4];
        uint32_t al3 = Al[(wm + 8 + lr) * LDAP + kpb + ka + 4];
#pragma unroll
        for (int nt = 0; nt < 8; nt++) {
            int nb = wn + nt * 8 + lr;
            uint32_t bh0 = Bh[(kpb + ka) * LDBP + nb];
            uint32_t bh1 = Bh[(kpb + ka + 4) * LDBP + nb];
            uint32_t bl0 = Bl[(kpb + ka) * LDBP + nb];
            uint32_t bl1 = Bl[(kpb + ka + 4) * LDBP + nb];
            mma_bf16(acc[nt], ah0, ah1, ah2, ah3, bh0, bh1);
            mma_bf16(acc[nt], al0, al1, al2, al3, bh0, bh1);
            mma_bf16(acc[nt], ah0, ah1, ah2, ah3, bl0, bl1);
        }
    }
}

__device__ __forceinline__ void frag_relu_toCf(float* Cf, const float acc[8][4],
                                               const float* __restrict__ bias,
                                               int wm, int wn, int lr, int ka) {
#pragma unroll
    for (int nt = 0; nt < 8; nt++) {
        int col = wn + nt * 8 + (ka << 1);
        float2 bb = *(const float2*)(bias + col);
        Cf[(wm + lr) * LDA + col]         = fmaxf(acc[nt][0] + bb.x, 0.f);
        Cf[(wm + lr) * LDA + col + 1]     = fmaxf(acc[nt][1] + bb.y, 0.f);
        Cf[(wm + 8 + lr) * LDA + col]     = fmaxf(acc[nt][2] + bb.x, 0.f);
        Cf[(wm + 8 + lr) * LDA + col + 1] = fmaxf(acc[nt][3] + bb.y, 0.f);
    }
}

// P1/P2 passes: P = Cf @ WM12[layer][pp], pre-split weights (device pointers)
__device__ __forceinline__ void p_passes(uint32_t* Ah, uint32_t* Al,
                                         uint32_t* Bh, uint32_t* Bl, float* Cf,
                                         int layer,
                                         int n0, int wm, int wn, int lr, int ka) {
    const uint32_t* w12h = g_wm12_h + layer * 128 * HH;
    const uint32_t* w12l = g_wm12_l + layer * 128 * HH;
#pragma unroll 1
    for (int pp = 0; pp < 2; pp++) {
        const uint32_t* GH = w12h + pp * 64 * HH;
        const uint32_t* GL = w12l + pp * 64 * HH;
        float* P = pp ? g_p2 : g_p1;
        float acc[8][4];
#pragma unroll
        for (int i = 0; i < 8; i++)
#pragma unroll
            for (int j = 0; j < 4; j++) acc[i][j] = 0.f;
#pragma unroll 1
        for (int kc = 0; kc < 4; kc++) {
            __syncthreads();
            stage_Abf_fromCf(Ah, Al, Cf, kc);
            stage_Bpre(Bh, Bl, GH, GL, kc * 16);
            __syncthreads();
            mma3_bf(Ah, Al, Bh, Bl, wm, wn, lr, ka, acc);
        }
        int row0 = n0 + wm + lr, row1 = row0 + 8;
#pragma unroll
        for (int nt = 0; nt < 8; nt++) {
            int col = wn + nt * 8 + (ka << 1);
            if (row0 < NN)
                *(float2*)(P + (ll)row0 * HH + col) = make_float2(acc[nt][0], acc[nt][1]);
            if (row1 < NN)
                *(float2*)(P + (ll)row1 * HH + col) = make_float2(acc[nt][2], acc[nt][3]);
        }
    }
}

// ---------------- fp32 helpers (encoders) ----------------
template<int KC>
__device__ __forceinline__ void load_B(float* Bs, const float* __restrict__ W, int k0) {
    int t = threadIdx.x;
#pragma unroll
    for (int i = 0; i < (KC * HH / 4) / TPB; i++) {
        int f = t + i * TPB;
        int k = f >> 5;
        int c = (f & 31) << 2;
        *(float4*)(Bs + k * HH + c) = *(const float4*)(W + (ll)(k0 + k) * HH + c);
    }
}

template<int KB, int LA>
__device__ __forceinline__ void mma8x4(const float* __restrict__ As,
                                       const float* __restrict__ Bs,
                                       int tr8, int tc4, float acc[8][4]) {
#pragma unroll
    for (int kb = 0; kb < KB; kb++) {
        float4 b0 = *(const float4*)(Bs + (kb * 4 + 0) * HH + tc4);
        float4 b1 = *(const float4*)(Bs + (kb * 4 + 1) * HH + tc4);
        float4 b2 = *(const float4*)(Bs + (kb * 4 + 2) * HH + tc4);
        float4 b3 = *(const float4*)(Bs + (kb * 4 + 3) * HH + tc4);
#pragma unroll
        for (int i = 0; i < 8; i++) {
            float4 a = *(const float4*)(As + (tr8 + i) * LA + kb * 4);
            acc[i][0] += a.x * b0.x; acc[i][1] += a.x * b0.y; acc[i][2] += a.x * b0.z; acc[i][3] += a.x * b0.w;
            acc[i][0] += a.y * b1.x; acc[i][1] += a.y * b1.y; acc[i][2] += a.y * b1.z; acc[i][3] += a.y * b1.w;
            acc[i][0] += a.z * b2.x; acc[i][1] += a.z * b2.y; acc[i][2] += a.z * b2.z; acc[i][3] += a.z * b2.w;
            acc[i][0] += a.w * b3.x; acc[i][1] += a.w * b3.y; acc[i][2] += a.w * b3.z; acc[i][3] += a.w * b3.w;
        }
    }
}

__device__ __forceinline__ float4 relu4(const float acc[4], float4 b) {
    float4 v;
    v.x = fmaxf(acc[0] + b.x, 0.f);
    v.y = fmaxf(acc[1] + b.y, 0.f);
    v.z = fmaxf(acc[2] + b.z, 0.f);
    v.w = fmaxf(acc[3] + b.w, 0.f);
    return v;
}

// ---------------- small utility kernels ----------------
__global__ void k_zero_misc() {
    int i = blockIdx.x * blockDim.x + threadIdx.x;
    if (i < NN) g_deg[i] = 0.f;
    if (i < GG * HH) g_pool[i] = 0.f;
    if (i < GG) g_cnt[i] = 0.f;
}
__global__ void k_zero_agg4() {
    int i = blockIdx.x * blockDim.x + threadIdx.x;
    if (i < NN * 32)
        *(float4*)(g_agg + (ll)i * 4) = make_float4(0.f, 0.f, 0.f, 0.f);
}
__global__ void k_deg(const int* __restrict__ dst) {
    int e = blockIdx.x * blockDim.x + threadIdx.x;
    if (e < EE) atomicAdd(&g_deg[dst[e]], 1.f);
}
__global__ void k_rdeg() {
    int n = blockIdx.x * blockDim.x + threadIdx.x;
    if (n < NN) g_rdeg[n] = 1.f / fmaxf(g_deg[n], 1.f);
}

// ---------------- fused node encoder: h = relu(x@Wn0+bn0); P1/P2 for layer 0 ----------------
__global__ void __launch_bounds__(TPB) k_enc_fused(const float* __restrict__ x,
                                                   const float* __restrict__ W,
                                                   const float* __restrict__ b) {
    extern __shared__ uint32_t sm[];
    uint32_t* Ah = sm + OFF_APH;
    uint32_t* Al = sm + OFF_APL;
    uint32_t* Bh = sm + OFF_BPH;
    uint32_t* Bl = sm + OFF_BPL;
    float*    Cf = (float*)(sm + OFF_CF);
    float*    As = (float*)Ah;   // fp32 aliases
    float*    Bs = (float*)Bh;

    int t = threadIdx.x;
    int lane = t & 31, wid = t >> 5;
    int wm = (wid >> 1) << 4, wn = (wid & 1) << 6;
    int lr = lane >> 2, ka = lane & 3;
    int tr8 = (t >> 5) << 3, tc4 = (t & 31) << 2;
    int r = t >> 2, q = t & 3;
    int n0 = blockIdx.x * BM;
    int row = min(n0 + r, NN - 1);

    float acc[8][4] = {};
#pragma unroll 1
    for (int c = 0; c < 2; c++) {
        __syncthreads();
        const float* p = x + (ll)row * 64 + c * 32;
        *(float4*)(As + r * LDAS + q * 4)      = *(const float4*)(p + q * 4);
        *(float4*)(As + r * LDAS + 16 + q * 4) = *(const float4*)(p + 16 + q * 4);
        load_B<32>(Bs, W, c * 32);
        __syncthreads();
        mma8x4<8, LDAS>(As, Bs, tr8, tc4, acc);
    }
    __syncthreads();
    float4 bb = *(const float4*)(b + tc4);
#pragma unroll
    for (int i = 0; i < 8; i++) {
        float4 v = relu4(acc[i], bb);
        int rr = n0 + tr8 + i;
        *(float4*)(Cf + (tr8 + i) * LDA + tc4) = v;
        if (rr < NN)
            *(float4*)(g_h + (ll)rr * HH + tc4) = v;
    }
    p_passes(Ah, Al, Bh, Bl, Cf, 0, n0, wm, wn, lr, ka);
}

// ---------------- edge encoder ----------------
__global__ void __launch_bounds__(TPB) k_enc_edges(const float* __restrict__ ea,
                                                   const float* __restrict__ W,
                                                   const float* __restrict__ b) {
    __shared__ __align__(16) float As[BM * 20];
    __shared__ __align__(16) float Bs[16 * HH];
    int t = threadIdx.x;
    int tr8 = (t >> 5) << 3, tc4 = (t & 31) << 2;
    int r = t >> 2, q = t & 3;
    int e0 = blockIdx.x * BM;
    float acc[8][4] = {};
    *(float4*)(As + r * 20 + q * 4) = *(const float4*)(ea + (ll)(e0 + r) * 16 + q * 4);
    load_B<16>(Bs, W, 0);
    __syncthreads();
    mma8x4<4, 20>(As, Bs, tr8, tc4, acc);
    float4 bb = *(const float4*)(b + tc4);
#pragma unroll
    for (int i = 0; i < 8; i++)
        *(float4*)(g_e + (ll)(e0 + tr8 + i) * HH + tc4) = relu4(acc[i], bb);
}

// ---------------- tf32 fused edge kernel (pre-converted weights via layer idx) ----------------
__global__ void __launch_bounds__(TPB) k_edge_tf32(const int* __restrict__ src,
                                                   const int* __restrict__ dst,
                                                   int layer,
                                                   const float* __restrict__ bM,
                                                   const float* __restrict__ be,
                                                   int do_edge) {
    extern __shared__ uint32_t smem_u[];
    uint32_t* As = smem_u;
    uint32_t* Bs = smem_u + BM * LDA;
    float*    Cs = (float*)(smem_u + BM * LDA);

    const uint32_t* wm3_t = g_wm3_t + layer * 128 * HH;
    const uint32_t* we_t  = g_we_t  + layer * 128 * HH;

    int t = threadIdx.x;
    int lane = t & 31, wid = t >> 5;
    int wm = (wid >> 1) << 4;
    int wn = (wid & 1) << 6;
    int lr = lane >> 2, ka = lane & 3;
    ll e0 = (ll)blockIdx.x * BM;

#pragma unroll
    for (int i = 0; i < 8; i++) {
        int f = t + i * TPB;
        int row = f >> 5, c4 = (f & 31) << 2;
        float4 v = *(const float4*)(g_e + (e0 + row) * HH + c4);
        uint4 u;
        u.x = f2tf(v.x); u.y = f2tf(v.y); u.z = f2tf(v.z); u.w = f2tf(v.w);
        *(uint4*)(As + row * LDA + c4) = u;
    }

    int npass = do_edge ? 2 : 1;
#pragma unroll 1
    for (int pass = 0; pass < npass; pass++) {
        const uint32_t* GT = pass ? we_t : wm3_t;
        float acc[8][4];
#pragma unroll
        for (int i = 0; i < 8; i++)
#pragma unroll
            for (int j = 0; j < 4; j++) acc[i][j] = 0.f;

#pragma unroll 1
        for (int kc = 0; kc < 4; kc++) {
            __syncthreads();
#pragma unroll
            for (int i = 0; i < 4; i++) {
                int f = t + i * TPB;
                int krow = f >> 5, c4 = (f & 31) << 2;
                *(uint4*)(Bs + krow * LDB + c4) =
                    *(const uint4*)(GT + (ll)(kc * 32 + krow) * HH + c4);
            }
            __syncthreads();
#pragma unroll
            for (int ks = 0; ks < 4; ks++) {
                int kb = kc * 32 + ks * 8 + ka;
                uint32_t a0 = As[(wm + lr) * LDA + kb];
                uint32_t a1 = As[(wm + 8 + lr) * LDA + kb];
                uint32_t a2 = As[(wm + lr) * LDA + kb + 4];
                uint32_t a3 = As[(wm + 8 + lr) * LDA + kb + 4];
#pragma unroll
                for (int nt = 0; nt < 8; nt++) {
                    int nb = wn + nt * 8 + lr;
                    uint32_t b0 = Bs[(ks * 8 + ka) * LDB + nb];
                    uint32_t b1 = Bs[(ks * 8 + 4 + ka) * LDB + nb];
                    mma_tf32(acc[nt], a0, a1, a2, a3, b0, b1);
                }
            }
        }
        __syncthreads();
#pragma unroll
        for (int nt = 0; nt < 8; nt++) {
            int col = wn + nt * 8 + (ka << 1);
            *(float2*)(Cs + (wm + lr) * LDA + col)     = make_float2(acc[nt][0], acc[nt][1]);
            *(float2*)(Cs + (wm + 8 + lr) * LDA + col) = make_float2(acc[nt][2], acc[nt][3]);
        }
        __syncthreads();
        if (pass == 0) {
#pragma unroll
            for (int i = 0; i < 8; i++) {
                int f = t + i * TPB;
                int row = f >> 5, c4 = (f & 31) << 2;
                int ge = (int)e0 + row;
                int d = dst[ge], s = src[ge];
                float4 c  = *(const float4*)(Cs + row * LDA + c4);
                float4 bb = *(const float4*)(bM + c4);
                float4 p1 = *(const float4*)(g_p1 + (ll)d * HH + c4);
                float4 p2 = *(const float4*)(g_p2 + (ll)s * HH + c4);
                float4 v;
                v.x = fmaxf(c.x + bb.x + p1.x + p2.x, 0.f);
                v.y = fmaxf(c.y + bb.y + p1.y + p2.y, 0.f);
                v.z = fmaxf(c.z + bb.z + p1.z + p2.z, 0.f);
                v.w = fmaxf(c.w + bb.w + p1.w + p2.w, 0.f);
                atomicAdd((float4*)(g_agg + (ll)d * HH + c4), v);
            }
        } else {
#pragma unroll
            for (int i = 0; i < 8; i++) {
                int f = t + i * TPB;
                int row = f >> 5, c4 = (f & 31) << 2;
                float4 c  = *(const float4*)(Cs + row * LDA + c4);
                float4 bb = *(const float4*)(be + c4);
                float4 v;
                v.x = fmaxf(c.x + bb.x, 0.f);
                v.y = fmaxf(c.y + bb.y, 0.f);
                v.z = fmaxf(c.z + bb.z, 0.f);
                v.w = fmaxf(c.w + bb.w, 0.f);
                *(float4*)(g_e + (e0 + row) * HH + c4) = v;
            }
        }
        if (pass + 1 < npass) __syncthreads();
    }
}

// ---------------- fused update (3xBF16, pre-split weights via layer idx) ----------------
__global__ void __launch_bounds__(TPB) k_update_fused(int layer,
                                                      const float* __restrict__ bU,
                                                      const float* __restrict__ bn,
                                                      int has_next) {
    extern __shared__ uint32_t sm[];
    uint32_t* Ah = sm + OFF_APH;
    uint32_t* Al = sm + OFF_APL;
    uint32_t* Bh = sm + OFF_BPH;
    uint32_t* Bl = sm + OFF_BPL;
    float*    Cf = (float*)(sm + OFF_CF);

    const uint32_t* wu_h = g_wu_h + layer * 128 * HH;
    const uint32_t* wu_l = g_wu_l + layer * 128 * HH;
    const uint32_t* wn_h = g_wn_h + layer * 64 * HH;
    const uint32_t* wn_l = g_wn_l + layer * 64 * HH;

    int t = threadIdx.x;
    int lane = t & 31, wid = t >> 5;
    int wm = (wid >> 1) << 4, wn = (wid & 1) << 6;
    int lr = lane >> 2, ka = lane & 3;
    int r = t >> 2, q = t & 3;
    int n0 = blockIdx.x * BM;
    int row = min(n0 + r, NN - 1);
    float rd = g_rdeg[row];

    // ---- stage 1: u = relu([h | agg*rdeg] @ WU + bU), K=256 ----
    float acc[8][4];
#pragma unroll
    for (int i = 0; i < 8; i++)
#pragma unroll
        for (int j = 0; j < 4; j++) acc[i][j] = 0.f;
#pragma unroll 1
    for (int c = 0; c < 8; c++) {
        __syncthreads();
        const float* p = (c < 4) ? (g_h + (ll)row * HH + c * 32)
                                 : (g_agg + (ll)row * HH + (c - 4) * 32);
        float sc = (c < 4) ? 1.f : rd;
        float4 v0 = *(const float4*)(p + q * 4);
        float4 v1 = *(const float4*)(p + 16 + q * 4);
        v0.x *= sc; v0.y *= sc; v0.z *= sc; v0.w *= sc;
        v1.x *= sc; v1.y *= sc; v1.z *= sc; v1.w *= sc;
        stage_Abf(Ah, Al, r, q, v0, v1);
        stage_Bpre(Bh, Bl, wu_h, wu_l, c * 16);
        __syncthreads();
        mma3_bf(Ah, Al, Bh, Bl, wm, wn, lr, ka, acc);
    }
    frag_relu_toCf(Cf, acc, bU, wm, wn, lr, ka);

    // ---- stage 2: hnew = relu(u @ Wn + bn), K=128 ----
#pragma unroll
    for (int i = 0; i < 8; i++)
#pragma unroll
        for (int j = 0; j < 4; j++) acc[i][j] = 0.f;
#pragma unroll 1
    for (int kc = 0; kc < 4; kc++) {
        __syncthreads();
        stage_Abf_fromCf(Ah, Al, Cf, kc);
        stage_Bpre(Bh, Bl, wn_h, wn_l, kc * 16);
        __syncthreads();
        mma3_bf(Ah, Al, Bh, Bl, wm, wn, lr, ka, acc);
    }
    __syncthreads();            // all Cf(u) reads complete before overwrite
    frag_relu_toCf(Cf, acc, bn, wm, wn, lr, ka);
    __syncthreads();
    // coalesced h store: 64x128 = 2048 float4 = 256 thr x 8 iters
#pragma unroll
    for (int i = 0; i < 8; i++) {
        int f = t + i * TPB;
        int rr = f >> 5, c4 = (f & 31) << 2;
        int gr = n0 + rr;
        if (gr < NN)
            *(float4*)(g_h + (ll)gr * HH + c4) = *(const float4*)(Cf + rr * LDA + c4);
    }

    // ---- stage 3: P1/P2 for next layer ----
    if (has_next)
        p_passes(Ah, Al, Bh, Bl, Cf, layer + 1, n0, wm, wn, lr, ka);
}

// ---------------- global mean pool (run-length batched; bvec is sorted) ----------------
__global__ void k_pool(const int* __restrict__ bvec) {
    int t = blockIdx.x * blockDim.x + threadIdx.x;
    int c4 = (t & 31) << 2;
    int nb = (t >> 5) * 16;
    if (nb >= NN) return;
    int end = min(nb + 16, NN);
    int g = bvec[nb];
    float4 s = make_float4(0.f, 0.f, 0.f, 0.f);
    float cnt = 0.f;
    for (int n = nb; n < end; n++) {
        int gn = bvec[n];
        if (gn != g) {
            atomicAdd((float4*)(g_pool + g * HH + c4), s);
            if (c4 == 0) atomicAdd(&g_cnt[g], cnt);
            s = make_float4(0.f, 0.f, 0.f, 0.f);
            cnt = 0.f;
            g = gn;
        }
        float4 hv = *(const float4*)(g_h + (ll)n * HH + c4);
        s.x += hv.x; s.y += hv.y; s.z += hv.z; s.w += hv.w;
        cnt += 1.f;
    }
    atomicAdd((float4*)(g_pool + g * HH + c4), s);
    if (c4 == 0) atomicAdd(&g_cnt[g], cnt);
}

__global__ void k_head(const float* __restrict__ Wh, const float* __restrict__ bh,
                       float* __restrict__ out) {
    int g = threadIdx.x;
    float rc = 1.f / fmaxf(g_cnt[g], 1.f);
    float acc = bh[0];
#pragma unroll
    for (int k = 0; k < HH; k++)
        acc += g_pool[g * HH + k] * rc * Wh[k];
    out[g] = acc;
}

// ---------------- launch ----------------
extern "C" void kernel_launch(void* const* d_in, const int* in_sizes, int n_in,
                              void* d_out, int out_size) {
    const float* x    = (const float*)d_in[0];
    const int*   ei   = (const int*)d_in[1];
    const float* ea   = (const float*)d_in[2];
    const int*   bvec = (const int*)d_in[3];
    const float* Wn0  = (const float*)d_in[4];
    const float* bn0  = (const float*)d_in[5];
    const float* We0  = (const float*)d_in[6];
    const float* be0  = (const float*)d_in[7];
    const float* WM   = (const float*)d_in[8];
    const float* bM   = (const float*)d_in[9];
    const float* WU   = (const float*)d_in[10];
    const float* bU   = (const float*)d_in[11];
    const float* Wn   = (const float*)d_in[12];
    const float* bn   = (const float*)d_in[13];
    const float* We   = (const float*)d_in[14];
    const float* be   = (const float*)d_in[15];
    const float* Wh   = (const float*)d_in[16];
    const float* bh   = (const float*)d_in[17];
    float* out = (float*)d_out;

    const int* src = ei;
    const int* dst = ei + EE;

    const int EDGE_SMEM = (BM * LDA + BM * LDA) * 4;
    static int attr_done = 0;
    if (!attr_done) {
        cudaFuncSetAttribute(k_edge_tf32, cudaFuncAttributeMaxDynamicSharedMemorySize,
                             EDGE_SMEM);
        cudaFuncSetAttribute(k_enc_fused, cudaFuncAttributeMaxDynamicSharedMemorySize,
                             NODE_SMEM);
        cudaFuncSetAttribute(k_update_fused, cudaFuncAttributeMaxDynamicSharedMemorySize,
                             NODE_SMEM);
        attr_done = 1;
    }

    k_prep<<<(3 * 40960 + 2 * 3 * 16384 + 255) / 256, 256>>>(WM, WU, Wn, We);

    k_zero_misc<<<(NN + 255) / 256, 256>>>();
    k_deg<<<(EE + 255) / 256, 256>>>(dst);
    k_rdeg<<<(NN + 255) / 256, 256>>>();

    int nblk = (NN + BM - 1) / BM;
    k_enc_fused<<<nblk, TPB, NODE_SMEM>>>(x, Wn0, bn0);
    k_enc_edges<<<EE / BM, TPB>>>(ea, We0, be0);

    for (int l = 0; l < 3; l++) {
        k_zero_agg4<<<(NN * 32 + 255) / 256, 256>>>();
        k_edge_tf32<<<EE / BM, TPB, EDGE_SMEM>>>(src, dst, l, bM + l * HH,
                                                 be + l * HH, l < 2 ? 1 : 0);
        k_update_fused<<<nblk, TPB, NODE_SMEM>>>(l, bU + l * HH, bn + l * HH,
                                                 l < 2 ? 1 : 0);
    }

    int pool_threads = ((NN + 15) / 16) * 32;
    k_pool<<<(pool_threads + 255) / 256, 256>>>(bvec);
    k_head<<<1, GG>>>(Wh, bh, out);
}

// round 10
// speedup vs baseline: 3.0072x; 1.0633x over previous
#include <cuda_runtime.h>
#include <cstdint>

#define NN 100000
#define EE 640000
#define GG 256
#define HH 128
#define TPB 256
#define BM 64
#define LDA 132
#define LDB 136
#define LDAS 36
#define LDAP 20
#define LDBP 136

typedef long long ll;

// ---------------- scratch ----------------
__device__ float g_h[NN * HH];
__device__ float g_agg[NN * HH];
__device__ float g_p1[NN * HH];
__device__ float g_p2[NN * HH];
__device__ float g_e[(ll)EE * HH];
__device__ float g_rdeg[NN];
__device__ float g_deg[NN];
__device__ float g_pool[GG * HH];
__device__ float g_cnt[GG];

// pre-converted weights (filled once per launch by k_prep)
__device__ uint32_t g_wu_h[3 * 128 * HH],   g_wu_l[3 * 128 * HH];
__device__ uint32_t g_wn_h[3 * 64 * HH],    g_wn_l[3 * 64 * HH];
__device__ uint32_t g_wm12_h[3 * 128 * HH], g_wm12_l[3 * 128 * HH];
__device__ uint32_t g_wm3_t[3 * 128 * HH];
__device__ uint32_t g_we_t[3 * 128 * HH];

// ---------------- tf32 helpers ----------------
__device__ __forceinline__ uint32_t f2tf(float f) {
    uint32_t u;
    asm("cvt.rna.tf32.f32 %0, %1;" : "=r"(u) : "f"(f));
    return u;
}
__device__ __forceinline__ void mma_tf32(float* c, uint32_t a0, uint32_t a1,
                                         uint32_t a2, uint32_t a3,
                                         uint32_t b0, uint32_t b1) {
    asm volatile(
        "mma.sync.aligned.m16n8k8.row.col.f32.tf32.tf32.f32 "
        "{%0,%1,%2,%3}, {%4,%5,%6,%7}, {%8,%9}, {%0,%1,%2,%3};\n"
        : "+f"(c[0]), "+f"(c[1]), "+f"(c[2]), "+f"(c[3])
        : "r"(a0), "r"(a1), "r"(a2), "r"(a3), "r"(b0), "r"(b1));
}

// ---------------- bf16 split helpers ----------------
__device__ __forceinline__ void split_pack(float v0, float v1,
                                           uint32_t& ph, uint32_t& pl) {
    uint32_t h;
    asm("cvt.rn.bf16x2.f32 %0, %1, %2;" : "=r"(h) : "f"(v1), "f"(v0));
    float h0 = __uint_as_float(h << 16);
    float h1 = __uint_as_float(h & 0xffff0000u);
    asm("cvt.rn.bf16x2.f32 %0, %1, %2;" : "=r"(pl) : "f"(v1 - h1), "f"(v0 - h0));
    ph = h;
}
__device__ __forceinline__ void mma_bf16(float* c, uint32_t a0, uint32_t a1,
                                         uint32_t a2, uint32_t a3,
                                         uint32_t b0, uint32_t b1) {
    asm volatile(
        "mma.sync.aligned.m16n8k16.row.col.f32.bf16.bf16.f32 "
        "{%0,%1,%2,%3}, {%4,%5,%6,%7}, {%8,%9}, {%0,%1,%2,%3};\n"
        : "+f"(c[0]), "+f"(c[1]), "+f"(c[2]), "+f"(c[3])
        : "r"(a0), "r"(a1), "r"(a2), "r"(a3), "r"(b0), "r"(b1));
}

// ---------------- weight prep ----------------
__global__ void k_prep(const float* __restrict__ WM, const float* __restrict__ WU,
                       const float* __restrict__ Wn, const float* __restrict__ We) {
    int i = blockIdx.x * blockDim.x + threadIdx.x;
    if (i < 3 * 40960) {
        int l = i / 40960, j = i % 40960;
        const float* W;
        uint32_t *dh, *dl;
        if (j < 16384)      { W = WU + (ll)l * 256 * HH; dh = g_wu_h + l * 16384;  dl = g_wu_l + l * 16384; }
        else if (j < 24576) { j -= 16384; W = Wn + (ll)l * 128 * HH; dh = g_wn_h + l * 8192; dl = g_wn_l + l * 8192; }
        else                { j -= 24576; W = WM + (ll)l * 384 * HH; dh = g_wm12_h + l * 16384; dl = g_wm12_l + l * 16384; }
        int kp = j >> 7, n = j & 127;
        uint32_t h, lo;
        split_pack(W[(ll)(2 * kp) * HH + n], W[(ll)(2 * kp + 1) * HH + n], h, lo);
        dh[j] = h; dl[j] = lo;
    } else {
        int k = i - 3 * 40960;
        if (k < 3 * 16384) {
            int l = k / 16384, j = k % 16384;
            g_wm3_t[k] = f2tf(WM[(ll)l * 384 * HH + 256 * HH + j]);
        } else {
            k -= 3 * 16384;
            if (k < 3 * 16384)
                g_we_t[k] = f2tf(We[k]);
        }
    }
}

// ---------------- node-kernel smem partition (uint32 words) ----------------
#define OFF_APH 0
#define OFF_APL (64 * LDAP)
#define OFF_B1H (2 * 64 * LDAP)
#define OFF_B1L (OFF_B1H + 16 * LDBP)
#define OFF_B2H (OFF_B1H + 2 * 16 * LDBP)
#define OFF_B2L (OFF_B1H + 3 * 16 * LDBP)
#define OFF_CF  (OFF_B1H + 4 * 16 * LDBP)
#define NODE_SMEM ((OFF_CF + 64 * LDA) * 4)

__device__ __forceinline__ void stage_Bpre(uint32_t* Bh, uint32_t* Bl,
                                           const uint32_t* __restrict__ GH,
                                           const uint32_t* __restrict__ GL, int kp0) {
    int t = threadIdx.x;
#pragma unroll
    for (int i = 0; i < 2; i++) {
        int f = t + i * TPB;
        int kp = f >> 5, n = (f & 31) << 2;
        *(uint4*)(Bh + kp * LDBP + n) = *(const uint4*)(GH + (ll)(kp0 + kp) * HH + n);
        *(uint4*)(Bl + kp * LDBP + n) = *(const uint4*)(GL + (ll)(kp0 + kp) * HH + n);
    }
}

__device__ __forceinline__ void stage_Abf(uint32_t* Ah, uint32_t* Al,
                                          int r, int q, float4 v0, float4 v1) {
    uint32_t h0, l0, h1, l1;
    split_pack(v0.x, v0.y, h0, l0);
    split_pack(v0.z, v0.w, h1, l1);
    *(uint2*)(Ah + r * LDAP + 2 * q) = make_uint2(h0, h1);
    *(uint2*)(Al + r * LDAP + 2 * q) = make_uint2(l0, l1);
    split_pack(v1.x, v1.y, h0, l0);
    split_pack(v1.z, v1.w, h1, l1);
    *(uint2*)(Ah + r * LDAP + 8 + 2 * q) = make_uint2(h0, h1);
    *(uint2*)(Al + r * LDAP + 8 + 2 * q) = make_uint2(l0, l1);
}

__device__ __forceinline__ void stage_Abf_fromCf(uint32_t* Ah, uint32_t* Al,
                                                 const float* Cf, int kc) {
    int t = threadIdx.x;
    int r = t >> 2, q = t & 3;
    float4 v0 = *(const float4*)(Cf + r * LDA + kc * 32 + q * 4);
    float4 v1 = *(const float4*)(Cf + r * LDA + kc * 32 + 16 + q * 4);
    stage_Abf(Ah, Al, r, q, v0, v1);
}

// 3xBF16 mma over one 32-K chunk (single B), warp computes 16x64
__device__ __forceinline__ void mma3_bf(const uint32_t* Ah, const uint32_t* Al,
                                        const uint32_t* Bh, const uint32_t* Bl,
                                        int wm, int wn, int lr, int ka,
                                        float acc[8][4]) {
#pragma unroll
    for (int ks = 0; ks < 2; ks++) {
        int kpb = ks * 8;
        uint32_t ah0 = Ah[(wm + lr) * LDAP + kpb + ka];
        uint32_t ah1 = Ah[(wm + 8 + lr) * LDAP + kpb + ka];
        uint32_t ah2 = Ah[(wm + lr) * LDAP + kpb + ka + 4];
        uint32_t ah3 = Ah[(wm + 8 + lr) * LDAP + kpb + ka + 4];
        uint32_t al0 = Al[(wm + lr) * LDAP + kpb + ka];
        uint32_t al1 = Al[(wm + 8 + lr) * LDAP + kpb + ka];
        uint32_t al2 = Al[(wm + lr) * LDAP + kpb + ka + 4];
        uint32_t al3 = Al[(wm + 8 + lr) * LDAP + kpb + ka + 4];
#pragma unroll
        for (int nt = 0; nt < 8; nt++) {
            int nb = wn + nt * 8 + lr;
            uint32_t bh0 = Bh[(kpb + ka) * LDBP + nb];
            uint32_t bh1 = Bh[(kpb + ka + 4) * LDBP + nb];
            uint32_t bl0 = Bl[(kpb + ka) * LDBP + nb];
            uint32_t bl1 = Bl[(kpb + ka + 4) * LDBP + nb];
            mma_bf16(acc[nt], ah0, ah1, ah2, ah3, bh0, bh1);
            mma_bf16(acc[nt], al0, al1, al2, al3, bh0, bh1);
            mma_bf16(acc[nt], ah0, ah1, ah2, ah3, bl0, bl1);
        }
    }
}

// dual-B version: shared A frags feed two accumulator sets
__device__ __forceinline__ void mma3_bf_dual(const uint32_t* Ah, const uint32_t* Al,
                                             const uint32_t* B1h, const uint32_t* B1l,
                                             const uint32_t* B2h, const uint32_t* B2l,
                                             int wm, int wn, int lr, int ka,
                                             float accA[8][4], float accB[8][4]) {
#pragma unroll
    for (int ks = 0; ks < 2; ks++) {
        int kpb = ks * 8;
        uint32_t ah0 = Ah[(wm + lr) * LDAP + kpb + ka];
        uint32_t ah1 = Ah[(wm + 8 + lr) * LDAP + kpb + ka];
        uint32_t ah2 = Ah[(wm + lr) * LDAP + kpb + ka + 4];
        uint32_t ah3 = Ah[(wm + 8 + lr) * LDAP + kpb + ka + 4];
        uint32_t al0 = Al[(wm + lr) * LDAP + kpb + ka];
        uint32_t al1 = Al[(wm + 8 + lr) * LDAP + kpb + ka];
        uint32_t al2 = Al[(wm + lr) * LDAP + kpb + ka + 4];
        uint32_t al3 = Al[(wm + 8 + lr) * LDAP + kpb + ka + 4];
#pragma unroll
        for (int nt = 0; nt < 8; nt++) {
            int nb = wn + nt * 8 + lr;
            uint32_t bh0 = B1h[(kpb + ka) * LDBP + nb];
            uint32_t bh1 = B1h[(kpb + ka + 4) * LDBP + nb];
            uint32_t bl0 = B1l[(kpb + ka) * LDBP + nb];
            uint32_t bl1 = B1l[(kpb + ka + 4) * LDBP + nb];
            mma_bf16(accA[nt], ah0, ah1, ah2, ah3, bh0, bh1);
            mma_bf16(accA[nt], al0, al1, al2, al3, bh0, bh1);
            mma_bf16(accA[nt], ah0, ah1, ah2, ah3, bl0, bl1);
            bh0 = B2h[(kpb + ka) * LDBP + nb];
            bh1 = B2h[(kpb + ka + 4) * LDBP + nb];
            bl0 = B2l[(kpb + ka) * LDBP + nb];
            bl1 = B2l[(kpb + ka + 4) * LDBP + nb];
            mma_bf16(accB[nt], ah0, ah1, ah2, ah3, bh0, bh1);
            mma_bf16(accB[nt], al0, al1, al2, al3, bh0, bh1);
            mma_bf16(accB[nt], ah0, ah1, ah2, ah3, bl0, bl1);
        }
    }
}

__device__ __forceinline__ void frag_relu_toCf(float* Cf, const float acc[8][4],
                                               const float* __restrict__ bias,
                                               int wm, int wn, int lr, int ka) {
#pragma unroll
    for (int nt = 0; nt < 8; nt++) {
        int col = wn + nt * 8 + (ka << 1);
        float2 bb = *(const float2*)(bias + col);
        Cf[(wm + lr) * LDA + col]         = fmaxf(acc[nt][0] + bb.x, 0.f);
        Cf[(wm + lr) * LDA + col + 1]     = fmaxf(acc[nt][1] + bb.y, 0.f);
        Cf[(wm + 8 + lr) * LDA + col]     = fmaxf(acc[nt][2] + bb.x, 0.f);
        Cf[(wm + 8 + lr) * LDA + col + 1] = fmaxf(acc[nt][3] + bb.y, 0.f);
    }
}

// P1/P2 fused pass: one K-loop, shared A frags, two acc sets
__device__ __forceinline__ void p_passes(uint32_t* Ah, uint32_t* Al,
                                         uint32_t* B1h, uint32_t* B1l,
                                         uint32_t* B2h, uint32_t* B2l, float* Cf,
                                         int layer,
                                         int n0, int wm, int wn, int lr, int ka) {
    const uint32_t* GH1 = g_wm12_h + layer * 128 * HH;
    const uint32_t* GL1 = g_wm12_l + layer * 128 * HH;
    const uint32_t* GH2 = GH1 + 64 * HH;
    const uint32_t* GL2 = GL1 + 64 * HH;
    float accA[8][4], accB[8][4];
#pragma unroll
    for (int i = 0; i < 8; i++)
#pragma unroll
        for (int j = 0; j < 4; j++) { accA[i][j] = 0.f; accB[i][j] = 0.f; }
#pragma unroll 1
    for (int kc = 0; kc < 4; kc++) {
        __syncthreads();
        stage_Abf_fromCf(Ah, Al, Cf, kc);
        stage_Bpre(B1h, B1l, GH1, GL1, kc * 16);
        stage_Bpre(B2h, B2l, GH2, GL2, kc * 16);
        __syncthreads();
        mma3_bf_dual(Ah, Al, B1h, B1l, B2h, B2l, wm, wn, lr, ka, accA, accB);
    }
    int row0 = n0 + wm + lr, row1 = row0 + 8;
#pragma unroll
    for (int nt = 0; nt < 8; nt++) {
        int col = wn + nt * 8 + (ka << 1);
        if (row0 < NN) {
            *(float2*)(g_p1 + (ll)row0 * HH + col) = make_float2(accA[nt][0], accA[nt][1]);
            *(float2*)(g_p2 + (ll)row0 * HH + col) = make_float2(accB[nt][0], accB[nt][1]);
        }
        if (row1 < NN) {
            *(float2*)(g_p1 + (ll)row1 * HH + col) = make_float2(accA[nt][2], accA[nt][3]);
            *(float2*)(g_p2 + (ll)row1 * HH + col) = make_float2(accB[nt][2], accB[nt][3]);
        }
    }
}

// ---------------- fp32 helpers (encoders) ----------------
template<int KC>
__device__ __forceinline__ void load_B(float* Bs, const float* __restrict__ W, int k0) {
    int t = threadIdx.x;
#pragma unroll
    for (int i = 0; i < (KC * HH / 4) / TPB; i++) {
        int f = t + i * TPB;
        int k = f >> 5;
        int c = (f & 31) << 2;
        *(float4*)(Bs + k * HH + c) = *(const float4*)(W + (ll)(k0 + k) * HH + c);
    }
}

template<int KB, int LA>
__device__ __forceinline__ void mma8x4(const float* __restrict__ As,
                                       const float* __restrict__ Bs,
                                       int tr8, int tc4, float acc[8][4]) {
#pragma unroll
    for (int kb = 0; kb < KB; kb++) {
        float4 b0 = *(const float4*)(Bs + (kb * 4 + 0) * HH + tc4);
        float4 b1 = *(const float4*)(Bs + (kb * 4 + 1) * HH + tc4);
        float4 b2 = *(const float4*)(Bs + (kb * 4 + 2) * HH + tc4);
        float4 b3 = *(const float4*)(Bs + (kb * 4 + 3) * HH + tc4);
#pragma unroll
        for (int i = 0; i < 8; i++) {
            float4 a = *(const float4*)(As + (tr8 + i) * LA + kb * 4);
            acc[i][0] += a.x * b0.x; acc[i][1] += a.x * b0.y; acc[i][2] += a.x * b0.z; acc[i][3] += a.x * b0.w;
            acc[i][0] += a.y * b1.x; acc[i][1] += a.y * b1.y; acc[i][2] += a.y * b1.z; acc[i][3] += a.y * b1.w;
            acc[i][0] += a.z * b2.x; acc[i][1] += a.z * b2.y; acc[i][2] += a.z * b2.z; acc[i][3] += a.z * b2.w;
            acc[i][0] += a.w * b3.x; acc[i][1] += a.w * b3.y; acc[i][2] += a.w * b3.z; acc[i][3] += a.w * b3.w;
        }
    }
}

__device__ __forceinline__ float4 relu4(const float acc[4], float4 b) {
    float4 v;
    v.x = fmaxf(acc[0] + b.x, 0.f);
    v.y = fmaxf(acc[1] + b.y, 0.f);
    v.z = fmaxf(acc[2] + b.z, 0.f);
    v.w = fmaxf(acc[3] + b.w, 0.f);
    return v;
}

// ---------------- small utility kernels ----------------
__global__ void k_zero_misc() {
    int i = blockIdx.x * blockDim.x + threadIdx.x;
    if (i < NN) g_deg[i] = 0.f;
    if (i < GG * HH) g_pool[i] = 0.f;
    if (i < GG) g_cnt[i] = 0.f;
}
__global__ void k_zero_agg4() {
    int i = blockIdx.x * blockDim.x + threadIdx.x;
    if (i < NN * 32)
        *(float4*)(g_agg + (ll)i * 4) = make_float4(0.f, 0.f, 0.f, 0.f);
}
__global__ void k_deg(const int* __restrict__ dst) {
    int e = blockIdx.x * blockDim.x + threadIdx.x;
    if (e < EE) atomicAdd(&g_deg[dst[e]], 1.f);
}
__global__ void k_rdeg() {
    int n = blockIdx.x * blockDim.x + threadIdx.x;
    if (n < NN) g_rdeg[n] = 1.f / fmaxf(g_deg[n], 1.f);
}

// ---------------- fused node encoder ----------------
__global__ void __launch_bounds__(TPB) k_enc_fused(const float* __restrict__ x,
                                                   const float* __restrict__ W,
                                                   const float* __restrict__ b) {
    extern __shared__ uint32_t sm[];
    uint32_t* Ah  = sm + OFF_APH;
    uint32_t* Al  = sm + OFF_APL;
    uint32_t* B1h = sm + OFF_B1H;
    uint32_t* B1l = sm + OFF_B1L;
    uint32_t* B2h = sm + OFF_B2H;
    uint32_t* B2l = sm + OFF_B2L;
    float*    Cf  = (float*)(sm + OFF_CF);
    float*    As  = (float*)Ah;   // fp32 aliases (2304 <= 2560 words)
    float*    Bs  = (float*)B1h;  // 4096 <= 8704 words

    int t = threadIdx.x;
    int lane = t & 31, wid = t >> 5;
    int wm = (wid >> 1) << 4, wn = (wid & 1) << 6;
    int lr = lane >> 2, ka = lane & 3;
    int tr8 = (t >> 5) << 3, tc4 = (t & 31) << 2;
    int r = t >> 2, q = t & 3;
    int n0 = blockIdx.x * BM;
    int row = min(n0 + r, NN - 1);

    float acc[8][4] = {};
#pragma unroll 1
    for (int c = 0; c < 2; c++) {
        __syncthreads();
        const float* p = x + (ll)row * 64 + c * 32;
        *(float4*)(As + r * LDAS + q * 4)      = *(const float4*)(p + q * 4);
        *(float4*)(As + r * LDAS + 16 + q * 4) = *(const float4*)(p + 16 + q * 4);
        load_B<32>(Bs, W, c * 32);
        __syncthreads();
        mma8x4<8, LDAS>(As, Bs, tr8, tc4, acc);
    }
    __syncthreads();
    float4 bb = *(const float4*)(b + tc4);
#pragma unroll
    for (int i = 0; i < 8; i++) {
        float4 v = relu4(acc[i], bb);
        int rr = n0 + tr8 + i;
        *(float4*)(Cf + (tr8 + i) * LDA + tc4) = v;
        if (rr < NN)
            *(float4*)(g_h + (ll)rr * HH + tc4) = v;
    }
    p_passes(Ah, Al, B1h, B1l, B2h, B2l, Cf, 0, n0, wm, wn, lr, ka);
}

// ---------------- edge encoder ----------------
__global__ void __launch_bounds__(TPB) k_enc_edges(const float* __restrict__ ea,
                                                   const float* __restrict__ W,
                                                   const float* __restrict__ b) {
    __shared__ __align__(16) float As[BM * 20];
    __shared__ __align__(16) float Bs[16 * HH];
    int t = threadIdx.x;
    int tr8 = (t >> 5) << 3, tc4 = (t & 31) << 2;
    int r = t >> 2, q = t & 3;
    int e0 = blockIdx.x * BM;
    float acc[8][4] = {};
    *(float4*)(As + r * 20 + q * 4) = *(const float4*)(ea + (ll)(e0 + r) * 16 + q * 4);
    load_B<16>(Bs, W, 0);
    __syncthreads();
    mma8x4<4, 20>(As, Bs, tr8, tc4, acc);
    float4 bb = *(const float4*)(b + tc4);
#pragma unroll
    for (int i = 0; i < 8; i++)
        *(float4*)(g_e + (ll)(e0 + tr8 + i) * HH + tc4) = relu4(acc[i], bb);
}

// ---------------- tf32 fused edge kernel: dual-acc single K-loop ----------------
// smem words: As 64*LDA (8448) | B1 32*LDB (4352) | B2 32*LDB (4352); Cs aliases B1+B2
#define EDGE_SMEM ((BM * LDA + 2 * 32 * LDB) * 4)
__global__ void __launch_bounds__(TPB) k_edge_tf32(const int* __restrict__ src,
                                                   const int* __restrict__ dst,
                                                   int layer,
                                                   const float* __restrict__ bM,
                                                   const float* __restrict__ be,
                                                   int do_edge) {
    extern __shared__ uint32_t smem_u[];
    uint32_t* As = smem_u;
    uint32_t* B1 = smem_u + BM * LDA;
    uint32_t* B2 = B1 + 32 * LDB;
    float*    Cs = (float*)B1;

    const uint32_t* wm3_t = g_wm3_t + layer * 128 * HH;
    const uint32_t* we_t  = g_we_t  + layer * 128 * HH;

    int t = threadIdx.x;
    int lane = t & 31, wid = t >> 5;
    int wm = (wid >> 1) << 4;
    int wn = (wid & 1) << 6;
    int lr = lane >> 2, ka = lane & 3;
    ll e0 = (ll)blockIdx.x * BM;

#pragma unroll
    for (int i = 0; i < 8; i++) {
        int f = t + i * TPB;
        int row = f >> 5, c4 = (f & 31) << 2;
        float4 v = *(const float4*)(g_e + (e0 + row) * HH + c4);
        uint4 u;
        u.x = f2tf(v.x); u.y = f2tf(v.y); u.z = f2tf(v.z); u.w = f2tf(v.w);
        *(uint4*)(As + row * LDA + c4) = u;
    }

    float accM[8][4], accE[8][4];
#pragma unroll
    for (int i = 0; i < 8; i++)
#pragma unroll
        for (int j = 0; j < 4; j++) { accM[i][j] = 0.f; accE[i][j] = 0.f; }

#pragma unroll 1
    for (int kc = 0; kc < 4; kc++) {
        __syncthreads();
#pragma unroll
        for (int i = 0; i < 4; i++) {
            int f = t + i * TPB;
            int krow = f >> 5, c4 = (f & 31) << 2;
            *(uint4*)(B1 + krow * LDB + c4) =
                *(const uint4*)(wm3_t + (ll)(kc * 32 + krow) * HH + c4);
        }
        if (do_edge) {
#pragma unroll
            for (int i = 0; i < 4; i++) {
                int f = t + i * TPB;
                int krow = f >> 5, c4 = (f & 31) << 2;
                *(uint4*)(B2 + krow * LDB + c4) =
                    *(const uint4*)(we_t + (ll)(kc * 32 + krow) * HH + c4);
            }
        }
        __syncthreads();
#pragma unroll
        for (int ks = 0; ks < 4; ks++) {
            int kb = kc * 32 + ks * 8 + ka;
            uint32_t a0 = As[(wm + lr) * LDA + kb];
            uint32_t a1 = As[(wm + 8 + lr) * LDA + kb];
            uint32_t a2 = As[(wm + lr) * LDA + kb + 4];
            uint32_t a3 = As[(wm + 8 + lr) * LDA + kb + 4];
#pragma unroll
            for (int nt = 0; nt < 8; nt++) {
                int nb = wn + nt * 8 + lr;
                uint32_t b0 = B1[(ks * 8 + ka) * LDB + nb];
                uint32_t b1 = B1[(ks * 8 + 4 + ka) * LDB + nb];
                mma_tf32(accM[nt], a0, a1, a2, a3, b0, b1);
            }
            if (do_edge) {
#pragma unroll
                for (int nt = 0; nt < 8; nt++) {
                    int nb = wn + nt * 8 + lr;
                    uint32_t b0 = B2[(ks * 8 + ka) * LDB + nb];
                    uint32_t b1 = B2[(ks * 8 + 4 + ka) * LDB + nb];
                    mma_tf32(accE[nt], a0, a1, a2, a3, b0, b1);
                }
            }
        }
    }

    // epilogue 1: messages -> agg (atomic scatter), via Cs (aliases B1/B2)
    __syncthreads();
#pragma unroll
    for (int nt = 0; nt < 8; nt++) {
        int col = wn + nt * 8 + (ka << 1);
        *(float2*)(Cs + (wm + lr) * LDA + col)     = make_float2(accM[nt][0], accM[nt][1]);
        *(float2*)(Cs + (wm + 8 + lr) * LDA + col) = make_float2(accM[nt][2], accM[nt][3]);
    }
    __syncthreads();
#pragma unroll
    for (int i = 0; i < 8; i++) {
        int f = t + i * TPB;
        int row = f >> 5, c4 = (f & 31) << 2;
        int ge = (int)e0 + row;
        int d = dst[ge], s = src[ge];
        float4 c  = *(const float4*)(Cs + row * LDA + c4);
        float4 bb = *(const float4*)(bM + c4);
        float4 p1 = *(const float4*)(g_p1 + (ll)d * HH + c4);
        float4 p2 = *(const float4*)(g_p2 + (ll)s * HH + c4);
        float4 v;
        v.x = fmaxf(c.x + bb.x + p1.x + p2.x, 0.f);
        v.y = fmaxf(c.y + bb.y + p1.y + p2.y, 0.f);
        v.z = fmaxf(c.z + bb.z + p1.z + p2.z, 0.f);
        v.w = fmaxf(c.w + bb.w + p1.w + p2.w, 0.f);
        atomicAdd((float4*)(g_agg + (ll)d * HH + c4), v);
    }

    // epilogue 2: e = relu(e@We + be)
    if (do_edge) {
        __syncthreads();
#pragma unroll
        for (int nt = 0; nt < 8; nt++) {
            int col = wn + nt * 8 + (ka << 1);
            *(float2*)(Cs + (wm + lr) * LDA + col)     = make_float2(accE[nt][0], accE[nt][1]);
            *(float2*)(Cs + (wm + 8 + lr) * LDA + col) = make_float2(accE[nt][2], accE[nt][3]);
        }
        __syncthreads();
#pragma unroll
        for (int i = 0; i < 8; i++) {
            int f = t + i * TPB;
            int row = f >> 5, c4 = (f & 31) << 2;
            float4 c  = *(const float4*)(Cs + row * LDA + c4);
            float4 bb = *(const float4*)(be + c4);
            float4 v;
            v.x = fmaxf(c.x + bb.x, 0.f);
            v.y = fmaxf(c.y + bb.y, 0.f);
            v.z = fmaxf(c.z + bb.z, 0.f);
            v.w = fmaxf(c.w + bb.w, 0.f);
            *(float4*)(g_e + (e0 + row) * HH + c4) = v;
        }
    }
}

// ---------------- fused update (3xBF16, pre-split weights) ----------------
__global__ void __launch_bounds__(TPB) k_update_fused(int layer,
                                                      const float* __restrict__ bU,
                                                      const float* __restrict__ bn,
                                                      int has_next) {
    extern __shared__ uint32_t sm[];
    uint32_t* Ah  = sm + OFF_APH;
    uint32_t* Al  = sm + OFF_APL;
    uint32_t* B1h = sm + OFF_B1H;
    uint32_t* B1l = sm + OFF_B1L;
    uint32_t* B2h = sm + OFF_B2H;
    uint32_t* B2l = sm + OFF_B2L;
    float*    Cf  = (float*)(sm + OFF_CF);

    const uint32_t* wu_h = g_wu_h + layer * 128 * HH;
    const uint32_t* wu_l = g_wu_l + layer * 128 * HH;
    const uint32_t* wn_h = g_wn_h + layer * 64 * HH;
    const uint32_t* wn_l = g_wn_l + layer * 64 * HH;

    int t = threadIdx.x;
    int lane = t & 31, wid = t >> 5;
    int wm = (wid >> 1) << 4, wn = (wid & 1) << 6;
    int lr = lane >> 2, ka = lane & 3;
    int r = t >> 2, q = t & 3;
    int n0 = blockIdx.x * BM;
    int row = min(n0 + r, NN - 1);
    float rd = g_rdeg[row];

    // ---- stage 1: u = relu([h | agg*rdeg] @ WU + bU), K=256 ----
    float acc[8][4];
#pragma unroll
    for (int i = 0; i < 8; i++)
#pragma unroll
        for (int j = 0; j < 4; j++) acc[i][j] = 0.f;
#pragma unroll 1
    for (int c = 0; c < 8; c++) {
        __syncthreads();
        const float* p = (c < 4) ? (g_h + (ll)row * HH + c * 32)
                                 : (g_agg + (ll)row * HH + (c - 4) * 32);
        float sc = (c < 4) ? 1.f : rd;
        float4 v0 = *(const float4*)(p + q * 4);
        float4 v1 = *(const float4*)(p + 16 + q * 4);
        v0.x *= sc; v0.y *= sc; v0.z *= sc; v0.w *= sc;
        v1.x *= sc; v1.y *= sc; v1.z *= sc; v1.w *= sc;
        stage_Abf(Ah, Al, r, q, v0, v1);
        stage_Bpre(B1h, B1l, wu_h, wu_l, c * 16);
        __syncthreads();
        mma3_bf(Ah, Al, B1h, B1l, wm, wn, lr, ka, acc);
    }
    frag_relu_toCf(Cf, acc, bU, wm, wn, lr, ka);

    // ---- stage 2: hnew = relu(u @ Wn + bn), K=128 ----
#pragma unroll
    for (int i = 0; i < 8; i++)
#pragma unroll
        for (int j = 0; j < 4; j++) acc[i][j] = 0.f;
#pragma unroll 1
    for (int kc = 0; kc < 4; kc++) {
        __syncthreads();
        stage_Abf_fromCf(Ah, Al, Cf, kc);
        stage_Bpre(B1h, B1l, wn_h, wn_l, kc * 16);
        __syncthreads();
        mma3_bf(Ah, Al, B1h, B1l, wm, wn, lr, ka, acc);
    }
    __syncthreads();            // all Cf(u) reads complete before overwrite
    frag_relu_toCf(Cf, acc, bn, wm, wn, lr, ka);
    __syncthreads();
#pragma unroll
    for (int i = 0; i < 8; i++) {
        int f = t + i * TPB;
        int rr = f >> 5, c4 = (f & 31) << 2;
        int gr = n0 + rr;
        if (gr < NN)
            *(float4*)(g_h + (ll)gr * HH + c4) = *(const float4*)(Cf + rr * LDA + c4);
    }

    // ---- stage 3: fused P1/P2 for next layer ----
    if (has_next)
        p_passes(Ah, Al, B1h, B1l, B2h, B2l, Cf, layer + 1, n0, wm, wn, lr, ka);
}

// ---------------- global mean pool (run-length batched; bvec is sorted) ----------------
__global__ void k_pool(const int* __restrict__ bvec) {
    int t = blockIdx.x * blockDim.x + threadIdx.x;
    int c4 = (t & 31) << 2;
    int nb = (t >> 5) * 16;
    if (nb >= NN) return;
    int end = min(nb + 16, NN);
    int g = bvec[nb];
    float4 s = make_float4(0.f, 0.f, 0.f, 0.f);
    float cnt = 0.f;
    for (int n = nb; n < end; n++) {
        int gn = bvec[n];
        if (gn != g) {
            atomicAdd((float4*)(g_pool + g * HH + c4), s);
            if (c4 == 0) atomicAdd(&g_cnt[g], cnt);
            s = make_float4(0.f, 0.f, 0.f, 0.f);
            cnt = 0.f;
            g = gn;
        }
        float4 hv = *(const float4*)(g_h + (ll)n * HH + c4);
        s.x += hv.x; s.y += hv.y; s.z += hv.z; s.w += hv.w;
        cnt += 1.f;
    }
    atomicAdd((float4*)(g_pool + g * HH + c4), s);
    if (c4 == 0) atomicAdd(&g_cnt[g], cnt);
}

__global__ void k_head(const float* __restrict__ Wh, const float* __restrict__ bh,
                       float* __restrict__ out) {
    int g = threadIdx.x;
    float rc = 1.f / fmaxf(g_cnt[g], 1.f);
    float acc = bh[0];
#pragma unroll
    for (int k = 0; k < HH; k++)
        acc += g_pool[g * HH + k] * rc * Wh[k];
    out[g] = acc;
}

// ---------------- launch ----------------
extern "C" void kernel_launch(void* const* d_in, const int* in_sizes, int n_in,
                              void* d_out, int out_size) {
    const float* x    = (const float*)d_in[0];
    const int*   ei   = (const int*)d_in[1];
    const float* ea   = (const float*)d_in[2];
    const int*   bvec = (const int*)d_in[3];
    const float* Wn0  = (const float*)d_in[4];
    const float* bn0  = (const float*)d_in[5];
    const float* We0  = (const float*)d_in[6];
    const float* be0  = (const float*)d_in[7];
    const float* WM   = (const float*)d_in[8];
    const float* bM   = (const float*)d_in[9];
    const float* WU   = (const float*)d_in[10];
    const float* bU   = (const float*)d_in[11];
    const float* Wn   = (const float*)d_in[12];
    const float* bn   = (const float*)d_in[13];
    const float* We   = (const float*)d_in[14];
    const float* be   = (const float*)d_in[15];
    const float* Wh   = (const float*)d_in[16];
    const float* bh   = (const float*)d_in[17];
    float* out = (float*)d_out;

    const int* src = ei;
    const int* dst = ei + EE;

    static int attr_done = 0;
    if (!attr_done) {
        cudaFuncSetAttribute(k_edge_tf32, cudaFuncAttributeMaxDynamicSharedMemorySize,
                             EDGE_SMEM);
        cudaFuncSetAttribute(k_enc_fused, cudaFuncAttributeMaxDynamicSharedMemorySize,
                             NODE_SMEM);
        cudaFuncSetAttribute(k_update_fused, cudaFuncAttributeMaxDynamicSharedMemorySize,
                             NODE_SMEM);
        attr_done = 1;
    }

    k_prep<<<(3 * 40960 + 2 * 3 * 16384 + 255) / 256, 256>>>(WM, WU, Wn, We);

    k_zero_misc<<<(NN + 255) / 256, 256>>>();
    k_deg<<<(EE + 255) / 256, 256>>>(dst);
    k_rdeg<<<(NN + 255) / 256, 256>>>();

    int nblk = (NN + BM - 1) / BM;
    k_enc_fused<<<nblk, TPB, NODE_SMEM>>>(x, Wn0, bn0);
    k_enc_edges<<<EE / BM, TPB>>>(ea, We0, be0);

    for (int l = 0; l < 3; l++) {
        k_zero_agg4<<<(NN * 32 + 255) / 256, 256>>>();
        k_edge_tf32<<<EE / BM, TPB, EDGE_SMEM>>>(src, dst, l, bM + l * HH,
                                                 be + l * HH, l < 2 ? 1 : 0);
        k_update_fused<<<nblk, TPB, NODE_SMEM>>>(l, bU + l * HH, bn + l * HH,
                                                 l < 2 ? 1 : 0);
    }

    int pool_threads = ((NN + 15) / 16) * 32;
    k_pool<<<(pool_threads + 255) / 256, 256>>>(bvec);
    k_head<<<1, GG>>>(Wh, bh, out);
}

// round 11
// speedup vs baseline: 3.0789x; 1.0238x over previous
#include <cuda_runtime.h>
#include <cstdint>

#define NN 100000
#define EE 640000
#define GG 256
#define HH 128
#define TPB 256
#define BM 64
#define EBM 128
#define ETPB 512
#define LDA 132
#define LDB 136
#define LDAS 36
#define LDAP 20
#define LDBP 136

typedef long long ll;

// ---------------- scratch ----------------
__device__ float g_h[NN * HH];
__device__ float g_agg[NN * HH];
__device__ float g_p1[NN * HH];
__device__ float g_p2[NN * HH];
__device__ uint32_t g_e[(ll)EE * HH];     // e stored as tf32 bit patterns
__device__ float g_rdeg[NN];
__device__ float g_deg[NN];
__device__ float g_pool[GG * HH];
__device__ float g_cnt[GG];

// pre-converted weights (filled once per launch by k_prep)
__device__ uint32_t g_wu_h[3 * 128 * HH],   g_wu_l[3 * 128 * HH];
__device__ uint32_t g_wn_h[3 * 64 * HH],    g_wn_l[3 * 64 * HH];
__device__ uint32_t g_wm12_h[3 * 128 * HH], g_wm12_l[3 * 128 * HH];
__device__ uint32_t g_wm3_t[3 * 128 * HH];
__device__ uint32_t g_we_t[3 * 128 * HH];

// ---------------- tf32 helpers ----------------
__device__ __forceinline__ uint32_t f2tf(float f) {
    uint32_t u;
    asm("cvt.rna.tf32.f32 %0, %1;" : "=r"(u) : "f"(f));
    return u;
}
__device__ __forceinline__ void mma_tf32(float* c, uint32_t a0, uint32_t a1,
                                         uint32_t a2, uint32_t a3,
                                         uint32_t b0, uint32_t b1) {
    asm volatile(
        "mma.sync.aligned.m16n8k8.row.col.f32.tf32.tf32.f32 "
        "{%0,%1,%2,%3}, {%4,%5,%6,%7}, {%8,%9}, {%0,%1,%2,%3};\n"
        : "+f"(c[0]), "+f"(c[1]), "+f"(c[2]), "+f"(c[3])
        : "r"(a0), "r"(a1), "r"(a2), "r"(a3), "r"(b0), "r"(b1));
}

// ---------------- bf16 split helpers ----------------
__device__ __forceinline__ void split_pack(float v0, float v1,
                                           uint32_t& ph, uint32_t& pl) {
    uint32_t h;
    asm("cvt.rn.bf16x2.f32 %0, %1, %2;" : "=r"(h) : "f"(v1), "f"(v0));
    float h0 = __uint_as_float(h << 16);
    float h1 = __uint_as_float(h & 0xffff0000u);
    asm("cvt.rn.bf16x2.f32 %0, %1, %2;" : "=r"(pl) : "f"(v1 - h1), "f"(v0 - h0));
    ph = h;
}
__device__ __forceinline__ void mma_bf16(float* c, uint32_t a0, uint32_t a1,
                                         uint32_t a2, uint32_t a3,
                                         uint32_t b0, uint32_t b1) {
    asm volatile(
        "mma.sync.aligned.m16n8k16.row.col.f32.bf16.bf16.f32 "
        "{%0,%1,%2,%3}, {%4,%5,%6,%7}, {%8,%9}, {%0,%1,%2,%3};\n"
        : "+f"(c[0]), "+f"(c[1]), "+f"(c[2]), "+f"(c[3])
        : "r"(a0), "r"(a1), "r"(a2), "r"(a3), "r"(b0), "r"(b1));
}

// ---------------- weight prep ----------------
__global__ void k_prep(const float* __restrict__ WM, const float* __restrict__ WU,
                       const float* __restrict__ Wn, const float* __restrict__ We) {
    int i = blockIdx.x * blockDim.x + threadIdx.x;
    if (i < 3 * 40960) {
        int l = i / 40960, j = i % 40960;
        const float* W;
        uint32_t *dh, *dl;
        if (j < 16384)      { W = WU + (ll)l * 256 * HH; dh = g_wu_h + l * 16384;  dl = g_wu_l + l * 16384; }
        else if (j < 24576) { j -= 16384; W = Wn + (ll)l * 128 * HH; dh = g_wn_h + l * 8192; dl = g_wn_l + l * 8192; }
        else                { j -= 24576; W = WM + (ll)l * 384 * HH; dh = g_wm12_h + l * 16384; dl = g_wm12_l + l * 16384; }
        int kp = j >> 7, n = j & 127;
        uint32_t h, lo;
        split_pack(W[(ll)(2 * kp) * HH + n], W[(ll)(2 * kp + 1) * HH + n], h, lo);
        dh[j] = h; dl[j] = lo;
    } else {
        int k = i - 3 * 40960;
        if (k < 3 * 16384) {
            int l = k / 16384, j = k % 16384;
            g_wm3_t[k] = f2tf(WM[(ll)l * 384 * HH + 256 * HH + j]);
        } else {
            k -= 3 * 16384;
            if (k < 3 * 16384)
                g_we_t[k] = f2tf(We[k]);
        }
    }
}

// ---------------- node-kernel smem partition (uint32 words) ----------------
#define OFF_APH 0
#define OFF_APL (64 * LDAP)
#define OFF_B1H (2 * 64 * LDAP)
#define OFF_B1L (OFF_B1H + 16 * LDBP)
#define OFF_B2H (OFF_B1H + 2 * 16 * LDBP)
#define OFF_B2L (OFF_B1H + 3 * 16 * LDBP)
#define OFF_CF  (OFF_B1H + 4 * 16 * LDBP)
#define NODE_SMEM ((OFF_CF + 64 * LDA) * 4)

__device__ __forceinline__ void stage_Bpre(uint32_t* Bh, uint32_t* Bl,
                                           const uint32_t* __restrict__ GH,
                                           const uint32_t* __restrict__ GL, int kp0) {
    int t = threadIdx.x;
#pragma unroll
    for (int i = 0; i < 2; i++) {
        int f = t + i * TPB;
        int kp = f >> 5, n = (f & 31) << 2;
        *(uint4*)(Bh + kp * LDBP + n) = *(const uint4*)(GH + (ll)(kp0 + kp) * HH + n);
        *(uint4*)(Bl + kp * LDBP + n) = *(const uint4*)(GL + (ll)(kp0 + kp) * HH + n);
    }
}

__device__ __forceinline__ void stage_Abf(uint32_t* Ah, uint32_t* Al,
                                          int r, int q, float4 v0, float4 v1) {
    uint32_t h0, l0, h1, l1;
    split_pack(v0.x, v0.y, h0, l0);
    split_pack(v0.z, v0.w, h1, l1);
    *(uint2*)(Ah + r * LDAP + 2 * q) = make_uint2(h0, h1);
    *(uint2*)(Al + r * LDAP + 2 * q) = make_uint2(l0, l1);
    split_pack(v1.x, v1.y, h0, l0);
    split_pack(v1.z, v1.w, h1, l1);
    *(uint2*)(Ah + r * LDAP + 8 + 2 * q) = make_uint2(h0, h1);
    *(uint2*)(Al + r * LDAP + 8 + 2 * q) = make_uint2(l0, l1);
}

__device__ __forceinline__ void stage_Abf_fromCf(uint32_t* Ah, uint32_t* Al,
                                                 const float* Cf, int kc) {
    int t = threadIdx.x;
    int r = t >> 2, q = t & 3;
    float4 v0 = *(const float4*)(Cf + r * LDA + kc * 32 + q * 4);
    float4 v1 = *(const float4*)(Cf + r * LDA + kc * 32 + 16 + q * 4);
    stage_Abf(Ah, Al, r, q, v0, v1);
}

__device__ __forceinline__ void mma3_bf(const uint32_t* Ah, const uint32_t* Al,
                                        const uint32_t* Bh, const uint32_t* Bl,
                                        int wm, int wn, int lr, int ka,
                                        float acc[8][4]) {
#pragma unroll
    for (int ks = 0; ks < 2; ks++) {
        int kpb = ks * 8;
        uint32_t ah0 = Ah[(wm + lr) * LDAP + kpb + ka];
        uint32_t ah1 = Ah[(wm + 8 + lr) * LDAP + kpb + ka];
        uint32_t ah2 = Ah[(wm + lr) * LDAP + kpb + ka + 4];
        uint32_t ah3 = Ah[(wm + 8 + lr) * LDAP + kpb + ka + 4];
        uint32_t al0 = Al[(wm + lr) * LDAP + kpb + ka];
        uint32_t al1 = Al[(wm + 8 + lr) * LDAP + kpb + ka];
        uint32_t al2 = Al[(wm + lr) * LDAP + kpb + ka + 4];
        uint32_t al3 = Al[(wm + 8 + lr) * LDAP + kpb + ka + 4];
#pragma unroll
        for (int nt = 0; nt < 8; nt++) {
            int nb = wn + nt * 8 + lr;
            uint32_t bh0 = Bh[(kpb + ka) * LDBP + nb];
            uint32_t bh1 = Bh[(kpb + ka + 4) * LDBP + nb];
            uint32_t bl0 = Bl[(kpb + ka) * LDBP + nb];
            uint32_t bl1 = Bl[(kpb + ka + 4) * LDBP + nb];
            mma_bf16(acc[nt], ah0, ah1, ah2, ah3, bh0, bh1);
            mma_bf16(acc[nt], al0, al1, al2, al3, bh0, bh1);
            mma_bf16(acc[nt], ah0, ah1, ah2, ah3, bl0, bl1);
        }
    }
}

__device__ __forceinline__ void mma3_bf_dual(const uint32_t* Ah, const uint32_t* Al,
                                             const uint32_t* B1h, const uint32_t* B1l,
                                             const uint32_t* B2h, const uint32_t* B2l,
                                             int wm, int wn, int lr, int ka,
                                             float accA[8][4], float accB[8][4]) {
#pragma unroll
    for (int ks = 0; ks < 2; ks++) {
        int kpb = ks * 8;
        uint32_t ah0 = Ah[(wm + lr) * LDAP + kpb + ka];
        uint32_t ah1 = Ah[(wm + 8 + lr) * LDAP + kpb + ka];
        uint32_t ah2 = Ah[(wm + lr) * LDAP + kpb + ka + 4];
        uint32_t ah3 = Ah[(wm + 8 + lr) * LDAP + kpb + ka + 4];
        uint32_t al0 = Al[(wm + lr) * LDAP + kpb + ka];
        uint32_t al1 = Al[(wm + 8 + lr) * LDAP + kpb + ka];
        uint32_t al2 = Al[(wm + lr) * LDAP + kpb + ka + 4];
        uint32_t al3 = Al[(wm + 8 + lr) * LDAP + kpb + ka + 4];
#pragma unroll
        for (int nt = 0; nt < 8; nt++) {
            int nb = wn + nt * 8 + lr;
            uint32_t bh0 = B1h[(kpb + ka) * LDBP + nb];
            uint32_t bh1 = B1h[(kpb + ka + 4) * LDBP + nb];
            uint32_t bl0 = B1l[(kpb + ka) * LDBP + nb];
            uint32_t bl1 = B1l[(kpb + ka + 4) * LDBP + nb];
            mma_bf16(accA[nt], ah0, ah1, ah2, ah3, bh0, bh1);
            mma_bf16(accA[nt], al0, al1, al2, al3, bh0, bh1);
            mma_bf16(accA[nt], ah0, ah1, ah2, ah3, bl0, bl1);
            bh0 = B2h[(kpb + ka) * LDBP + nb];
            bh1 = B2h[(kpb + ka + 4) * LDBP + nb];
            bl0 = B2l[(kpb + ka) * LDBP + nb];
            bl1 = B2l[(kpb + ka + 4) * LDBP + nb];
            mma_bf16(accB[nt], ah0, ah1, ah2, ah3, bh0, bh1);
            mma_bf16(accB[nt], al0, al1, al2, al3, bh0, bh1);
            mma_bf16(accB[nt], ah0, ah1, ah2, ah3, bl0, bl1);
        }
    }
}

__device__ __forceinline__ void frag_relu_toCf(float* Cf, const float acc[8][4],
                                               const float* __restrict__ bias,
                                               int wm, int wn, int lr, int ka) {
#pragma unroll
    for (int nt = 0; nt < 8; nt++) {
        int col = wn + nt * 8 + (ka << 1);
        float2 bb = *(const float2*)(bias + col);
        Cf[(wm + lr) * LDA + col]         = fmaxf(acc[nt][0] + bb.x, 0.f);
        Cf[(wm + lr) * LDA + col + 1]     = fmaxf(acc[nt][1] + bb.y, 0.f);
        Cf[(wm + 8 + lr) * LDA + col]     = fmaxf(acc[nt][2] + bb.x, 0.f);
        Cf[(wm + 8 + lr) * LDA + col + 1] = fmaxf(acc[nt][3] + bb.y, 0.f);
    }
}

// P1/P2 fused pass
__device__ __forceinline__ void p_passes(uint32_t* Ah, uint32_t* Al,
                                         uint32_t* B1h, uint32_t* B1l,
                                         uint32_t* B2h, uint32_t* B2l, float* Cf,
                                         int layer,
                                         int n0, int wm, int wn, int lr, int ka) {
    const uint32_t* GH1 = g_wm12_h + layer * 128 * HH;
    const uint32_t* GL1 = g_wm12_l + layer * 128 * HH;
    const uint32_t* GH2 = GH1 + 64 * HH;
    const uint32_t* GL2 = GL1 + 64 * HH;
    float accA[8][4], accB[8][4];
#pragma unroll
    for (int i = 0; i < 8; i++)
#pragma unroll
        for (int j = 0; j < 4; j++) { accA[i][j] = 0.f; accB[i][j] = 0.f; }
#pragma unroll 1
    for (int kc = 0; kc < 4; kc++) {
        __syncthreads();
        stage_Abf_fromCf(Ah, Al, Cf, kc);
        stage_Bpre(B1h, B1l, GH1, GL1, kc * 16);
        stage_Bpre(B2h, B2l, GH2, GL2, kc * 16);
        __syncthreads();
        mma3_bf_dual(Ah, Al, B1h, B1l, B2h, B2l, wm, wn, lr, ka, accA, accB);
    }
    int row0 = n0 + wm + lr, row1 = row0 + 8;
#pragma unroll
    for (int nt = 0; nt < 8; nt++) {
        int col = wn + nt * 8 + (ka << 1);
        if (row0 < NN) {
            *(float2*)(g_p1 + (ll)row0 * HH + col) = make_float2(accA[nt][0], accA[nt][1]);
            *(float2*)(g_p2 + (ll)row0 * HH + col) = make_float2(accB[nt][0], accB[nt][1]);
        }
        if (row1 < NN) {
            *(float2*)(g_p1 + (ll)row1 * HH + col) = make_float2(accA[nt][2], accA[nt][3]);
            *(float2*)(g_p2 + (ll)row1 * HH + col) = make_float2(accB[nt][2], accB[nt][3]);
        }
    }
}

// ---------------- fp32 helpers (encoders) ----------------
template<int KC>
__device__ __forceinline__ void load_B(float* Bs, const float* __restrict__ W, int k0) {
    int t = threadIdx.x;
#pragma unroll
    for (int i = 0; i < (KC * HH / 4) / TPB; i++) {
        int f = t + i * TPB;
        int k = f >> 5;
        int c = (f & 31) << 2;
        *(float4*)(Bs + k * HH + c) = *(const float4*)(W + (ll)(k0 + k) * HH + c);
    }
}

template<int KB, int LA>
__device__ __forceinline__ void mma8x4(const float* __restrict__ As,
                                       const float* __restrict__ Bs,
                                       int tr8, int tc4, float acc[8][4]) {
#pragma unroll
    for (int kb = 0; kb < KB; kb++) {
        float4 b0 = *(const float4*)(Bs + (kb * 4 + 0) * HH + tc4);
        float4 b1 = *(const float4*)(Bs + (kb * 4 + 1) * HH + tc4);
        float4 b2 = *(const float4*)(Bs + (kb * 4 + 2) * HH + tc4);
        float4 b3 = *(const float4*)(Bs + (kb * 4 + 3) * HH + tc4);
#pragma unroll
        for (int i = 0; i < 8; i++) {
            float4 a = *(const float4*)(As + (tr8 + i) * LA + kb * 4);
            acc[i][0] += a.x * b0.x; acc[i][1] += a.x * b0.y; acc[i][2] += a.x * b0.z; acc[i][3] += a.x * b0.w;
            acc[i][0] += a.y * b1.x; acc[i][1] += a.y * b1.y; acc[i][2] += a.y * b1.z; acc[i][3] += a.y * b1.w;
            acc[i][0] += a.z * b2.x; acc[i][1] += a.z * b2.y; acc[i][2] += a.z * b2.z; acc[i][3] += a.z * b2.w;
            acc[i][0] += a.w * b3.x; acc[i][1] += a.w * b3.y; acc[i][2] += a.w * b3.z; acc[i][3] += a.w * b3.w;
        }
    }
}

__device__ __forceinline__ float4 relu4(const float acc[4], float4 b) {
    float4 v;
    v.x = fmaxf(acc[0] + b.x, 0.f);
    v.y = fmaxf(acc[1] + b.y, 0.f);
    v.z = fmaxf(acc[2] + b.z, 0.f);
    v.w = fmaxf(acc[3] + b.w, 0.f);
    return v;
}

// ---------------- small utility kernels ----------------
__global__ void k_zero_misc() {
    int i = blockIdx.x * blockDim.x + threadIdx.x;
    if (i < NN) g_deg[i] = 0.f;
    if (i < GG * HH) g_pool[i] = 0.f;
    if (i < GG) g_cnt[i] = 0.f;
}
__global__ void k_deg(const int* __restrict__ dst) {
    int e = blockIdx.x * blockDim.x + threadIdx.x;
    if (e < EE) atomicAdd(&g_deg[dst[e]], 1.f);
}
__global__ void k_rdeg() {
    int n = blockIdx.x * blockDim.x + threadIdx.x;
    if (n < NN) g_rdeg[n] = 1.f / fmaxf(g_deg[n], 1.f);
}

// ---------------- fused node encoder (+ agg zero for layer 0) ----------------
__global__ void __launch_bounds__(TPB) k_enc_fused(const float* __restrict__ x,
                                                   const float* __restrict__ W,
                                                   const float* __restrict__ b) {
    extern __shared__ uint32_t sm[];
    uint32_t* Ah  = sm + OFF_APH;
    uint32_t* Al  = sm + OFF_APL;
    uint32_t* B1h = sm + OFF_B1H;
    uint32_t* B1l = sm + OFF_B1L;
    uint32_t* B2h = sm + OFF_B2H;
    uint32_t* B2l = sm + OFF_B2L;
    float*    Cf  = (float*)(sm + OFF_CF);
    float*    As  = (float*)Ah;
    float*    Bs  = (float*)B1h;

    int t = threadIdx.x;
    int lane = t & 31, wid = t >> 5;
    int wm = (wid >> 1) << 4, wn = (wid & 1) << 6;
    int lr = lane >> 2, ka = lane & 3;
    int tr8 = (t >> 5) << 3, tc4 = (t & 31) << 2;
    int r = t >> 2, q = t & 3;
    int n0 = blockIdx.x * BM;
    int row = min(n0 + r, NN - 1);

    // zero agg rows for this block (layer 0 prep)
    float4 z = make_float4(0.f, 0.f, 0.f, 0.f);
#pragma unroll
    for (int i = 0; i < 8; i++) {
        int f = t + i * TPB;
        int rr = n0 + (f >> 5);
        if (rr < NN)
            *(float4*)(g_agg + (ll)rr * HH + ((f & 31) << 2)) = z;
    }

    float acc[8][4] = {};
#pragma unroll 1
    for (int c = 0; c < 2; c++) {
        __syncthreads();
        const float* p = x + (ll)row * 64 + c * 32;
        *(float4*)(As + r * LDAS + q * 4)      = *(const float4*)(p + q * 4);
        *(float4*)(As + r * LDAS + 16 + q * 4) = *(const float4*)(p + 16 + q * 4);
        load_B<32>(Bs, W, c * 32);
        __syncthreads();
        mma8x4<8, LDAS>(As, Bs, tr8, tc4, acc);
    }
    __syncthreads();
    float4 bb = *(const float4*)(b + tc4);
#pragma unroll
    for (int i = 0; i < 8; i++) {
        float4 v = relu4(acc[i], bb);
        int rr = n0 + tr8 + i;
        *(float4*)(Cf + (tr8 + i) * LDA + tc4) = v;
        if (rr < NN)
            *(float4*)(g_h + (ll)rr * HH + tc4) = v;
    }
    p_passes(Ah, Al, B1h, B1l, B2h, B2l, Cf, 0, n0, wm, wn, lr, ka);
}

// ---------------- edge encoder (writes tf32 e) ----------------
__global__ void __launch_bounds__(TPB) k_enc_edges(const float* __restrict__ ea,
                                                   const float* __restrict__ W,
                                                   const float* __restrict__ b) {
    __shared__ __align__(16) float As[BM * 20];
    __shared__ __align__(16) float Bs[16 * HH];
    int t = threadIdx.x;
    int tr8 = (t >> 5) << 3, tc4 = (t & 31) << 2;
    int r = t >> 2, q = t & 3;
    int e0 = blockIdx.x * BM;
    float acc[8][4] = {};
    *(float4*)(As + r * 20 + q * 4) = *(const float4*)(ea + (ll)(e0 + r) * 16 + q * 4);
    load_B<16>(Bs, W, 0);
    __syncthreads();
    mma8x4<4, 20>(As, Bs, tr8, tc4, acc);
    float4 bb = *(const float4*)(b + tc4);
#pragma unroll
    for (int i = 0; i < 8; i++) {
        float4 v = relu4(acc[i], bb);
        uint4 u;
        u.x = f2tf(v.x); u.y = f2tf(v.y); u.z = f2tf(v.z); u.w = f2tf(v.w);
        *(uint4*)(g_e + (ll)(e0 + tr8 + i) * HH + tc4) = u;
    }
}

// ---------------- tf32 fused edge kernel: BM=128, 512 threads, dual-acc ----------------
// smem words: As 128*LDA (16896) | B1 32*LDB (4352) | B2 32*LDB (4352); Cs aliases As
#define EDGE_SMEM ((EBM * LDA + 2 * 32 * LDB) * 4)
__global__ void __launch_bounds__(ETPB) k_edge_tf32(const int* __restrict__ src,
                                                    const int* __restrict__ dst,
                                                    int layer,
                                                    const float* __restrict__ bM,
                                                    const float* __restrict__ be,
                                                    int do_edge) {
    extern __shared__ uint32_t smem_u[];
    uint32_t* As = smem_u;
    uint32_t* B1 = smem_u + EBM * LDA;
    uint32_t* B2 = B1 + 32 * LDB;
    float*    Cs = (float*)As;      // reused after mainloop

    const uint32_t* wm3_t = g_wm3_t + layer * 128 * HH;
    const uint32_t* we_t  = g_we_t  + layer * 128 * HH;

    int t = threadIdx.x;
    int lane = t & 31, wid = t >> 5;            // wid 0..15
    int wm = (wid >> 1) << 4;                   // 0..112
    int wn = (wid & 1) << 6;
    int lr = lane >> 2, ka = lane & 3;
    ll e0 = (ll)blockIdx.x * EBM;

    // A stage: pure copies (e already tf32)
#pragma unroll
    for (int i = 0; i < 8; i++) {
        int f = t + i * ETPB;
        int row = f >> 5, c4 = (f & 31) << 2;
        *(uint4*)(As + row * LDA + c4) = *(const uint4*)(g_e + (e0 + row) * HH + c4);
    }

    float accM[8][4], accE[8][4];
#pragma unroll
    for (int i = 0; i < 8; i++)
#pragma unroll
        for (int j = 0; j < 4; j++) { accM[i][j] = 0.f; accE[i][j] = 0.f; }

#pragma unroll 1
    for (int kc = 0; kc < 4; kc++) {
        __syncthreads();
        {
            int f = t;
            int krow = f >> 5, c4 = (f & 31) << 2;
            if (t < 512) {  // 32 rows x 8 uint4 = 256 uint4 per matrix; 2 iters over 512 thr
#pragma unroll
                for (int i = 0; i < 2; i++) {
                    int ff = t + i * ETPB;
                    if (ff < 32 * 32) {
                        krow = ff >> 5; c4 = (ff & 31) << 2;
                        *(uint4*)(B1 + krow * LDB + c4) =
                            *(const uint4*)(wm3_t + (ll)(kc * 32 + krow) * HH + c4);
                        if (do_edge)
                            *(uint4*)(B2 + krow * LDB + c4) =
                                *(const uint4*)(we_t + (ll)(kc * 32 + krow) * HH + c4);
                    }
                }
            }
        }
        __syncthreads();
#pragma unroll
        for (int ks = 0; ks < 4; ks++) {
            int kb = kc * 32 + ks * 8 + ka;
            uint32_t a0 = As[(wm + lr) * LDA + kb];
            uint32_t a1 = As[(wm + 8 + lr) * LDA + kb];
            uint32_t a2 = As[(wm + lr) * LDA + kb + 4];
            uint32_t a3 = As[(wm + 8 + lr) * LDA + kb + 4];
#pragma unroll
            for (int nt = 0; nt < 8; nt++) {
                int nb = wn + nt * 8 + lr;
                uint32_t b0 = B1[(ks * 8 + ka) * LDB + nb];
                uint32_t b1 = B1[(ks * 8 + 4 + ka) * LDB + nb];
                mma_tf32(accM[nt], a0, a1, a2, a3, b0, b1);
            }
            if (do_edge) {
#pragma unroll
                for (int nt = 0; nt < 8; nt++) {
                    int nb = wn + nt * 8 + lr;
                    uint32_t b0 = B2[(ks * 8 + ka) * LDB + nb];
                    uint32_t b1 = B2[(ks * 8 + 4 + ka) * LDB + nb];
                    mma_tf32(accE[nt], a0, a1, a2, a3, b0, b1);
                }
            }
        }
    }

    // epilogue 1: messages -> agg (atomic scatter); Cs aliases As (A data dead)
    __syncthreads();
#pragma unroll
    for (int nt = 0; nt < 8; nt++) {
        int col = wn + nt * 8 + (ka << 1);
        *(float2*)(Cs + (wm + lr) * LDA + col)     = make_float2(accM[nt][0], accM[nt][1]);
        *(float2*)(Cs + (wm + 8 + lr) * LDA + col) = make_float2(accM[nt][2], accM[nt][3]);
    }
    __syncthreads();
#pragma unroll
    for (int i = 0; i < 8; i++) {
        int f = t + i * ETPB;
        int row = f >> 5, c4 = (f & 31) << 2;
        int ge = (int)e0 + row;
        int d = dst[ge], s = src[ge];
        float4 c  = *(const float4*)(Cs + row * LDA + c4);
        float4 bb = *(const float4*)(bM + c4);
        float4 p1 = *(const float4*)(g_p1 + (ll)d * HH + c4);
        float4 p2 = *(const float4*)(g_p2 + (ll)s * HH + c4);
        float4 v;
        v.x = fmaxf(c.x + bb.x + p1.x + p2.x, 0.f);
        v.y = fmaxf(c.y + bb.y + p1.y + p2.y, 0.f);
        v.z = fmaxf(c.z + bb.z + p1.z + p2.z, 0.f);
        v.w = fmaxf(c.w + bb.w + p1.w + p2.w, 0.f);
        atomicAdd((float4*)(g_agg + (ll)d * HH + c4), v);
    }

    // epilogue 2: e = tf32(relu(e@We + be))
    if (do_edge) {
        __syncthreads();
#pragma unroll
        for (int nt = 0; nt < 8; nt++) {
            int col = wn + nt * 8 + (ka << 1);
            *(float2*)(Cs + (wm + lr) * LDA + col)     = make_float2(accE[nt][0], accE[nt][1]);
            *(float2*)(Cs + (wm + 8 + lr) * LDA + col) = make_float2(accE[nt][2], accE[nt][3]);
        }
        __syncthreads();
#pragma unroll
        for (int i = 0; i < 8; i++) {
            int f = t + i * ETPB;
            int row = f >> 5, c4 = (f & 31) << 2;
            float4 c  = *(const float4*)(Cs + row * LDA + c4);
            float4 bb = *(const float4*)(be + c4);
            uint4 u;
            u.x = f2tf(fmaxf(c.x + bb.x, 0.f));
            u.y = f2tf(fmaxf(c.y + bb.y, 0.f));
            u.z = f2tf(fmaxf(c.z + bb.z, 0.f));
            u.w = f2tf(fmaxf(c.w + bb.w, 0.f));
            *(uint4*)(g_e + (e0 + row) * HH + c4) = u;
        }
    }
}

// ---------------- fused update (3xBF16) + agg zeroing ----------------
__global__ void __launch_bounds__(TPB) k_update_fused(int layer,
                                                      const float* __restrict__ bU,
                                                      const float* __restrict__ bn,
                                                      int has_next) {
    extern __shared__ uint32_t sm[];
    uint32_t* Ah  = sm + OFF_APH;
    uint32_t* Al  = sm + OFF_APL;
    uint32_t* B1h = sm + OFF_B1H;
    uint32_t* B1l = sm + OFF_B1L;
    uint32_t* B2h = sm + OFF_B2H;
    uint32_t* B2l = sm + OFF_B2L;
    float*    Cf  = (float*)(sm + OFF_CF);

    const uint32_t* wu_h = g_wu_h + layer * 128 * HH;
    const uint32_t* wu_l = g_wu_l + layer * 128 * HH;
    const uint32_t* wn_h = g_wn_h + layer * 64 * HH;
    const uint32_t* wn_l = g_wn_l + layer * 64 * HH;

    int t = threadIdx.x;
    int lane = t & 31, wid = t >> 5;
    int wm = (wid >> 1) << 4, wn = (wid & 1) << 6;
    int lr = lane >> 2, ka = lane & 3;
    int r = t >> 2, q = t & 3;
    int n0 = blockIdx.x * BM;
    int row = min(n0 + r, NN - 1);
    float rd = g_rdeg[row];

    // ---- stage 1: u = relu([h | agg*rdeg] @ WU + bU), K=256 ----
    float acc[8][4];
#pragma unroll
    for (int i = 0; i < 8; i++)
#pragma unroll
        for (int j = 0; j < 4; j++) acc[i][j] = 0.f;
#pragma unroll 1
    for (int c = 0; c < 8; c++) {
        __syncthreads();
        const float* p = (c < 4) ? (g_h + (ll)row * HH + c * 32)
                                 : (g_agg + (ll)row * HH + (c - 4) * 32);
        float sc = (c < 4) ? 1.f : rd;
        float4 v0 = *(const float4*)(p + q * 4);
        float4 v1 = *(const float4*)(p + 16 + q * 4);
        v0.x *= sc; v0.y *= sc; v0.z *= sc; v0.w *= sc;
        v1.x *= sc; v1.y *= sc; v1.z *= sc; v1.w *= sc;
        stage_Abf(Ah, Al, r, q, v0, v1);
        stage_Bpre(B1h, B1l, wu_h, wu_l, c * 16);
        __syncthreads();
        mma3_bf(Ah, Al, B1h, B1l, wm, wn, lr, ka, acc);
    }
    frag_relu_toCf(Cf, acc, bU, wm, wn, lr, ka);

    // zero agg rows for the next layer (all stage-1 agg reads completed:
    // last read precedes the final staged __syncthreads above)
    {
        float4 z = make_float4(0.f, 0.f, 0.f, 0.f);
#pragma unroll
        for (int i = 0; i < 8; i++) {
            int f = t + i * TPB;
            int rr = n0 + (f >> 5);
            if (rr < NN)
                *(float4*)(g_agg + (ll)rr * HH + ((f & 31) << 2)) = z;
        }
    }

    // ---- stage 2: hnew = relu(u @ Wn + bn), K=128 ----
#pragma unroll
    for (int i = 0; i < 8; i++)
#pragma unroll
        for (int j = 0; j < 4; j++) acc[i][j] = 0.f;
#pragma unroll 1
    for (int kc = 0; kc < 4; kc++) {
        __syncthreads();
        stage_Abf_fromCf(Ah, Al, Cf, kc);
        stage_Bpre(B1h, B1l, wn_h, wn_l, kc * 16);
        __syncthreads();
        mma3_bf(Ah, Al, B1h, B1l, wm, wn, lr, ka, acc);
    }
    __syncthreads();
    frag_relu_toCf(Cf, acc, bn, wm, wn, lr, ka);
    __syncthreads();
#pragma unroll
    for (int i = 0; i < 8; i++) {
        int f = t + i * TPB;
        int rr = f >> 5, c4 = (f & 31) << 2;
        int gr = n0 + rr;
        if (gr < NN)
            *(float4*)(g_h + (ll)gr * HH + c4) = *(const float4*)(Cf + rr * LDA + c4);
    }

    // ---- stage 3: fused P1/P2 for next layer ----
    if (has_next)
        p_passes(Ah, Al, B1h, B1l, B2h, B2l, Cf, layer + 1, n0, wm, wn, lr, ka);
}

// ---------------- global mean pool ----------------
__global__ void k_pool(const int* __restrict__ bvec) {
    int t = blockIdx.x * blockDim.x + threadIdx.x;
    int c4 = (t & 31) << 2;
    int nb = (t >> 5) * 16;
    if (nb >= NN) return;
    int end = min(nb + 16, NN);
    int g = bvec[nb];
    float4 s = make_float4(0.f, 0.f, 0.f, 0.f);
    float cnt = 0.f;
    for (int n = nb; n < end; n++) {
        int gn = bvec[n];
        if (gn != g) {
            atomicAdd((float4*)(g_pool + g * HH + c4), s);
            if (c4 == 0) atomicAdd(&g_cnt[g], cnt);
            s = make_float4(0.f, 0.f, 0.f, 0.f);
            cnt = 0.f;
            g = gn;
        }
        float4 hv = *(const float4*)(g_h + (ll)n * HH + c4);
        s.x += hv.x; s.y += hv.y; s.z += hv.z; s.w += hv.w;
        cnt += 1.f;
    }
    atomicAdd((float4*)(g_pool + g * HH + c4), s);
    if (c4 == 0) atomicAdd(&g_cnt[g], cnt);
}

__global__ void k_head(const float* __restrict__ Wh, const float* __restrict__ bh,
                       float* __restrict__ out) {
    int g = threadIdx.x;
    float rc = 1.f / fmaxf(g_cnt[g], 1.f);
    float acc = bh[0];
#pragma unroll
    for (int k = 0; k < HH; k++)
        acc += g_pool[g * HH + k] * rc * Wh[k];
    out[g] = acc;
}

// ---------------- launch ----------------
extern "C" void kernel_launch(void* const* d_in, const int* in_sizes, int n_in,
                              void* d_out, int out_size) {
    const float* x    = (const float*)d_in[0];
    const int*   ei   = (const int*)d_in[1];
    const float* ea   = (const float*)d_in[2];
    const int*   bvec = (const int*)d_in[3];
    const float* Wn0  = (const float*)d_in[4];
    const float* bn0  = (const float*)d_in[5];
    const float* We0  = (const float*)d_in[6];
    const float* be0  = (const float*)d_in[7];
    const float* WM   = (const float*)d_in[8];
    const float* bM   = (const float*)d_in[9];
    const float* WU   = (const float*)d_in[10];
    const float* bU   = (const float*)d_in[11];
    const float* Wn   = (const float*)d_in[12];
    const float* bn   = (const float*)d_in[13];
    const float* We   = (const float*)d_in[14];
    const float* be   = (const float*)d_in[15];
    const float* Wh   = (const float*)d_in[16];
    const float* bh   = (const float*)d_in[17];
    float* out = (float*)d_out;

    const int* src = ei;
    const int* dst = ei + EE;

    static int attr_done = 0;
    if (!attr_done) {
        cudaFuncSetAttribute(k_edge_tf32, cudaFuncAttributeMaxDynamicSharedMemorySize,
                             EDGE_SMEM);
        cudaFuncSetAttribute(k_enc_fused, cudaFuncAttributeMaxDynamicSharedMemorySize,
                             NODE_SMEM);
        cudaFuncSetAttribute(k_update_fused, cudaFuncAttributeMaxDynamicSharedMemorySize,
                             NODE_SMEM);
        attr_done = 1;
    }

    k_prep<<<(3 * 40960 + 2 * 3 * 16384 + 255) / 256, 256>>>(WM, WU, Wn, We);

    k_zero_misc<<<(NN + 255) / 256, 256>>>();
    k_deg<<<(EE + 255) / 256, 256>>>(dst);
    k_rdeg<<<(NN + 255) / 256, 256>>>();

    int nblk = (NN + BM - 1) / BM;
    k_enc_fused<<<nblk, TPB, NODE_SMEM>>>(x, Wn0, bn0);
    k_enc_edges<<<EE / BM, TPB>>>(ea, We0, be0);

    for (int l = 0; l < 3; l++) {
        k_edge_tf32<<<EE / EBM, ETPB, EDGE_SMEM>>>(src, dst, l, bM + l * HH,
                                                   be + l * HH, l < 2 ? 1 : 0);
        k_update_fused<<<nblk, TPB, NODE_SMEM>>>(l, bU + l * HH, bn + l * HH,
                                                 l < 2 ? 1 : 0);
    }

    int pool_threads = ((NN + 15) / 16) * 32;
    k_pool<<<(pool_threads + 255) / 256, 256>>>(bvec);
    k_head<<<1, GG>>>(Wh, bh, out);
}

// round 12
// speedup vs baseline: 3.2305x; 1.0493x over previous
#include <cuda_runtime.h>
#include <cstdint>

#define NN 100000
#define EE 640000
#define GG 256
#define HH 128
#define TPB 256
#define BM 64
#define EBM 128
#define ETPB 512
#define LDA 132
#define LDB 136
#define LDAS 36
#define LDAP 20
#define LDBP 136

typedef long long ll;

// ---------------- scratch ----------------
__device__ float g_h[NN * HH];
__device__ float g_agg[NN * HH];
__device__ float g_p1[NN * HH];
__device__ float g_p2[NN * HH];
__device__ uint32_t g_e[(ll)EE * HH];     // e stored as tf32 bit patterns
__device__ float g_rdeg[NN];
__device__ float g_deg[NN];
__device__ float g_pool[GG * HH];
__device__ float g_cnt[GG];

// pre-converted weights (filled once per launch by k_prep)
__device__ uint32_t g_wu_h[3 * 128 * HH],   g_wu_l[3 * 128 * HH];
__device__ uint32_t g_wn_h[3 * 64 * HH],    g_wn_l[3 * 64 * HH];
__device__ uint32_t g_wm12_h[3 * 128 * HH], g_wm12_l[3 * 128 * HH];
__device__ uint32_t g_wm3_t[3 * 128 * HH];
__device__ uint32_t g_we_t[3 * 128 * HH];
__device__ uint32_t g_we0_t[16 * HH];       // edge encoder weight tf32

// ---------------- tf32 helpers ----------------
__device__ __forceinline__ uint32_t f2tf(float f) {
    uint32_t u;
    asm("cvt.rna.tf32.f32 %0, %1;" : "=r"(u) : "f"(f));
    return u;
}
__device__ __forceinline__ void mma_tf32(float* c, uint32_t a0, uint32_t a1,
                                         uint32_t a2, uint32_t a3,
                                         uint32_t b0, uint32_t b1) {
    asm volatile(
        "mma.sync.aligned.m16n8k8.row.col.f32.tf32.tf32.f32 "
        "{%0,%1,%2,%3}, {%4,%5,%6,%7}, {%8,%9}, {%0,%1,%2,%3};\n"
        : "+f"(c[0]), "+f"(c[1]), "+f"(c[2]), "+f"(c[3])
        : "r"(a0), "r"(a1), "r"(a2), "r"(a3), "r"(b0), "r"(b1));
}

// ---------------- bf16 split helpers ----------------
__device__ __forceinline__ void split_pack(float v0, float v1,
                                           uint32_t& ph, uint32_t& pl) {
    uint32_t h;
    asm("cvt.rn.bf16x2.f32 %0, %1, %2;" : "=r"(h) : "f"(v1), "f"(v0));
    float h0 = __uint_as_float(h << 16);
    float h1 = __uint_as_float(h & 0xffff0000u);
    asm("cvt.rn.bf16x2.f32 %0, %1, %2;" : "=r"(pl) : "f"(v1 - h1), "f"(v0 - h0));
    ph = h;
}
__device__ __forceinline__ void mma_bf16(float* c, uint32_t a0, uint32_t a1,
                                         uint32_t a2, uint32_t a3,
                                         uint32_t b0, uint32_t b1) {
    asm volatile(
        "mma.sync.aligned.m16n8k16.row.col.f32.bf16.bf16.f32 "
        "{%0,%1,%2,%3}, {%4,%5,%6,%7}, {%8,%9}, {%0,%1,%2,%3};\n"
        : "+f"(c[0]), "+f"(c[1]), "+f"(c[2]), "+f"(c[3])
        : "r"(a0), "r"(a1), "r"(a2), "r"(a3), "r"(b0), "r"(b1));
}

// ---------------- weight prep ----------------
__global__ void k_prep(const float* __restrict__ WM, const float* __restrict__ WU,
                       const float* __restrict__ Wn, const float* __restrict__ We,
                       const float* __restrict__ We0) {
    int i = blockIdx.x * blockDim.x + threadIdx.x;
    if (i < 3 * 40960) {
        int l = i / 40960, j = i % 40960;
        const float* W;
        uint32_t *dh, *dl;
        if (j < 16384)      { W = WU + (ll)l * 256 * HH; dh = g_wu_h + l * 16384;  dl = g_wu_l + l * 16384; }
        else if (j < 24576) { j -= 16384; W = Wn + (ll)l * 128 * HH; dh = g_wn_h + l * 8192; dl = g_wn_l + l * 8192; }
        else                { j -= 24576; W = WM + (ll)l * 384 * HH; dh = g_wm12_h + l * 16384; dl = g_wm12_l + l * 16384; }
        int kp = j >> 7, n = j & 127;
        uint32_t h, lo;
        split_pack(W[(ll)(2 * kp) * HH + n], W[(ll)(2 * kp + 1) * HH + n], h, lo);
        dh[j] = h; dl[j] = lo;
    } else {
        int k = i - 3 * 40960;
        if (k < 3 * 16384) {
            int l = k / 16384, j = k % 16384;
            g_wm3_t[k] = f2tf(WM[(ll)l * 384 * HH + 256 * HH + j]);
        } else {
            k -= 3 * 16384;
            if (k < 3 * 16384) {
                g_we_t[k] = f2tf(We[k]);
            } else {
                k -= 3 * 16384;
                if (k < 16 * HH)
                    g_we0_t[k] = f2tf(We0[k]);
            }
        }
    }
}

// ---------------- node-kernel smem partition (uint32 words) ----------------
#define OFF_APH 0
#define OFF_APL (64 * LDAP)
#define OFF_B1H (2 * 64 * LDAP)
#define OFF_B1L (OFF_B1H + 16 * LDBP)
#define OFF_B2H (OFF_B1H + 2 * 16 * LDBP)
#define OFF_B2L (OFF_B1H + 3 * 16 * LDBP)
#define OFF_CF  (OFF_B1H + 4 * 16 * LDBP)
#define NODE_SMEM ((OFF_CF + 64 * LDA) * 4)

__device__ __forceinline__ void stage_Bpre(uint32_t* Bh, uint32_t* Bl,
                                           const uint32_t* __restrict__ GH,
                                           const uint32_t* __restrict__ GL, int kp0) {
    int t = threadIdx.x;
#pragma unroll
    for (int i = 0; i < 2; i++) {
        int f = t + i * TPB;
        int kp = f >> 5, n = (f & 31) << 2;
        *(uint4*)(Bh + kp * LDBP + n) = *(const uint4*)(GH + (ll)(kp0 + kp) * HH + n);
        *(uint4*)(Bl + kp * LDBP + n) = *(const uint4*)(GL + (ll)(kp0 + kp) * HH + n);
    }
}

__device__ __forceinline__ void stage_Abf(uint32_t* Ah, uint32_t* Al,
                                          int r, int q, float4 v0, float4 v1) {
    uint32_t h0, l0, h1, l1;
    split_pack(v0.x, v0.y, h0, l0);
    split_pack(v0.z, v0.w, h1, l1);
    *(uint2*)(Ah + r * LDAP + 2 * q) = make_uint2(h0, h1);
    *(uint2*)(Al + r * LDAP + 2 * q) = make_uint2(l0, l1);
    split_pack(v1.x, v1.y, h0, l0);
    split_pack(v1.z, v1.w, h1, l1);
    *(uint2*)(Ah + r * LDAP + 8 + 2 * q) = make_uint2(h0, h1);
    *(uint2*)(Al + r * LDAP + 8 + 2 * q) = make_uint2(l0, l1);
}

__device__ __forceinline__ void stage_Abf_fromCf(uint32_t* Ah, uint32_t* Al,
                                                 const float* Cf, int kc) {
    int t = threadIdx.x;
    int r = t >> 2, q = t & 3;
    float4 v0 = *(const float4*)(Cf + r * LDA + kc * 32 + q * 4);
    float4 v1 = *(const float4*)(Cf + r * LDA + kc * 32 + 16 + q * 4);
    stage_Abf(Ah, Al, r, q, v0, v1);
}

__device__ __forceinline__ void mma3_bf(const uint32_t* Ah, const uint32_t* Al,
                                        const uint32_t* Bh, const uint32_t* Bl,
                                        int wm, int wn, int lr, int ka,
                                        float acc[8][4]) {
#pragma unroll
    for (int ks = 0; ks < 2; ks++) {
        int kpb = ks * 8;
        uint32_t ah0 = Ah[(wm + lr) * LDAP + kpb + ka];
        uint32_t ah1 = Ah[(wm + 8 + lr) * LDAP + kpb + ka];
        uint32_t ah2 = Ah[(wm + lr) * LDAP + kpb + ka + 4];
        uint32_t ah3 = Ah[(wm + 8 + lr) * LDAP + kpb + ka + 4];
        uint32_t al0 = Al[(wm + lr) * LDAP + kpb + ka];
        uint32_t al1 = Al[(wm + 8 + lr) * LDAP + kpb + ka];
        uint32_t al2 = Al[(wm + lr) * LDAP + kpb + ka + 4];
        uint32_t al3 = Al[(wm + 8 + lr) * LDAP + kpb + ka + 4];
#pragma unroll
        for (int nt = 0; nt < 8; nt++) {
            int nb = wn + nt * 8 + lr;
            uint32_t bh0 = Bh[(kpb + ka) * LDBP + nb];
            uint32_t bh1 = Bh[(kpb + ka + 4) * LDBP + nb];
            uint32_t bl0 = Bl[(kpb + ka) * LDBP + nb];
            uint32_t bl1 = Bl[(kpb + ka + 4) * LDBP + nb];
            mma_bf16(acc[nt], ah0, ah1, ah2, ah3, bh0, bh1);
            mma_bf16(acc[nt], al0, al1, al2, al3, bh0, bh1);
            mma_bf16(acc[nt], ah0, ah1, ah2, ah3, bl0, bl1);
        }
    }
}

__device__ __forceinline__ void mma3_bf_dual(const uint32_t* Ah, const uint32_t* Al,
                                             const uint32_t* B1h, const uint32_t* B1l,
                                             const uint32_t* B2h, const uint32_t* B2l,
                                             int wm, int wn, int lr, int ka,
                                             float accA[8][4], float accB[8][4]) {
#pragma unroll
    for (int ks = 0; ks < 2; ks++) {
        int kpb = ks * 8;
        uint32_t ah0 = Ah[(wm + lr) * LDAP + kpb + ka];
        uint32_t ah1 = Ah[(wm + 8 + lr) * LDAP + kpb + ka];
        uint32_t ah2 = Ah[(wm + lr) * LDAP + kpb + ka + 4];
        uint32_t ah3 = Ah[(wm + 8 + lr) * LDAP + kpb + ka + 4];
        uint32_t al0 = Al[(wm + lr) * LDAP + kpb + ka];
        uint32_t al1 = Al[(wm + 8 + lr) * LDAP + kpb + ka];
        uint32_t al2 = Al[(wm + lr) * LDAP + kpb + ka + 4];
        uint32_t al3 = Al[(wm + 8 + lr) * LDAP + kpb + ka + 4];
#pragma unroll
        for (int nt = 0; nt < 8; nt++) {
            int nb = wn + nt * 8 + lr;
            uint32_t bh0 = B1h[(kpb + ka) * LDBP + nb];
            uint32_t bh1 = B1h[(kpb + ka + 4) * LDBP + nb];
            uint32_t bl0 = B1l[(kpb + ka) * LDBP + nb];
            uint32_t bl1 = B1l[(kpb + ka + 4) * LDBP + nb];
            mma_bf16(accA[nt], ah0, ah1, ah2, ah3, bh0, bh1);
            mma_bf16(accA[nt], al0, al1, al2, al3, bh0, bh1);
            mma_bf16(accA[nt], ah0, ah1, ah2, ah3, bl0, bl1);
            bh0 = B2h[(kpb + ka) * LDBP + nb];
            bh1 = B2h[(kpb + ka + 4) * LDBP + nb];
            bl0 = B2l[(kpb + ka) * LDBP + nb];
            bl1 = B2l[(kpb + ka + 4) * LDBP + nb];
            mma_bf16(accB[nt], ah0, ah1, ah2, ah3, bh0, bh1);
            mma_bf16(accB[nt], al0, al1, al2, al3, bh0, bh1);
            mma_bf16(accB[nt], ah0, ah1, ah2, ah3, bl0, bl1);
        }
    }
}

__device__ __forceinline__ void frag_relu_toCf(float* Cf, const float acc[8][4],
                                               const float* __restrict__ bias,
                                               int wm, int wn, int lr, int ka) {
#pragma unroll
    for (int nt = 0; nt < 8; nt++) {
        int col = wn + nt * 8 + (ka << 1);
        float2 bb = *(const float2*)(bias + col);
        Cf[(wm + lr) * LDA + col]         = fmaxf(acc[nt][0] + bb.x, 0.f);
        Cf[(wm + lr) * LDA + col + 1]     = fmaxf(acc[nt][1] + bb.y, 0.f);
        Cf[(wm + 8 + lr) * LDA + col]     = fmaxf(acc[nt][2] + bb.x, 0.f);
        Cf[(wm + 8 + lr) * LDA + col + 1] = fmaxf(acc[nt][3] + bb.y, 0.f);
    }
}

// P1/P2 fused pass
__device__ __forceinline__ void p_passes(uint32_t* Ah, uint32_t* Al,
                                         uint32_t* B1h, uint32_t* B1l,
                                         uint32_t* B2h, uint32_t* B2l, float* Cf,
                                         int layer,
                                         int n0, int wm, int wn, int lr, int ka) {
    const uint32_t* GH1 = g_wm12_h + layer * 128 * HH;
    const uint32_t* GL1 = g_wm12_l + layer * 128 * HH;
    const uint32_t* GH2 = GH1 + 64 * HH;
    const uint32_t* GL2 = GL1 + 64 * HH;
    float accA[8][4], accB[8][4];
#pragma unroll
    for (int i = 0; i < 8; i++)
#pragma unroll
        for (int j = 0; j < 4; j++) { accA[i][j] = 0.f; accB[i][j] = 0.f; }
#pragma unroll 1
    for (int kc = 0; kc < 4; kc++) {
        __syncthreads();
        stage_Abf_fromCf(Ah, Al, Cf, kc);
        stage_Bpre(B1h, B1l, GH1, GL1, kc * 16);
        stage_Bpre(B2h, B2l, GH2, GL2, kc * 16);
        __syncthreads();
        mma3_bf_dual(Ah, Al, B1h, B1l, B2h, B2l, wm, wn, lr, ka, accA, accB);
    }
    int row0 = n0 + wm + lr, row1 = row0 + 8;
#pragma unroll
    for (int nt = 0; nt < 8; nt++) {
        int col = wn + nt * 8 + (ka << 1);
        if (row0 < NN) {
            *(float2*)(g_p1 + (ll)row0 * HH + col) = make_float2(accA[nt][0], accA[nt][1]);
            *(float2*)(g_p2 + (ll)row0 * HH + col) = make_float2(accB[nt][0], accB[nt][1]);
        }
        if (row1 < NN) {
            *(float2*)(g_p1 + (ll)row1 * HH + col) = make_float2(accA[nt][2], accA[nt][3]);
            *(float2*)(g_p2 + (ll)row1 * HH + col) = make_float2(accB[nt][2], accB[nt][3]);
        }
    }
}

// ---------------- fp32 helpers (node encoder) ----------------
template<int KC>
__device__ __forceinline__ void load_B(float* Bs, const float* __restrict__ W, int k0) {
    int t = threadIdx.x;
#pragma unroll
    for (int i = 0; i < (KC * HH / 4) / TPB; i++) {
        int f = t + i * TPB;
        int k = f >> 5;
        int c = (f & 31) << 2;
        *(float4*)(Bs + k * HH + c) = *(const float4*)(W + (ll)(k0 + k) * HH + c);
    }
}

template<int KB, int LA>
__device__ __forceinline__ void mma8x4(const float* __restrict__ As,
                                       const float* __restrict__ Bs,
                                       int tr8, int tc4, float acc[8][4]) {
#pragma unroll
    for (int kb = 0; kb < KB; kb++) {
        float4 b0 = *(const float4*)(Bs + (kb * 4 + 0) * HH + tc4);
        float4 b1 = *(const float4*)(Bs + (kb * 4 + 1) * HH + tc4);
        float4 b2 = *(const float4*)(Bs + (kb * 4 + 2) * HH + tc4);
        float4 b3 = *(const float4*)(Bs + (kb * 4 + 3) * HH + tc4);
#pragma unroll
        for (int i = 0; i < 8; i++) {
            float4 a = *(const float4*)(As + (tr8 + i) * LA + kb * 4);
            acc[i][0] += a.x * b0.x; acc[i][1] += a.x * b0.y; acc[i][2] += a.x * b0.z; acc[i][3] += a.x * b0.w;
            acc[i][0] += a.y * b1.x; acc[i][1] += a.y * b1.y; acc[i][2] += a.y * b1.z; acc[i][3] += a.y * b1.w;
            acc[i][0] += a.z * b2.x; acc[i][1] += a.z * b2.y; acc[i][2] += a.z * b2.z; acc[i][3] += a.z * b2.w;
            acc[i][0] += a.w * b3.x; acc[i][1] += a.w * b3.y; acc[i][2] += a.w * b3.z; acc[i][3] += a.w * b3.w;
        }
    }
}

__device__ __forceinline__ float4 relu4(const float acc[4], float4 b) {
    float4 v;
    v.x = fmaxf(acc[0] + b.x, 0.f);
    v.y = fmaxf(acc[1] + b.y, 0.f);
    v.z = fmaxf(acc[2] + b.z, 0.f);
    v.w = fmaxf(acc[3] + b.w, 0.f);
    return v;
}

// ---------------- small utility kernels ----------------
__global__ void k_zero_misc() {
    int i = blockIdx.x * blockDim.x + threadIdx.x;
    if (i < NN) g_deg[i] = 0.f;
    if (i < GG * HH) g_pool[i] = 0.f;
    if (i < GG) g_cnt[i] = 0.f;
}
__global__ void k_deg(const int* __restrict__ dst) {
    int e = blockIdx.x * blockDim.x + threadIdx.x;
    if (e < EE) atomicAdd(&g_deg[dst[e]], 1.f);
}
__global__ void k_rdeg() {
    int n = blockIdx.x * blockDim.x + threadIdx.x;
    if (n < NN) g_rdeg[n] = 1.f / fmaxf(g_deg[n], 1.f);
}

// ---------------- fused node encoder (+ agg zero for layer 0) ----------------
__global__ void __launch_bounds__(TPB) k_enc_fused(const float* __restrict__ x,
                                                   const float* __restrict__ W,
                                                   const float* __restrict__ b) {
    extern __shared__ uint32_t sm[];
    uint32_t* Ah  = sm + OFF_APH;
    uint32_t* Al  = sm + OFF_APL;
    uint32_t* B1h = sm + OFF_B1H;
    uint32_t* B1l = sm + OFF_B1L;
    uint32_t* B2h = sm + OFF_B2H;
    uint32_t* B2l = sm + OFF_B2L;
    float*    Cf  = (float*)(sm + OFF_CF);
    float*    As  = (float*)Ah;
    float*    Bs  = (float*)B1h;

    int t = threadIdx.x;
    int lane = t & 31, wid = t >> 5;
    int wm = (wid >> 1) << 4, wn = (wid & 1) << 6;
    int lr = lane >> 2, ka = lane & 3;
    int tr8 = (t >> 5) << 3, tc4 = (t & 31) << 2;
    int r = t >> 2, q = t & 3;
    int n0 = blockIdx.x * BM;
    int row = min(n0 + r, NN - 1);

    // zero agg rows for this block (layer 0 prep)
    float4 z = make_float4(0.f, 0.f, 0.f, 0.f);
#pragma unroll
    for (int i = 0; i < 8; i++) {
        int f = t + i * TPB;
        int rr = n0 + (f >> 5);
        if (rr < NN)
            *(float4*)(g_agg + (ll)rr * HH + ((f & 31) << 2)) = z;
    }

    float acc[8][4] = {};
#pragma unroll 1
    for (int c = 0; c < 2; c++) {
        __syncthreads();
        const float* p = x + (ll)row * 64 + c * 32;
        *(float4*)(As + r * LDAS + q * 4)      = *(const float4*)(p + q * 4);
        *(float4*)(As + r * LDAS + 16 + q * 4) = *(const float4*)(p + 16 + q * 4);
        load_B<32>(Bs, W, c * 32);
        __syncthreads();
        mma8x4<8, LDAS>(As, Bs, tr8, tc4, acc);
    }
    __syncthreads();
    float4 bb = *(const float4*)(b + tc4);
#pragma unroll
    for (int i = 0; i < 8; i++) {
        float4 v = relu4(acc[i], bb);
        int rr = n0 + tr8 + i;
        *(float4*)(Cf + (tr8 + i) * LDA + tc4) = v;
        if (rr < NN)
            *(float4*)(g_h + (ll)rr * HH + tc4) = v;
    }
    p_passes(Ah, Al, B1h, B1l, B2h, B2l, Cf, 0, n0, wm, wn, lr, ka);
}

// ---------------- tf32 fused edge kernel: BM=128, 512 threads, dual-acc ----------------
// layer 0 additionally computes e = relu(ea @ We0 + be0) in-tile (no g_e read).
// smem words: As 128*LDA (16896) | B1 32*LDB (4352) | B2 32*LDB (4352); Cs aliases As
#define EDGE_SMEM ((EBM * LDA + 2 * 32 * LDB) * 4)
__global__ void __launch_bounds__(ETPB) k_edge_tf32(const int* __restrict__ src,
                                                    const int* __restrict__ dst,
                                                    int layer,
                                                    const float* __restrict__ bM,
                                                    const float* __restrict__ be,
                                                    const float* __restrict__ ea,
                                                    const float* __restrict__ be0,
                                                    int do_edge) {
    extern __shared__ uint32_t smem_u[];
    uint32_t* As = smem_u;
    uint32_t* B1 = smem_u + EBM * LDA;
    uint32_t* B2 = B1 + 32 * LDB;
    float*    Cs = (float*)As;      // reused after mainloop

    const uint32_t* wm3_t = g_wm3_t + layer * 128 * HH;
    const uint32_t* we_t  = g_we_t  + layer * 128 * HH;

    int t = threadIdx.x;
    int lane = t & 31, wid = t >> 5;            // wid 0..15
    int wm = (wid >> 1) << 4;                   // 0..112
    int wn = (wid & 1) << 6;
    int lr = lane >> 2, ka = lane & 3;
    ll e0 = (ll)blockIdx.x * EBM;

    if (layer == 0) {
        // ---- in-tile edge encoder: As = tf32(relu(ea @ We0 + be0)) ----
        uint32_t* EA = B1;   // ea tile, tf32, [row][LDAP]
        uint32_t* WB = B2;   // We0 tf32, [k][LDB]
        {
            int rr = t >> 2, qq = t & 3;   // 128 rows x 4 float4
            float4 v = *(const float4*)(ea + (e0 + rr) * 16 + qq * 4);
            uint4 u;
            u.x = f2tf(v.x); u.y = f2tf(v.y); u.z = f2tf(v.z); u.w = f2tf(v.w);
            *(uint4*)(EA + rr * LDAP + qq * 4) = u;
        }
        {
            int krow = t >> 5, c4 = (t & 31) << 2;   // 16 rows x 32 uint4 = 512
            *(uint4*)(WB + krow * LDB + c4) = *(const uint4*)(g_we0_t + krow * HH + c4);
        }
        __syncthreads();
        float accW[8][4] = {};
#pragma unroll
        for (int ks = 0; ks < 2; ks++) {
            int kb = ks * 8 + ka;
            uint32_t a0 = EA[(wm + lr) * LDAP + kb];
            uint32_t a1 = EA[(wm + 8 + lr) * LDAP + kb];
            uint32_t a2 = EA[(wm + lr) * LDAP + kb + 4];
            uint32_t a3 = EA[(wm + 8 + lr) * LDAP + kb + 4];
#pragma unroll
            for (int nt = 0; nt < 8; nt++) {
                int nb = wn + nt * 8 + lr;
                uint32_t b0 = WB[(ks * 8 + ka) * LDB + nb];
                uint32_t b1 = WB[(ks * 8 + 4 + ka) * LDB + nb];
                mma_tf32(accW[nt], a0, a1, a2, a3, b0, b1);
            }
        }
        // frag write -> As as tf32 (mainloop A operand)
#pragma unroll
        for (int nt = 0; nt < 8; nt++) {
            int col = wn + nt * 8 + (ka << 1);
            float2 bb = *(const float2*)(be0 + col);
            As[(wm + lr) * LDA + col]         = f2tf(fmaxf(accW[nt][0] + bb.x, 0.f));
            As[(wm + lr) * LDA + col + 1]     = f2tf(fmaxf(accW[nt][1] + bb.y, 0.f));
            As[(wm + 8 + lr) * LDA + col]     = f2tf(fmaxf(accW[nt][2] + bb.x, 0.f));
            As[(wm + 8 + lr) * LDA + col + 1] = f2tf(fmaxf(accW[nt][3] + bb.y, 0.f));
        }
    } else {
        // A stage: pure copies (e already tf32)
#pragma unroll
        for (int i = 0; i < 8; i++) {
            int f = t + i * ETPB;
            int row = f >> 5, c4 = (f & 31) << 2;
            *(uint4*)(As + row * LDA + c4) = *(const uint4*)(g_e + (e0 + row) * HH + c4);
        }
    }

    float accM[8][4], accE[8][4];
#pragma unroll
    for (int i = 0; i < 8; i++)
#pragma unroll
        for (int j = 0; j < 4; j++) { accM[i][j] = 0.f; accE[i][j] = 0.f; }

#pragma unroll 1
    for (int kc = 0; kc < 4; kc++) {
        __syncthreads();
#pragma unroll
        for (int i = 0; i < 2; i++) {
            int ff = t + i * ETPB;
            int krow = ff >> 5, c4 = (ff & 31) << 2;
            if (ff < 32 * 32) {
                *(uint4*)(B1 + krow * LDB + c4) =
                    *(const uint4*)(wm3_t + (ll)(kc * 32 + krow) * HH + c4);
                if (do_edge)
                    *(uint4*)(B2 + krow * LDB + c4) =
                        *(const uint4*)(we_t + (ll)(kc * 32 + krow) * HH + c4);
            }
        }
        __syncthreads();
#pragma unroll
        for (int ks = 0; ks < 4; ks++) {
            int kb = kc * 32 + ks * 8 + ka;
            uint32_t a0 = As[(wm + lr) * LDA + kb];
            uint32_t a1 = As[(wm + 8 + lr) * LDA + kb];
            uint32_t a2 = As[(wm + lr) * LDA + kb + 4];
            uint32_t a3 = As[(wm + 8 + lr) * LDA + kb + 4];
#pragma unroll
            for (int nt = 0; nt < 8; nt++) {
                int nb = wn + nt * 8 + lr;
                uint32_t b0 = B1[(ks * 8 + ka) * LDB + nb];
                uint32_t b1 = B1[(ks * 8 + 4 + ka) * LDB + nb];
                mma_tf32(accM[nt], a0, a1, a2, a3, b0, b1);
            }
            if (do_edge) {
#pragma unroll
                for (int nt = 0; nt < 8; nt++) {
                    int nb = wn + nt * 8 + lr;
                    uint32_t b0 = B2[(ks * 8 + ka) * LDB + nb];
                    uint32_t b1 = B2[(ks * 8 + 4 + ka) * LDB + nb];
                    mma_tf32(accE[nt], a0, a1, a2, a3, b0, b1);
                }
            }
        }
    }

    // epilogue 1: messages -> agg (atomic scatter); Cs aliases As (A data dead)
    __syncthreads();
#pragma unroll
    for (int nt = 0; nt < 8; nt++) {
        int col = wn + nt * 8 + (ka << 1);
        *(float2*)(Cs + (wm + lr) * LDA + col)     = make_float2(accM[nt][0], accM[nt][1]);
        *(float2*)(Cs + (wm + 8 + lr) * LDA + col) = make_float2(accM[nt][2], accM[nt][3]);
    }
    __syncthreads();
#pragma unroll
    for (int i = 0; i < 8; i++) {
        int f = t + i * ETPB;
        int row = f >> 5, c4 = (f & 31) << 2;
        int ge = (int)e0 + row;
        int d = dst[ge], s = src[ge];
        float4 c  = *(const float4*)(Cs + row * LDA + c4);
        float4 bb = *(const float4*)(bM + c4);
        float4 p1 = *(const float4*)(g_p1 + (ll)d * HH + c4);
        float4 p2 = *(const float4*)(g_p2 + (ll)s * HH + c4);
        float4 v;
        v.x = fmaxf(c.x + bb.x + p1.x + p2.x, 0.f);
        v.y = fmaxf(c.y + bb.y + p1.y + p2.y, 0.f);
        v.z = fmaxf(c.z + bb.z + p1.z + p2.z, 0.f);
        v.w = fmaxf(c.w + bb.w + p1.w + p2.w, 0.f);
        atomicAdd((float4*)(g_agg + (ll)d * HH + c4), v);
    }

    // epilogue 2: e = tf32(relu(e@We + be))
    if (do_edge) {
        __syncthreads();
#pragma unroll
        for (int nt = 0; nt < 8; nt++) {
            int col = wn + nt * 8 + (ka << 1);
            *(float2*)(Cs + (wm + lr) * LDA + col)     = make_float2(accE[nt][0], accE[nt][1]);
            *(float2*)(Cs + (wm + 8 + lr) * LDA + col) = make_float2(accE[nt][2], accE[nt][3]);
        }
        __syncthreads();
#pragma unroll
        for (int i = 0; i < 8; i++) {
            int f = t + i * ETPB;
            int row = f >> 5, c4 = (f & 31) << 2;
            float4 c  = *(const float4*)(Cs + row * LDA + c4);
            float4 bb = *(const float4*)(be + c4);
            uint4 u;
            u.x = f2tf(fmaxf(c.x + bb.x, 0.f));
            u.y = f2tf(fmaxf(c.y + bb.y, 0.f));
            u.z = f2tf(fmaxf(c.z + bb.z, 0.f));
            u.w = f2tf(fmaxf(c.w + bb.w, 0.f));
            *(uint4*)(g_e + (e0 + row) * HH + c4) = u;
        }
    }
}

// ---------------- fused update (3xBF16) + agg zeroing ----------------
__global__ void __launch_bounds__(TPB) k_update_fused(int layer,
                                                      const float* __restrict__ bU,
                                                      const float* __restrict__ bn,
                                                      int has_next) {
    extern __shared__ uint32_t sm[];
    uint32_t* Ah  = sm + OFF_APH;
    uint32_t* Al  = sm + OFF_APL;
    uint32_t* B1h = sm + OFF_B1H;
    uint32_t* B1l = sm + OFF_B1L;
    uint32_t* B2h = sm + OFF_B2H;
    uint32_t* B2l = sm + OFF_B2L;
    float*    Cf  = (float*)(sm + OFF_CF);

    const uint32_t* wu_h = g_wu_h + layer * 128 * HH;
    const uint32_t* wu_l = g_wu_l + layer * 128 * HH;
    const uint32_t* wn_h = g_wn_h + layer * 64 * HH;
    const uint32_t* wn_l = g_wn_l + layer * 64 * HH;

    int t = threadIdx.x;
    int lane = t & 31, wid = t >> 5;
    int wm = (wid >> 1) << 4, wn = (wid & 1) << 6;
    int lr = lane >> 2, ka = lane & 3;
    int r = t >> 2, q = t & 3;
    int n0 = blockIdx.x * BM;
    int row = min(n0 + r, NN - 1);
    float rd = g_rdeg[row];

    // ---- stage 1: u = relu([h | agg*rdeg] @ WU + bU), K=256 ----
    float acc[8][4];
#pragma unroll
    for (int i = 0; i < 8; i++)
#pragma unroll
        for (int j = 0; j < 4; j++) acc[i][j] = 0.f;
#pragma unroll 1
    for (int c = 0; c < 8; c++) {
        __syncthreads();
        const float* p = (c < 4) ? (g_h + (ll)row * HH + c * 32)
                                 : (g_agg + (ll)row * HH + (c - 4) * 32);
        float sc = (c < 4) ? 1.f : rd;
        float4 v0 = *(const float4*)(p + q * 4);
        float4 v1 = *(const float4*)(p + 16 + q * 4);
        v0.x *= sc; v0.y *= sc; v0.z *= sc; v0.w *= sc;
        v1.x *= sc; v1.y *= sc; v1.z *= sc; v1.w *= sc;
        stage_Abf(Ah, Al, r, q, v0, v1);
        stage_Bpre(B1h, B1l, wu_h, wu_l, c * 16);
        __syncthreads();
        mma3_bf(Ah, Al, B1h, B1l, wm, wn, lr, ka, acc);
    }
    frag_relu_toCf(Cf, acc, bU, wm, wn, lr, ka);

    // zero agg rows for the next layer
    {
        float4 z = make_float4(0.f, 0.f, 0.f, 0.f);
#pragma unroll
        for (int i = 0; i < 8; i++) {
            int f = t + i * TPB;
            int rr = n0 + (f >> 5);
            if (rr < NN)
                *(float4*)(g_agg + (ll)rr * HH + ((f & 31) << 2)) = z;
        }
    }

    // ---- stage 2: hnew = relu(u @ Wn + bn), K=128 ----
#pragma unroll
    for (int i = 0; i < 8; i++)
#pragma unroll
        for (int j = 0; j < 4; j++) acc[i][j] = 0.f;
#pragma unroll 1
    for (int kc = 0; kc < 4; kc++) {
        __syncthreads();
        stage_Abf_fromCf(Ah, Al, Cf, kc);
        stage_Bpre(B1h, B1l, wn_h, wn_l, kc * 16);
        __syncthreads();
        mma3_bf(Ah, Al, B1h, B1l, wm, wn, lr, ka, acc);
    }
    __syncthreads();
    frag_relu_toCf(Cf, acc, bn, wm, wn, lr, ka);
    __syncthreads();
#pragma unroll
    for (int i = 0; i < 8; i++) {
        int f = t + i * TPB;
        int rr = f >> 5, c4 = (f & 31) << 2;
        int gr = n0 + rr;
        if (gr < NN)
            *(float4*)(g_h + (ll)gr * HH + c4) = *(const float4*)(Cf + rr * LDA + c4);
    }

    // ---- stage 3: fused P1/P2 for next layer ----
    if (has_next)
        p_passes(Ah, Al, B1h, B1l, B2h, B2l, Cf, layer + 1, n0, wm, wn, lr, ka);
}

// ---------------- global mean pool ----------------
__global__ void k_pool(const int* __restrict__ bvec) {
    int t = blockIdx.x * blockDim.x + threadIdx.x;
    int c4 = (t & 31) << 2;
    int nb = (t >> 5) * 16;
    if (nb >= NN) return;
    int end = min(nb + 16, NN);
    int g = bvec[nb];
    float4 s = make_float4(0.f, 0.f, 0.f, 0.f);
    float cnt = 0.f;
    for (int n = nb; n < end; n++) {
        int gn = bvec[n];
        if (gn != g) {
            atomicAdd((float4*)(g_pool + g * HH + c4), s);
            if (c4 == 0) atomicAdd(&g_cnt[g], cnt);
            s = make_float4(0.f, 0.f, 0.f, 0.f);
            cnt = 0.f;
            g = gn;
        }
        float4 hv = *(const float4*)(g_h + (ll)n * HH + c4);
        s.x += hv.x; s.y += hv.y; s.z += hv.z; s.w += hv.w;
        cnt += 1.f;
    }
    atomicAdd((float4*)(g_pool + g * HH + c4), s);
    if (c4 == 0) atomicAdd(&g_cnt[g], cnt);
}

__global__ void k_head(const float* __restrict__ Wh, const float* __restrict__ bh,
                       float* __restrict__ out) {
    int g = threadIdx.x;
    float rc = 1.f / fmaxf(g_cnt[g], 1.f);
    float acc = bh[0];
#pragma unroll
    for (int k = 0; k < HH; k++)
        acc += g_pool[g * HH + k] * rc * Wh[k];
    out[g] = acc;
}

// ---------------- launch ----------------
extern "C" void kernel_launch(void* const* d_in, const int* in_sizes, int n_in,
                              void* d_out, int out_size) {
    const float* x    = (const float*)d_in[0];
    const int*   ei   = (const int*)d_in[1];
    const float* ea   = (const float*)d_in[2];
    const int*   bvec = (const int*)d_in[3];
    const float* Wn0  = (const float*)d_in[4];
    const float* bn0  = (const float*)d_in[5];
    const float* We0  = (const float*)d_in[6];
    const float* be0  = (const float*)d_in[7];
    const float* WM   = (const float*)d_in[8];
    const float* bM   = (const float*)d_in[9];
    const float* WU   = (const float*)d_in[10];
    const float* bU   = (const float*)d_in[11];
    const float* Wn   = (const float*)d_in[12];
    const float* bn   = (const float*)d_in[13];
    const float* We   = (const float*)d_in[14];
    const float* be   = (const float*)d_in[15];
    const float* Wh   = (const float*)d_in[16];
    const float* bh   = (const float*)d_in[17];
    float* out = (float*)d_out;

    const int* src = ei;
    const int* dst = ei + EE;

    static int attr_done = 0;
    if (!attr_done) {
        cudaFuncSetAttribute(k_edge_tf32, cudaFuncAttributeMaxDynamicSharedMemorySize,
                             EDGE_SMEM);
        cudaFuncSetAttribute(k_enc_fused, cudaFuncAttributeMaxDynamicSharedMemorySize,
                             NODE_SMEM);
        cudaFuncSetAttribute(k_update_fused, cudaFuncAttributeMaxDynamicSharedMemorySize,
                             NODE_SMEM);
        attr_done = 1;
    }

    int prep_threads = 3 * 40960 + 2 * 3 * 16384 + 16 * HH;
    k_prep<<<(prep_threads + 255) / 256, 256>>>(WM, WU, Wn, We, We0);

    k_zero_misc<<<(NN + 255) / 256, 256>>>();
    k_deg<<<(EE + 255) / 256, 256>>>(dst);
    k_rdeg<<<(NN + 255) / 256, 256>>>();

    int nblk = (NN + BM - 1) / BM;
    k_enc_fused<<<nblk, TPB, NODE_SMEM>>>(x, Wn0, bn0);

    for (int l = 0; l < 3; l++) {
        k_edge_tf32<<<EE / EBM, ETPB, EDGE_SMEM>>>(src, dst, l, bM + l * HH,
                                                   be + l * HH, ea, be0,
                                                   l < 2 ? 1 : 0);
        k_update_fused<<<nblk, TPB, NODE_SMEM>>>(l, bU + l * HH, bn + l * HH,
                                                 l < 2 ? 1 : 0);
    }

    int pool_threads = ((NN + 15) / 16) * 32;
    k_pool<<<(pool_threads + 255) / 256, 256>>>(bvec);
    k_head<<<1, GG>>>(Wh, bh, out);
}